// round 5
// baseline (speedup 1.0000x reference)
#include <cuda_runtime.h>
#include <math.h>

// ---------------------------------------------------------------------------
// Swin block: B=8, H=W=256, C=48, NH=3 (hd=16), WS=8 (N=64), SS=4, HID=192
// Kernel A (per window, 64 thr): LN1 -> qkv (q in regs, k/v smem) -> attention
//   (+rpb +shift mask) -> SE -> proj -> scatter. Weights via uniform __ldg.
// Kernel B (per token): residual -> LN2 -> fc1 -> GELU(erf) -> fc2 -> residual.
// ---------------------------------------------------------------------------

#define BB    8
#define HH    256
#define WWD   256
#define CC    48
#define NWIN  1024   // 32*32 windows per image
#define BN    8192   // BB*NWIN

// scratch for attention-branch output (bijective pixel map, written once)
__device__ float g_attn[(size_t)BB * HH * WWD * CC];

#define SKV 100   // k/v row stride (floats): 400B, 16B-aligned, 8-way wr conflict only
#define SSC 65    // score / x-stage row stride (odd -> conflict-free scalar)

#define A_SMEM_FLOATS (64*SKV + 64*SSC + 676 + 48 + 48 + 4)
#define B_SMEM_FLOATS (192*48 + 192*48 + 192 + 48 + 48 + 48)

__global__ void __launch_bounds__(64) attn_kernel(
    const float* __restrict__ x,
    const float* __restrict__ g1,   const float* __restrict__ b1,
    const float* __restrict__ qkvw, const float* __restrict__ qkvb,
    const float* __restrict__ rpbt, const float* __restrict__ wf,
    const float* __restrict__ sw1,  const float* __restrict__ sb1,
    const float* __restrict__ sw2,  const float* __restrict__ sb2,
    const float* __restrict__ pw,   const float* __restrict__ pb)
{
    extern __shared__ float sm[];
    float* s_kv  = sm;               // 64*SKV : [tok][0..47]=k, [48..95]=v
    float* s_sc  = s_kv + 64*SKV;    // 64*SSC : first LN'd x (for SE), then scores
    float* s_rpb = s_sc + 64*SSC;    // 676 (675 used)
    float* s_mean= s_rpb + 676;      // 48
    float* s_se  = s_mean + 48;      // 48
    float* s_hh  = s_se + 48;        // 4

    const int tid = threadIdx.x;

    for (int i = tid; i < 675; i += 64) s_rpb[i] = __ldg(rpbt + i);

    // ---- window / pixel coordinates -------------------------------------
    const int blk = blockIdx.x;
    const int b  = blk >> 10;
    const int w  = blk & 1023;
    const int wy = w >> 5, wx = w & 31;
    const int ti = tid >> 3, tj = tid & 7;
    const int gy = (wy*8 + ti + 4) & 255;
    const int gx = (wx*8 + tj + 4) & 255;
    const size_t pix = ((size_t)b << 16) | (gy << 8) | gx;
    const float* xrow = x + pix * CC;

    // ---- load + LN1 -------------------------------------------------------
    float xr[48];
    float mu = 0.f, sq = 0.f;
    #pragma unroll
    for (int c = 0; c < 48; c += 4) {
        float4 v = __ldg((const float4*)(xrow + c));
        xr[c]=v.x; xr[c+1]=v.y; xr[c+2]=v.z; xr[c+3]=v.w;
        mu += v.x + v.y + v.z + v.w;
        sq += v.x*v.x + v.y*v.y + v.z*v.z + v.w*v.w;
    }
    mu *= (1.f/48.f);
    const float inv = rsqrtf(sq*(1.f/48.f) - mu*mu + 1e-5f);
    #pragma unroll
    for (int c = 0; c < 48; c++) {
        xr[c] = (xr[c] - mu) * inv * __ldg(g1 + c) + __ldg(b1 + c);
        s_sc[tid*SSC + c] = xr[c];     // stage LN'd x for the SE mean
    }

    // ---- qkv: q -> regs (pre-scaled), k/v -> smem ------------------------
    const float4* w4 = (const float4*)qkvw;
    float q[48];
    for (int o = 0; o < 48; o++) {
        float a0=0.f,a1=0.f,a2=0.f,a3=0.f;
        #pragma unroll
        for (int i = 0; i < 12; i++) {
            float4 wv = __ldg(w4 + o*12 + i);
            a0 += xr[4*i+0]*wv.x; a1 += xr[4*i+1]*wv.y;
            a2 += xr[4*i+2]*wv.z; a3 += xr[4*i+3]*wv.w;
        }
        q[o] = ((a0+a1)+(a2+a3) + __ldg(qkvb + o)) * 0.25f;  // * hd^-0.5
    }
    for (int o = 0; o < 96; o++) {
        float a0=0.f,a1=0.f,a2=0.f,a3=0.f;
        #pragma unroll
        for (int i = 0; i < 12; i++) {
            float4 wv = __ldg(w4 + (48+o)*12 + i);
            a0 += xr[4*i+0]*wv.x; a1 += xr[4*i+1]*wv.y;
            a2 += xr[4*i+2]*wv.z; a3 += xr[4*i+3]*wv.w;
        }
        s_kv[tid*SKV + o] = (a0+a1)+(a2+a3) + __ldg(qkvb + 48 + o);
    }
    __syncthreads();

    // ---- SE branch (mean over tokens of LN'd x) ---------------------------
    if (tid < 48) {
        float s = 0.f;
        for (int t = 0; t < 64; t++) s += s_sc[t*SSC + tid];
        s_mean[tid] = s * (1.f/64.f);
    }
    __syncthreads();
    if (tid < 3) {
        float a = __ldg(sb1 + tid);
        #pragma unroll
        for (int c = 0; c < 48; c++) a += s_mean[c] * __ldg(sw1 + tid*48 + c);
        s_hh[tid] = fmaxf(a, 0.f);
    }
    __syncthreads();
    if (tid < 48) {
        float a = __ldg(sb2 + tid) + s_hh[0]*__ldg(sw2 + tid*3+0)
                                   + s_hh[1]*__ldg(sw2 + tid*3+1)
                                   + s_hh[2]*__ldg(sw2 + tid*3+2);
        s_se[tid] = 1.f/(1.f + __expf(-a));
    }
    __syncthreads();   // also guards s_sc reuse (x data -> scores)

    // ---- attention: thread = query row ------------------------------------
    float out[48];
    #pragma unroll
    for (int c = 0; c < 48; c++) out[c] = 0.f;

    const int regy = (wy == 31) ? (ti >= 4 ? 2 : 1) : 0;
    const int regx = (wx == 31) ? (tj >= 4 ? 2 : 1) : 0;
    float* myrow = s_sc + tid*SSC;

    for (int h = 0; h < 3; h++) {
        float mx = -1e30f;
        for (int j = 0; j < 64; j++) {
            const float4* kr = (const float4*)(s_kv + j*SKV + h*16);
            float s0=0.f,s1=0.f,s2=0.f,s3=0.f;
            #pragma unroll
            for (int i = 0; i < 4; i++) {
                float4 kv = kr[i];
                s0 += q[h*16+4*i+0]*kv.x; s1 += q[h*16+4*i+1]*kv.y;
                s2 += q[h*16+4*i+2]*kv.z; s3 += q[h*16+4*i+3]*kv.w;
            }
            float s = (s0+s1)+(s2+s3);
            const int rj = j >> 3, cj = j & 7;
            s += s_rpb[((ti - rj + 7)*15 + (tj - cj + 7))*3 + h];
            const int ryj = (wy == 31) ? (rj >= 4 ? 2 : 1) : 0;
            const int rxj = (wx == 31) ? (cj >= 4 ? 2 : 1) : 0;
            if (ryj != regy || rxj != regx) s -= 100.f;
            myrow[j] = s;
            mx = fmaxf(mx, s);
        }
        float sum = 0.f;
        for (int j = 0; j < 64; j++) {
            float e = __expf(myrow[j] - mx);
            myrow[j] = e;
            sum += e;
        }
        const float is = 1.f / sum;
        for (int j = 0; j < 64; j++) {
            const float wgt = myrow[j] * is;
            const float4* vr = (const float4*)(s_kv + j*SKV + 48 + h*16);
            #pragma unroll
            for (int i = 0; i < 4; i++) {
                float4 vv = vr[i];
                out[h*16+4*i+0] += wgt*vv.x; out[h*16+4*i+1] += wgt*vv.y;
                out[h*16+4*i+2] += wgt*vv.z; out[h*16+4*i+3] += wgt*vv.w;
            }
        }
    }

    // ---- SE add ------------------------------------------------------------
    const float wfv = __ldg(wf);
    #pragma unroll
    for (int c = 0; c < 48; c++) out[c] += wfv * xr[c] * s_se[c];

    // ---- proj + scatter -----------------------------------------------------
    const float4* pw4 = (const float4*)pw;
    float* orow = g_attn + pix * CC;
    #pragma unroll 2
    for (int c4 = 0; c4 < 48; c4 += 4) {
        float4 r;
        #pragma unroll
        for (int k = 0; k < 4; k++) {
            const int cp = c4 + k;
            float a0=0.f,a1=0.f,a2=0.f,a3=0.f;
            #pragma unroll
            for (int i = 0; i < 12; i++) {
                float4 wv = __ldg(pw4 + cp*12 + i);
                a0 += out[4*i+0]*wv.x; a1 += out[4*i+1]*wv.y;
                a2 += out[4*i+2]*wv.z; a3 += out[4*i+3]*wv.w;
            }
            ((float*)&r)[k] = (a0+a1)+(a2+a3) + __ldg(pb + cp);
        }
        *(float4*)(orow + c4) = r;
    }
}

__global__ void __launch_bounds__(128) mlp_kernel(
    const float* __restrict__ x,
    const float* __restrict__ g2,   const float* __restrict__ b2,
    const float* __restrict__ f1w,  const float* __restrict__ f1b,
    const float* __restrict__ f2w,  const float* __restrict__ f2b,
    float* __restrict__ out)
{
    extern __shared__ float sm[];
    float* s_f1 = sm;                 // 192*48  fc1 rows
    float* s_f2 = s_f1 + 192*48;      // 192*48  fc2 transposed to [o][c]
    float* s_1b = s_f2 + 192*48;      // 192
    float* s_g2 = s_1b + 192;         // 48
    float* s_b2 = s_g2 + 48;          // 48
    float* s_2b = s_b2 + 48;          // 48

    const int tid = threadIdx.x;
    for (int i = tid; i < 192*48; i += 128) s_f1[i] = f1w[i];
    for (int i = tid; i < 192*48; i += 128) {       // coalesced read, transp. write
        const int c = i / 192, o = i % 192;
        s_f2[o*48 + c] = f2w[i];
    }
    for (int i = tid; i < 192; i += 128) s_1b[i] = f1b[i];
    if (tid < 48) { s_g2[tid] = g2[tid]; s_b2[tid] = b2[tid]; s_2b[tid] = f2b[tid]; }
    __syncthreads();

    const size_t tok = (size_t)blockIdx.x*128 + tid;
    const float* xrow = x      + tok*48;
    const float* hrow = g_attn + tok*48;
    float* orow = out + tok*48;

    // residual sum -> early write to out (frees 48 regs), LN2 into xln
    float xln[48];
    float mu = 0.f, sq = 0.f;
    #pragma unroll
    for (int c = 0; c < 48; c += 4) {
        float4 a = __ldg((const float4*)(xrow + c));
        float4 h = *(const float4*)(hrow + c);
        float4 s;
        s.x = a.x + h.x; s.y = a.y + h.y; s.z = a.z + h.z; s.w = a.w + h.w;
        *(float4*)(orow + c) = s;
        xln[c]=s.x; xln[c+1]=s.y; xln[c+2]=s.z; xln[c+3]=s.w;
        mu += s.x + s.y + s.z + s.w;
        sq += s.x*s.x + s.y*s.y + s.z*s.z + s.w*s.w;
    }
    mu *= (1.f/48.f);
    const float inv = rsqrtf(sq*(1.f/48.f) - mu*mu + 1e-5f);
    #pragma unroll
    for (int c = 0; c < 48; c++)
        xln[c] = (xln[c] - mu) * inv * s_g2[c] + s_b2[c];

    float acc[48];
    #pragma unroll
    for (int c = 0; c < 48; c++) acc[c] = s_2b[c];   // fc2 bias

    const float4* f1_4 = (const float4*)s_f1;
    const float4* f2_4 = (const float4*)s_f2;
    for (int o = 0; o < 192; o++) {
        float h0=0.f,h1=0.f,h2=0.f,h3=0.f;
        #pragma unroll
        for (int i = 0; i < 12; i++) {
            float4 wv = f1_4[o*12 + i];
            h0 += xln[4*i+0]*wv.x; h1 += xln[4*i+1]*wv.y;
            h2 += xln[4*i+2]*wv.z; h3 += xln[4*i+3]*wv.w;
        }
        const float hs = (h0+h1)+(h2+h3) + s_1b[o];
        const float g = 0.5f * hs * (1.f + erff(hs * 0.7071067811865476f));
        #pragma unroll
        for (int i = 0; i < 12; i++) {
            float4 wv = f2_4[o*12 + i];
            acc[4*i+0] += g*wv.x; acc[4*i+1] += g*wv.y;
            acc[4*i+2] += g*wv.z; acc[4*i+3] += g*wv.w;
        }
    }

    __syncthreads();   // compiler memory barrier: force real re-read of orow
    #pragma unroll
    for (int c = 0; c < 48; c += 4) {
        float4 r = *(const float4*)(orow + c);
        r.x += acc[c];   r.y += acc[c+1];
        r.z += acc[c+2]; r.w += acc[c+3];
        *(float4*)(orow + c) = r;
    }
}

extern "C" void kernel_launch(void* const* d_in, const int* in_sizes, int n_in,
                              void* d_out, int out_size)
{
    const float* x      = (const float*)d_in[0];
    const float* g1     = (const float*)d_in[1];
    const float* b1     = (const float*)d_in[2];
    const float* qkvw   = (const float*)d_in[3];
    const float* qkvb   = (const float*)d_in[4];
    const float* rpbt   = (const float*)d_in[5];
    const float* wf     = (const float*)d_in[6];
    const float* sw1    = (const float*)d_in[7];
    const float* sb1    = (const float*)d_in[8];
    const float* sw2    = (const float*)d_in[9];
    const float* sb2    = (const float*)d_in[10];
    const float* pw     = (const float*)d_in[11];
    const float* pb     = (const float*)d_in[12];
    const float* g2     = (const float*)d_in[13];
    const float* b2     = (const float*)d_in[14];
    const float* f1w    = (const float*)d_in[15];
    const float* f1b    = (const float*)d_in[16];
    const float* f2w    = (const float*)d_in[17];
    const float* f2b    = (const float*)d_in[18];
    float* out = (float*)d_out;

    const int a_smem = A_SMEM_FLOATS * 4;   // 45,344 B
    const int b_smem = B_SMEM_FLOATS * 4;   // 75,072 B
    cudaFuncSetAttribute(attn_kernel, cudaFuncAttributeMaxDynamicSharedMemorySize, a_smem);
    cudaFuncSetAttribute(mlp_kernel,  cudaFuncAttributeMaxDynamicSharedMemorySize, b_smem);

    attn_kernel<<<BN, 64, a_smem>>>(x, g1, b1, qkvw, qkvb, rpbt, wf,
                                    sw1, sb1, sw2, sb2, pw, pb);

    mlp_kernel<<<(BB*HH*WWD)/128, 128, b_smem>>>(x, g2, b2, f1w, f1b, f2w, f2b, out);
}

// round 6
// speedup vs baseline: 1.3026x; 1.3026x over previous
#include <cuda_runtime.h>
#include <math.h>
#include <stdint.h>

// ---------------------------------------------------------------------------
// Swin block: B=8, H=W=256, C=48, NH=3 (hd=16), WS=8 (N=64), SS=4, HID=192
// Kernel A (per window, 64 thr): LN1 -> qkv -> attention -> SE -> proj.
// Kernel B (per token block): residual -> LN2 -> tf32 tensor-core MLP.
// ---------------------------------------------------------------------------

#define BB    8
#define HH    256
#define WWD   256
#define CC    48
#define NWIN  1024
#define BN    8192

__device__ float g_attn[(size_t)BB * HH * WWD * CC];

#define SKV 100
#define SSC 65
#define A_SMEM_FLOATS (64*SKV + 64*SSC + 676 + 48 + 48 + 4)

// ---- MLP tensor kernel geometry ----
#define XS  52      // xln / Y staging row stride (floats)
#define W1S 52      // w1 row stride
#define W2S 196     // w2 row stride
#define B_SMEM_FLOATS (192*W1S + 48*W2S + 192 + 48 + 48 + 48 + 8*32*XS)

__device__ __forceinline__ uint32_t f2tf32(float v) {
    uint32_t t;
    asm("cvt.rna.tf32.f32 %0, %1;" : "=r"(t) : "f"(v));
    return t;
}
__device__ __forceinline__ void mma_tf32(float* c, const uint32_t* a, const uint32_t* b) {
    asm volatile("mma.sync.aligned.m16n8k8.row.col.f32.tf32.tf32.f32 "
        "{%0,%1,%2,%3}, {%4,%5,%6,%7}, {%8,%9}, {%0,%1,%2,%3};"
        : "+f"(c[0]), "+f"(c[1]), "+f"(c[2]), "+f"(c[3])
        : "r"(a[0]), "r"(a[1]), "r"(a[2]), "r"(a[3]), "r"(b[0]), "r"(b[1]));
}

// ===========================================================================
__global__ void __launch_bounds__(64) attn_kernel(
    const float* __restrict__ x,
    const float* __restrict__ g1,   const float* __restrict__ b1,
    const float* __restrict__ qkvw, const float* __restrict__ qkvb,
    const float* __restrict__ rpbt, const float* __restrict__ wf,
    const float* __restrict__ sw1,  const float* __restrict__ sb1,
    const float* __restrict__ sw2,  const float* __restrict__ sb2,
    const float* __restrict__ pw,   const float* __restrict__ pb)
{
    extern __shared__ float sm[];
    float* s_kv  = sm;
    float* s_sc  = s_kv + 64*SKV;
    float* s_rpb = s_sc + 64*SSC;
    float* s_mean= s_rpb + 676;
    float* s_se  = s_mean + 48;
    float* s_hh  = s_se + 48;

    const int tid = threadIdx.x;

    for (int i = tid; i < 675; i += 64) s_rpb[i] = __ldg(rpbt + i);

    const int blk = blockIdx.x;
    const int b  = blk >> 10;
    const int w  = blk & 1023;
    const int wy = w >> 5, wx = w & 31;
    const int ti = tid >> 3, tj = tid & 7;
    const int gy = (wy*8 + ti + 4) & 255;
    const int gx = (wx*8 + tj + 4) & 255;
    const size_t pix = ((size_t)b << 16) | (gy << 8) | gx;
    const float* xrow = x + pix * CC;

    float xr[48];
    float mu = 0.f, sq = 0.f;
    #pragma unroll
    for (int c = 0; c < 48; c += 4) {
        float4 v = __ldg((const float4*)(xrow + c));
        xr[c]=v.x; xr[c+1]=v.y; xr[c+2]=v.z; xr[c+3]=v.w;
        mu += v.x + v.y + v.z + v.w;
        sq += v.x*v.x + v.y*v.y + v.z*v.z + v.w*v.w;
    }
    mu *= (1.f/48.f);
    const float inv = rsqrtf(sq*(1.f/48.f) - mu*mu + 1e-5f);
    #pragma unroll
    for (int c = 0; c < 48; c++) {
        xr[c] = (xr[c] - mu) * inv * __ldg(g1 + c) + __ldg(b1 + c);
        s_sc[tid*SSC + c] = xr[c];
    }

    const float4* w4 = (const float4*)qkvw;
    float q[48];
    for (int o = 0; o < 48; o++) {
        float a0=0.f,a1=0.f,a2=0.f,a3=0.f;
        #pragma unroll
        for (int i = 0; i < 12; i++) {
            float4 wv = __ldg(w4 + o*12 + i);
            a0 += xr[4*i+0]*wv.x; a1 += xr[4*i+1]*wv.y;
            a2 += xr[4*i+2]*wv.z; a3 += xr[4*i+3]*wv.w;
        }
        q[o] = ((a0+a1)+(a2+a3) + __ldg(qkvb + o)) * 0.25f;
    }
    for (int o = 0; o < 96; o++) {
        float a0=0.f,a1=0.f,a2=0.f,a3=0.f;
        #pragma unroll
        for (int i = 0; i < 12; i++) {
            float4 wv = __ldg(w4 + (48+o)*12 + i);
            a0 += xr[4*i+0]*wv.x; a1 += xr[4*i+1]*wv.y;
            a2 += xr[4*i+2]*wv.z; a3 += xr[4*i+3]*wv.w;
        }
        s_kv[tid*SKV + o] = (a0+a1)+(a2+a3) + __ldg(qkvb + 48 + o);
    }
    __syncthreads();

    if (tid < 48) {
        float s = 0.f;
        for (int t = 0; t < 64; t++) s += s_sc[t*SSC + tid];
        s_mean[tid] = s * (1.f/64.f);
    }
    __syncthreads();
    if (tid < 3) {
        float a = __ldg(sb1 + tid);
        #pragma unroll
        for (int c = 0; c < 48; c++) a += s_mean[c] * __ldg(sw1 + tid*48 + c);
        s_hh[tid] = fmaxf(a, 0.f);
    }
    __syncthreads();
    if (tid < 48) {
        float a = __ldg(sb2 + tid) + s_hh[0]*__ldg(sw2 + tid*3+0)
                                   + s_hh[1]*__ldg(sw2 + tid*3+1)
                                   + s_hh[2]*__ldg(sw2 + tid*3+2);
        s_se[tid] = 1.f/(1.f + __expf(-a));
    }
    __syncthreads();

    float out[48];
    #pragma unroll
    for (int c = 0; c < 48; c++) out[c] = 0.f;

    const int regy = (wy == 31) ? (ti >= 4 ? 2 : 1) : 0;
    const int regx = (wx == 31) ? (tj >= 4 ? 2 : 1) : 0;
    float* myrow = s_sc + tid*SSC;

    for (int h = 0; h < 3; h++) {
        float mx = -1e30f;
        for (int j = 0; j < 64; j++) {
            const float4* kr = (const float4*)(s_kv + j*SKV + h*16);
            float s0=0.f,s1=0.f,s2=0.f,s3=0.f;
            #pragma unroll
            for (int i = 0; i < 4; i++) {
                float4 kv = kr[i];
                s0 += q[h*16+4*i+0]*kv.x; s1 += q[h*16+4*i+1]*kv.y;
                s2 += q[h*16+4*i+2]*kv.z; s3 += q[h*16+4*i+3]*kv.w;
            }
            float s = (s0+s1)+(s2+s3);
            const int rj = j >> 3, cj = j & 7;
            s += s_rpb[((ti - rj + 7)*15 + (tj - cj + 7))*3 + h];
            const int ryj = (wy == 31) ? (rj >= 4 ? 2 : 1) : 0;
            const int rxj = (wx == 31) ? (cj >= 4 ? 2 : 1) : 0;
            if (ryj != regy || rxj != regx) s -= 100.f;
            myrow[j] = s;
            mx = fmaxf(mx, s);
        }
        float sum = 0.f;
        for (int j = 0; j < 64; j++) {
            float e = __expf(myrow[j] - mx);
            myrow[j] = e;
            sum += e;
        }
        const float is = 1.f / sum;
        for (int j = 0; j < 64; j++) {
            const float wgt = myrow[j] * is;
            const float4* vr = (const float4*)(s_kv + j*SKV + 48 + h*16);
            #pragma unroll
            for (int i = 0; i < 4; i++) {
                float4 vv = vr[i];
                out[h*16+4*i+0] += wgt*vv.x; out[h*16+4*i+1] += wgt*vv.y;
                out[h*16+4*i+2] += wgt*vv.z; out[h*16+4*i+3] += wgt*vv.w;
            }
        }
    }

    const float wfv = __ldg(wf);
    #pragma unroll
    for (int c = 0; c < 48; c++) out[c] += wfv * xr[c] * s_se[c];

    const float4* pw4 = (const float4*)pw;
    float* orow = g_attn + pix * CC;
    #pragma unroll 2
    for (int c4 = 0; c4 < 48; c4 += 4) {
        float4 r;
        #pragma unroll
        for (int k = 0; k < 4; k++) {
            const int cp = c4 + k;
            float a0=0.f,a1=0.f,a2=0.f,a3=0.f;
            #pragma unroll
            for (int i = 0; i < 12; i++) {
                float4 wv = __ldg(pw4 + cp*12 + i);
                a0 += out[4*i+0]*wv.x; a1 += out[4*i+1]*wv.y;
                a2 += out[4*i+2]*wv.z; a3 += out[4*i+3]*wv.w;
            }
            ((float*)&r)[k] = (a0+a1)+(a2+a3) + __ldg(pb + cp);
        }
        *(float4*)(orow + c4) = r;
    }
}

// ===========================================================================
// MLP: tf32 mma.sync tensor-core pipeline. 256 thr = 8 warps, 32 tokens/warp.
// ===========================================================================
__global__ void __launch_bounds__(256) mlp_kernel(
    const float* __restrict__ x,
    const float* __restrict__ g2,   const float* __restrict__ b2,
    const float* __restrict__ f1w,  const float* __restrict__ f1b,
    const float* __restrict__ f2w,  const float* __restrict__ f2b,
    float* __restrict__ out)
{
    extern __shared__ float sm[];
    uint32_t* s_w1 = (uint32_t*)sm;                    // 192 x W1S  tf32 bits
    uint32_t* s_w2 = (uint32_t*)(sm + 192*W1S);        // 48  x W2S  tf32 bits
    float* s_b1 = sm + 192*W1S + 48*W2S;               // 192
    float* s_2b = s_b1 + 192;                          // 48
    float* s_g2 = s_2b + 48;                           // 48
    float* s_b2 = s_g2 + 48;                           // 48
    float* s_xg = s_b2 + 48;                           // 8 warps x 32 x XS

    const int tid  = threadIdx.x;
    const int wid  = tid >> 5;
    const int lane = tid & 31;
    const int lr   = lane >> 2;        // 0..7
    const int lq   = lane & 3;         // 0..3
    const bool odd = lane & 1;

    // ---- stage weights (pre-converted to tf32) ---------------------------
    for (int i = tid; i < 192*48; i += 256) {
        s_w1[(i/48)*W1S + (i%48)]   = f2tf32(f1w[i]);    // [hid][ch]
        s_w2[(i/192)*W2S + (i%192)] = f2tf32(f2w[i]);    // [ch][hid]
    }
    for (int i = tid; i < 192; i += 256) s_b1[i] = f1b[i];
    if (tid < 48) { s_2b[tid] = f2b[tid]; s_g2[tid] = g2[tid]; s_b2[tid] = b2[tid]; }
    __syncthreads();

    // ---- residual + LN2 (thread = token), store tf32(xln) ----------------
    const size_t tok = (size_t)blockIdx.x*256 + tid;
    const float* xrow = x      + tok*48;
    const float* hrow = g_attn + tok*48;
    float* orow = out + tok*48;

    {
        float v[48];
        float mu = 0.f, sq = 0.f;
        #pragma unroll
        for (int c = 0; c < 48; c += 4) {
            float4 a = __ldg((const float4*)(xrow + c));
            float4 h = *(const float4*)(hrow + c);
            float4 s;
            s.x = a.x + h.x; s.y = a.y + h.y; s.z = a.z + h.z; s.w = a.w + h.w;
            *(float4*)(orow + c) = s;                 // residual parked in out
            v[c]=s.x; v[c+1]=s.y; v[c+2]=s.z; v[c+3]=s.w;
            mu += s.x + s.y + s.z + s.w;
            sq += s.x*s.x + s.y*s.y + s.z*s.z + s.w*s.w;
        }
        mu *= (1.f/48.f);
        const float inv = rsqrtf(sq*(1.f/48.f) - mu*mu + 1e-5f);
        uint32_t* myx = (uint32_t*)(s_xg + (size_t)wid*32*XS + lane*XS);
        #pragma unroll
        for (int c = 0; c < 48; c++)
            myx[c] = f2tf32((v[c] - mu) * inv * s_g2[c] + s_b2[c]);
    }
    __syncthreads();

    // ---- load full A (xln 32x48) as mma fragments: 2 m-tiles x 6 k-tiles --
    uint32_t afr[2][6][4];
    {
        const uint32_t* wx = (const uint32_t*)(s_xg + (size_t)wid*32*XS);
        #pragma unroll
        for (int mt = 0; mt < 2; mt++)
            #pragma unroll
            for (int kt = 0; kt < 6; kt++) {
                const int r = mt*16 + lr, c = kt*8 + lq;
                afr[mt][kt][0] = wx[r*XS + c];
                afr[mt][kt][1] = wx[(r+8)*XS + c];
                afr[mt][kt][2] = wx[r*XS + c + 4];
                afr[mt][kt][3] = wx[(r+8)*XS + c + 4];
            }
    }

    // ---- main loop over 24 hidden chunks of 8 -----------------------------
    float yacc[2][6][4];
    #pragma unroll
    for (int mt = 0; mt < 2; mt++)
        #pragma unroll
        for (int nt = 0; nt < 6; nt++)
            #pragma unroll
            for (int r = 0; r < 4; r++) yacc[mt][nt][r] = 0.f;

    for (int nt = 0; nt < 24; nt++) {
        // GEMM1: H chunk [32 x 8] = xln [32x48] * W1chunk^T
        uint32_t bf[6][2];
        #pragma unroll
        for (int kt = 0; kt < 6; kt++) {
            const uint32_t* wr = s_w1 + (8*nt + lr)*W1S + kt*8 + lq;
            bf[kt][0] = wr[0];
            bf[kt][1] = wr[4];
        }
        float h[2][4] = {{0.f,0.f,0.f,0.f},{0.f,0.f,0.f,0.f}};
        #pragma unroll
        for (int kt = 0; kt < 6; kt++) {
            mma_tf32(h[0], afr[0][kt], bf[kt]);
            mma_tf32(h[1], afr[1][kt], bf[kt]);
        }
        // bias + exact GELU
        const float2 bb = *(const float2*)(s_b1 + 8*nt + 2*lq);
        #pragma unroll
        for (int mt = 0; mt < 2; mt++)
            #pragma unroll
            for (int r = 0; r < 4; r++) {
                const float hs = h[mt][r] + ((r & 1) ? bb.y : bb.x);
                h[mt][r] = 0.5f * hs * (1.f + erff(hs * 0.7071067811865476f));
            }
        // C-frag -> A-frag remap via shuffles (G = gelu'd chunk, 32x8)
        uint32_t ga[2][4];
        const int s0 = (lane & ~3) | ((lane & 3) >> 1);
        const int s2 = s0 + 2;
        #pragma unroll
        for (int mt = 0; mt < 2; mt++) {
            const float p0 = __shfl_sync(0xffffffffu, h[mt][0], s0);
            const float p1 = __shfl_sync(0xffffffffu, h[mt][1], s0);
            const float p2 = __shfl_sync(0xffffffffu, h[mt][2], s0);
            const float p3 = __shfl_sync(0xffffffffu, h[mt][3], s0);
            const float q0 = __shfl_sync(0xffffffffu, h[mt][0], s2);
            const float q1 = __shfl_sync(0xffffffffu, h[mt][1], s2);
            const float q2 = __shfl_sync(0xffffffffu, h[mt][2], s2);
            const float q3 = __shfl_sync(0xffffffffu, h[mt][3], s2);
            ga[mt][0] = f2tf32(odd ? p1 : p0);
            ga[mt][1] = f2tf32(odd ? p3 : p2);
            ga[mt][2] = f2tf32(odd ? q1 : q0);
            ga[mt][3] = f2tf32(odd ? q3 : q2);
        }
        // GEMM2: Y [32 x 48] += G [32x8] * W2chunk [8 x 48]
        #pragma unroll
        for (int nt2 = 0; nt2 < 6; nt2++) {
            uint32_t b2f[2];
            const uint32_t* wr = s_w2 + (8*nt2 + lr)*W2S + 8*nt + lq;
            b2f[0] = wr[0];
            b2f[1] = wr[4];
            mma_tf32(yacc[0][nt2], ga[0], b2f);
            mma_tf32(yacc[1][nt2], ga[1], b2f);
        }
    }

    // ---- epilogue: stage Y in (reused) warp buffer, coalesced writeback ---
    __syncwarp();
    float* wy = s_xg + (size_t)wid*32*XS;
    #pragma unroll
    for (int mt = 0; mt < 2; mt++)
        #pragma unroll
        for (int nt2 = 0; nt2 < 6; nt2++) {
            const int r = mt*16 + lr;
            const int c = 8*nt2 + 2*lq;
            *(float2*)(wy + r*XS + c)     = make_float2(yacc[mt][nt2][0], yacc[mt][nt2][1]);
            *(float2*)(wy + (r+8)*XS + c) = make_float2(yacc[mt][nt2][2], yacc[mt][nt2][3]);
        }
    __syncwarp();

    #pragma unroll
    for (int c = 0; c < 48; c += 4) {
        float4 yv  = *(float4*)(wy + lane*XS + c);
        float4 res = __ldcg((const float4*)(orow + c));   // force reload of residual
        float4 r;
        r.x = res.x + yv.x + s_2b[c];
        r.y = res.y + yv.y + s_2b[c+1];
        r.z = res.z + yv.z + s_2b[c+2];
        r.w = res.w + yv.w + s_2b[c+3];
        *(float4*)(orow + c) = r;
    }
}

// ===========================================================================
extern "C" void kernel_launch(void* const* d_in, const int* in_sizes, int n_in,
                              void* d_out, int out_size)
{
    const float* x      = (const float*)d_in[0];
    const float* g1     = (const float*)d_in[1];
    const float* b1     = (const float*)d_in[2];
    const float* qkvw   = (const float*)d_in[3];
    const float* qkvb   = (const float*)d_in[4];
    const float* rpbt   = (const float*)d_in[5];
    const float* wf     = (const float*)d_in[6];
    const float* sw1    = (const float*)d_in[7];
    const float* sb1    = (const float*)d_in[8];
    const float* sw2    = (const float*)d_in[9];
    const float* sb2    = (const float*)d_in[10];
    const float* pw     = (const float*)d_in[11];
    const float* pb     = (const float*)d_in[12];
    const float* g2     = (const float*)d_in[13];
    const float* b2     = (const float*)d_in[14];
    const float* f1w    = (const float*)d_in[15];
    const float* f1b    = (const float*)d_in[16];
    const float* f2w    = (const float*)d_in[17];
    const float* f2b    = (const float*)d_in[18];
    float* out = (float*)d_out;

    const int a_smem = A_SMEM_FLOATS * 4;   // ~45 KB
    const int b_smem = B_SMEM_FLOATS * 4;   // ~132 KB
    cudaFuncSetAttribute(attn_kernel, cudaFuncAttributeMaxDynamicSharedMemorySize, a_smem);
    cudaFuncSetAttribute(mlp_kernel,  cudaFuncAttributeMaxDynamicSharedMemorySize, b_smem);

    attn_kernel<<<BN, 64, a_smem>>>(x, g1, b1, qkvw, qkvb, rpbt, wf,
                                    sw1, sb1, sw2, sb2, pw, pb);

    mlp_kernel<<<(BB*HH*WWD)/256, 256, b_smem>>>(x, g2, b2, f1w, f1b, f2w, f2b, out);
}

// round 7
// speedup vs baseline: 1.3029x; 1.0002x over previous
#include <cuda_runtime.h>
#include <math.h>
#include <stdint.h>

// ---------------------------------------------------------------------------
// Swin block: B=8, H=W=256, C=48, NH=3 (hd=16), WS=8 (N=64), SS=4, HID=192
// Kernel A (per window, 64 thr): LN1 -> qkv -> attention -> SE -> proj.
// Kernel B (per token block): residual -> LN2 -> tf32 tensor-core MLP.
// ---------------------------------------------------------------------------

#define BB    8
#define HH    256
#define WWD   256
#define CC    48
#define NWIN  1024
#define BN    8192

__device__ float g_attn[(size_t)BB * HH * WWD * CC];

#define SKV 100
#define SSC 65
#define A_SMEM_FLOATS (64*SKV + 64*SSC + 676 + 48 + 48 + 4)

// ---- MLP tensor kernel geometry ----
#define XS  52      // xln / Y staging row stride (floats)
#define W1S 52      // w1 row stride
#define W2S 196     // w2 row stride
#define B_SMEM_FLOATS (192*W1S + 48*W2S + 192 + 48 + 48 + 48 + 8*32*XS)

__device__ __forceinline__ uint32_t f2tf32(float v) {
    uint32_t t;
    asm("cvt.rna.tf32.f32 %0, %1;" : "=r"(t) : "f"(v));
    return t;
}
__device__ __forceinline__ void mma_tf32(float* c, const uint32_t* a, const uint32_t* b) {
    asm volatile("mma.sync.aligned.m16n8k8.row.col.f32.tf32.tf32.f32 "
        "{%0,%1,%2,%3}, {%4,%5,%6,%7}, {%8,%9}, {%0,%1,%2,%3};"
        : "+f"(c[0]), "+f"(c[1]), "+f"(c[2]), "+f"(c[3])
        : "r"(a[0]), "r"(a[1]), "r"(a[2]), "r"(a[3]), "r"(b[0]), "r"(b[1]));
}

// ===========================================================================
__global__ void __launch_bounds__(64) attn_kernel(
    const float* __restrict__ x,
    const float* __restrict__ g1,   const float* __restrict__ b1,
    const float* __restrict__ qkvw, const float* __restrict__ qkvb,
    const float* __restrict__ rpbt, const float* __restrict__ wf,
    const float* __restrict__ sw1,  const float* __restrict__ sb1,
    const float* __restrict__ sw2,  const float* __restrict__ sb2,
    const float* __restrict__ pw,   const float* __restrict__ pb)
{
    extern __shared__ float sm[];
    float* s_kv  = sm;
    float* s_sc  = s_kv + 64*SKV;
    float* s_rpb = s_sc + 64*SSC;
    float* s_mean= s_rpb + 676;
    float* s_se  = s_mean + 48;
    float* s_hh  = s_se + 48;

    const int tid = threadIdx.x;

    for (int i = tid; i < 675; i += 64) s_rpb[i] = __ldg(rpbt + i);

    const int blk = blockIdx.x;
    const int b  = blk >> 10;
    const int w  = blk & 1023;
    const int wy = w >> 5, wx = w & 31;
    const int ti = tid >> 3, tj = tid & 7;
    const int gy = (wy*8 + ti + 4) & 255;
    const int gx = (wx*8 + tj + 4) & 255;
    const size_t pix = ((size_t)b << 16) | (gy << 8) | gx;
    const float* xrow = x + pix * CC;

    float xr[48];
    float mu = 0.f, sq = 0.f;
    #pragma unroll
    for (int c = 0; c < 48; c += 4) {
        float4 v = __ldg((const float4*)(xrow + c));
        xr[c]=v.x; xr[c+1]=v.y; xr[c+2]=v.z; xr[c+3]=v.w;
        mu += v.x + v.y + v.z + v.w;
        sq += v.x*v.x + v.y*v.y + v.z*v.z + v.w*v.w;
    }
    mu *= (1.f/48.f);
    const float inv = rsqrtf(sq*(1.f/48.f) - mu*mu + 1e-5f);
    #pragma unroll
    for (int c = 0; c < 48; c++) {
        xr[c] = (xr[c] - mu) * inv * __ldg(g1 + c) + __ldg(b1 + c);
        s_sc[tid*SSC + c] = xr[c];
    }

    const float4* w4 = (const float4*)qkvw;
    float q[48];
    for (int o = 0; o < 48; o++) {
        float a0=0.f,a1=0.f,a2=0.f,a3=0.f;
        #pragma unroll
        for (int i = 0; i < 12; i++) {
            float4 wv = __ldg(w4 + o*12 + i);
            a0 += xr[4*i+0]*wv.x; a1 += xr[4*i+1]*wv.y;
            a2 += xr[4*i+2]*wv.z; a3 += xr[4*i+3]*wv.w;
        }
        q[o] = ((a0+a1)+(a2+a3) + __ldg(qkvb + o)) * 0.25f;
    }
    for (int o = 0; o < 96; o++) {
        float a0=0.f,a1=0.f,a2=0.f,a3=0.f;
        #pragma unroll
        for (int i = 0; i < 12; i++) {
            float4 wv = __ldg(w4 + (48+o)*12 + i);
            a0 += xr[4*i+0]*wv.x; a1 += xr[4*i+1]*wv.y;
            a2 += xr[4*i+2]*wv.z; a3 += xr[4*i+3]*wv.w;
        }
        s_kv[tid*SKV + o] = (a0+a1)+(a2+a3) + __ldg(qkvb + 48 + o);
    }
    __syncthreads();

    if (tid < 48) {
        float s = 0.f;
        for (int t = 0; t < 64; t++) s += s_sc[t*SSC + tid];
        s_mean[tid] = s * (1.f/64.f);
    }
    __syncthreads();
    if (tid < 3) {
        float a = __ldg(sb1 + tid);
        #pragma unroll
        for (int c = 0; c < 48; c++) a += s_mean[c] * __ldg(sw1 + tid*48 + c);
        s_hh[tid] = fmaxf(a, 0.f);
    }
    __syncthreads();
    if (tid < 48) {
        float a = __ldg(sb2 + tid) + s_hh[0]*__ldg(sw2 + tid*3+0)
                                   + s_hh[1]*__ldg(sw2 + tid*3+1)
                                   + s_hh[2]*__ldg(sw2 + tid*3+2);
        s_se[tid] = 1.f/(1.f + __expf(-a));
    }
    __syncthreads();

    float out[48];
    #pragma unroll
    for (int c = 0; c < 48; c++) out[c] = 0.f;

    const int regy = (wy == 31) ? (ti >= 4 ? 2 : 1) : 0;
    const int regx = (wx == 31) ? (tj >= 4 ? 2 : 1) : 0;
    float* myrow = s_sc + tid*SSC;

    for (int h = 0; h < 3; h++) {
        float mx = -1e30f;
        for (int j = 0; j < 64; j++) {
            const float4* kr = (const float4*)(s_kv + j*SKV + h*16);
            float s0=0.f,s1=0.f,s2=0.f,s3=0.f;
            #pragma unroll
            for (int i = 0; i < 4; i++) {
                float4 kv = kr[i];
                s0 += q[h*16+4*i+0]*kv.x; s1 += q[h*16+4*i+1]*kv.y;
                s2 += q[h*16+4*i+2]*kv.z; s3 += q[h*16+4*i+3]*kv.w;
            }
            float s = (s0+s1)+(s2+s3);
            const int rj = j >> 3, cj = j & 7;
            s += s_rpb[((ti - rj + 7)*15 + (tj - cj + 7))*3 + h];
            const int ryj = (wy == 31) ? (rj >= 4 ? 2 : 1) : 0;
            const int rxj = (wx == 31) ? (cj >= 4 ? 2 : 1) : 0;
            if (ryj != regy || rxj != regx) s -= 100.f;
            myrow[j] = s;
            mx = fmaxf(mx, s);
        }
        float sum = 0.f;
        for (int j = 0; j < 64; j++) {
            float e = __expf(myrow[j] - mx);
            myrow[j] = e;
            sum += e;
        }
        const float is = 1.f / sum;
        for (int j = 0; j < 64; j++) {
            const float wgt = myrow[j] * is;
            const float4* vr = (const float4*)(s_kv + j*SKV + 48 + h*16);
            #pragma unroll
            for (int i = 0; i < 4; i++) {
                float4 vv = vr[i];
                out[h*16+4*i+0] += wgt*vv.x; out[h*16+4*i+1] += wgt*vv.y;
                out[h*16+4*i+2] += wgt*vv.z; out[h*16+4*i+3] += wgt*vv.w;
            }
        }
    }

    const float wfv = __ldg(wf);
    #pragma unroll
    for (int c = 0; c < 48; c++) out[c] += wfv * xr[c] * s_se[c];

    const float4* pw4 = (const float4*)pw;
    float* orow = g_attn + pix * CC;
    #pragma unroll 2
    for (int c4 = 0; c4 < 48; c4 += 4) {
        float4 r;
        #pragma unroll
        for (int k = 0; k < 4; k++) {
            const int cp = c4 + k;
            float a0=0.f,a1=0.f,a2=0.f,a3=0.f;
            #pragma unroll
            for (int i = 0; i < 12; i++) {
                float4 wv = __ldg(pw4 + cp*12 + i);
                a0 += out[4*i+0]*wv.x; a1 += out[4*i+1]*wv.y;
                a2 += out[4*i+2]*wv.z; a3 += out[4*i+3]*wv.w;
            }
            ((float*)&r)[k] = (a0+a1)+(a2+a3) + __ldg(pb + cp);
        }
        *(float4*)(orow + c4) = r;
    }
}

// ===========================================================================
// MLP: tf32 mma.sync tensor-core pipeline. 256 thr = 8 warps, 32 tokens/warp.
// ===========================================================================
__global__ void __launch_bounds__(256) mlp_kernel(
    const float* __restrict__ x,
    const float* __restrict__ g2,   const float* __restrict__ b2,
    const float* __restrict__ f1w,  const float* __restrict__ f1b,
    const float* __restrict__ f2w,  const float* __restrict__ f2b,
    float* __restrict__ out)
{
    extern __shared__ float sm[];
    uint32_t* s_w1 = (uint32_t*)sm;                    // 192 x W1S  tf32 bits
    uint32_t* s_w2 = (uint32_t*)(sm + 192*W1S);        // 48  x W2S  tf32 bits
    float* s_b1 = sm + 192*W1S + 48*W2S;               // 192
    float* s_2b = s_b1 + 192;                          // 48
    float* s_g2 = s_2b + 48;                           // 48
    float* s_b2 = s_g2 + 48;                           // 48
    float* s_xg = s_b2 + 48;                           // 8 warps x 32 x XS

    const int tid  = threadIdx.x;
    const int wid  = tid >> 5;
    const int lane = tid & 31;
    const int lr   = lane >> 2;        // 0..7
    const int lq   = lane & 3;         // 0..3
    const bool odd = lane & 1;

    // ---- stage weights (pre-converted to tf32) ---------------------------
    for (int i = tid; i < 192*48; i += 256) {
        s_w1[(i/48)*W1S + (i%48)]   = f2tf32(f1w[i]);    // [hid][ch]
        s_w2[(i/192)*W2S + (i%192)] = f2tf32(f2w[i]);    // [ch][hid]
    }
    for (int i = tid; i < 192; i += 256) s_b1[i] = f1b[i];
    if (tid < 48) { s_2b[tid] = f2b[tid]; s_g2[tid] = g2[tid]; s_b2[tid] = b2[tid]; }
    __syncthreads();

    // ---- residual + LN2 (thread = token), store tf32(xln) ----------------
    const size_t tok = (size_t)blockIdx.x*256 + tid;
    const float* xrow = x      + tok*48;
    const float* hrow = g_attn + tok*48;
    float* orow = out + tok*48;

    {
        float v[48];
        float mu = 0.f, sq = 0.f;
        #pragma unroll
        for (int c = 0; c < 48; c += 4) {
            float4 a = __ldg((const float4*)(xrow + c));
            float4 h = *(const float4*)(hrow + c);
            float4 s;
            s.x = a.x + h.x; s.y = a.y + h.y; s.z = a.z + h.z; s.w = a.w + h.w;
            *(float4*)(orow + c) = s;                 // residual parked in out
            v[c]=s.x; v[c+1]=s.y; v[c+2]=s.z; v[c+3]=s.w;
            mu += s.x + s.y + s.z + s.w;
            sq += s.x*s.x + s.y*s.y + s.z*s.z + s.w*s.w;
        }
        mu *= (1.f/48.f);
        const float inv = rsqrtf(sq*(1.f/48.f) - mu*mu + 1e-5f);
        uint32_t* myx = (uint32_t*)(s_xg + (size_t)wid*32*XS + lane*XS);
        #pragma unroll
        for (int c = 0; c < 48; c++)
            myx[c] = f2tf32((v[c] - mu) * inv * s_g2[c] + s_b2[c]);
    }
    __syncthreads();

    // ---- load full A (xln 32x48) as mma fragments: 2 m-tiles x 6 k-tiles --
    uint32_t afr[2][6][4];
    {
        const uint32_t* wx = (const uint32_t*)(s_xg + (size_t)wid*32*XS);
        #pragma unroll
        for (int mt = 0; mt < 2; mt++)
            #pragma unroll
            for (int kt = 0; kt < 6; kt++) {
                const int r = mt*16 + lr, c = kt*8 + lq;
                afr[mt][kt][0] = wx[r*XS + c];
                afr[mt][kt][1] = wx[(r+8)*XS + c];
                afr[mt][kt][2] = wx[r*XS + c + 4];
                afr[mt][kt][3] = wx[(r+8)*XS + c + 4];
            }
    }

    // ---- main loop over 24 hidden chunks of 8 -----------------------------
    float yacc[2][6][4];
    #pragma unroll
    for (int mt = 0; mt < 2; mt++)
        #pragma unroll
        for (int nt = 0; nt < 6; nt++)
            #pragma unroll
            for (int r = 0; r < 4; r++) yacc[mt][nt][r] = 0.f;

    for (int nt = 0; nt < 24; nt++) {
        // GEMM1: H chunk [32 x 8] = xln [32x48] * W1chunk^T
        uint32_t bf[6][2];
        #pragma unroll
        for (int kt = 0; kt < 6; kt++) {
            const uint32_t* wr = s_w1 + (8*nt + lr)*W1S + kt*8 + lq;
            bf[kt][0] = wr[0];
            bf[kt][1] = wr[4];
        }
        float h[2][4] = {{0.f,0.f,0.f,0.f},{0.f,0.f,0.f,0.f}};
        #pragma unroll
        for (int kt = 0; kt < 6; kt++) {
            mma_tf32(h[0], afr[0][kt], bf[kt]);
            mma_tf32(h[1], afr[1][kt], bf[kt]);
        }
        // bias + exact GELU
        const float2 bb = *(const float2*)(s_b1 + 8*nt + 2*lq);
        #pragma unroll
        for (int mt = 0; mt < 2; mt++)
            #pragma unroll
            for (int r = 0; r < 4; r++) {
                const float hs = h[mt][r] + ((r & 1) ? bb.y : bb.x);
                h[mt][r] = 0.5f * hs * (1.f + erff(hs * 0.7071067811865476f));
            }
        // C-frag -> A-frag remap via shuffles (G = gelu'd chunk, 32x8)
        uint32_t ga[2][4];
        const int s0 = (lane & ~3) | ((lane & 3) >> 1);
        const int s2 = s0 + 2;
        #pragma unroll
        for (int mt = 0; mt < 2; mt++) {
            const float p0 = __shfl_sync(0xffffffffu, h[mt][0], s0);
            const float p1 = __shfl_sync(0xffffffffu, h[mt][1], s0);
            const float p2 = __shfl_sync(0xffffffffu, h[mt][2], s0);
            const float p3 = __shfl_sync(0xffffffffu, h[mt][3], s0);
            const float q0 = __shfl_sync(0xffffffffu, h[mt][0], s2);
            const float q1 = __shfl_sync(0xffffffffu, h[mt][1], s2);
            const float q2 = __shfl_sync(0xffffffffu, h[mt][2], s2);
            const float q3 = __shfl_sync(0xffffffffu, h[mt][3], s2);
            ga[mt][0] = f2tf32(odd ? p1 : p0);
            ga[mt][1] = f2tf32(odd ? p3 : p2);
            ga[mt][2] = f2tf32(odd ? q1 : q0);
            ga[mt][3] = f2tf32(odd ? q3 : q2);
        }
        // GEMM2: Y [32 x 48] += G [32x8] * W2chunk [8 x 48]
        #pragma unroll
        for (int nt2 = 0; nt2 < 6; nt2++) {
            uint32_t b2f[2];
            const uint32_t* wr = s_w2 + (8*nt2 + lr)*W2S + 8*nt + lq;
            b2f[0] = wr[0];
            b2f[1] = wr[4];
            mma_tf32(yacc[0][nt2], ga[0], b2f);
            mma_tf32(yacc[1][nt2], ga[1], b2f);
        }
    }

    // ---- epilogue: stage Y in (reused) warp buffer, coalesced writeback ---
    __syncwarp();
    float* wy = s_xg + (size_t)wid*32*XS;
    #pragma unroll
    for (int mt = 0; mt < 2; mt++)
        #pragma unroll
        for (int nt2 = 0; nt2 < 6; nt2++) {
            const int r = mt*16 + lr;
            const int c = 8*nt2 + 2*lq;
            *(float2*)(wy + r*XS + c)     = make_float2(yacc[mt][nt2][0], yacc[mt][nt2][1]);
            *(float2*)(wy + (r+8)*XS + c) = make_float2(yacc[mt][nt2][2], yacc[mt][nt2][3]);
        }
    __syncwarp();

    #pragma unroll
    for (int c = 0; c < 48; c += 4) {
        float4 yv  = *(float4*)(wy + lane*XS + c);
        float4 res = __ldcg((const float4*)(orow + c));   // force reload of residual
        float4 r;
        r.x = res.x + yv.x + s_2b[c];
        r.y = res.y + yv.y + s_2b[c+1];
        r.z = res.z + yv.z + s_2b[c+2];
        r.w = res.w + yv.w + s_2b[c+3];
        *(float4*)(orow + c) = r;
    }
}

// ===========================================================================
extern "C" void kernel_launch(void* const* d_in, const int* in_sizes, int n_in,
                              void* d_out, int out_size)
{
    const float* x      = (const float*)d_in[0];
    const float* g1     = (const float*)d_in[1];
    const float* b1     = (const float*)d_in[2];
    const float* qkvw   = (const float*)d_in[3];
    const float* qkvb   = (const float*)d_in[4];
    const float* rpbt   = (const float*)d_in[5];
    const float* wf     = (const float*)d_in[6];
    const float* sw1    = (const float*)d_in[7];
    const float* sb1    = (const float*)d_in[8];
    const float* sw2    = (const float*)d_in[9];
    const float* sb2    = (const float*)d_in[10];
    const float* pw     = (const float*)d_in[11];
    const float* pb     = (const float*)d_in[12];
    const float* g2     = (const float*)d_in[13];
    const float* b2     = (const float*)d_in[14];
    const float* f1w    = (const float*)d_in[15];
    const float* f1b    = (const float*)d_in[16];
    const float* f2w    = (const float*)d_in[17];
    const float* f2b    = (const float*)d_in[18];
    float* out = (float*)d_out;

    const int a_smem = A_SMEM_FLOATS * 4;   // ~45 KB
    const int b_smem = B_SMEM_FLOATS * 4;   // ~132 KB
    cudaFuncSetAttribute(attn_kernel, cudaFuncAttributeMaxDynamicSharedMemorySize, a_smem);
    cudaFuncSetAttribute(mlp_kernel,  cudaFuncAttributeMaxDynamicSharedMemorySize, b_smem);

    attn_kernel<<<BN, 64, a_smem>>>(x, g1, b1, qkvw, qkvb, rpbt, wf,
                                    sw1, sb1, sw2, sb2, pw, pb);

    mlp_kernel<<<(BB*HH*WWD)/256, 256, b_smem>>>(x, g2, b2, f1w, f1b, f2w, f2b, out);
}

// round 8
// speedup vs baseline: 2.3523x; 1.8055x over previous
#include <cuda_runtime.h>
#include <math.h>
#include <stdint.h>

// ---------------------------------------------------------------------------
// Swin block: B=8, H=W=256, C=48, NH=3 (hd=16), WS=8 (N=64), SS=4, HID=192
// Kernel A: 4 windows/CTA, 2 warps/window. All GEMM stages (qkv, q.k^T, P.V,
//           proj) on tf32 mma.sync; softmax in fragment registers.
// Kernel B: tf32 tensor-core MLP (unchanged from R7).
// ---------------------------------------------------------------------------

#define BB    8
#define HH    256
#define WWD   256
#define CC    48
#define NWIN  1024
#define BN    8192

__device__ float g_attn[(size_t)BB * HH * WWD * CC];

__device__ __forceinline__ uint32_t f2tf32(float v) {
    uint32_t t;
    asm("cvt.rna.tf32.f32 %0, %1;" : "=r"(t) : "f"(v));
    return t;
}
__device__ __forceinline__ void mma_tf32(float* c, const uint32_t* a, const uint32_t* b) {
    asm volatile("mma.sync.aligned.m16n8k8.row.col.f32.tf32.tf32.f32 "
        "{%0,%1,%2,%3}, {%4,%5,%6,%7}, {%8,%9}, {%0,%1,%2,%3};"
        : "+f"(c[0]), "+f"(c[1]), "+f"(c[2]), "+f"(c[3])
        : "r"(a[0]), "r"(a[1]), "r"(a[2]), "r"(a[3]), "r"(b[0]), "r"(b[1]));
}
// C-fragment (m16n8 tile, 4 floats) -> A-fragment (m16k8 tile, 4 tf32 regs).
__device__ __forceinline__ void c2a(const float* c, uint32_t* a, int lane) {
    const int s0 = (lane & ~3) | ((lane & 3) >> 1);
    const int s2 = s0 + 2;
    const bool odd = lane & 1;
    float p0 = __shfl_sync(0xffffffffu, c[0], s0), p1 = __shfl_sync(0xffffffffu, c[1], s0);
    float p2 = __shfl_sync(0xffffffffu, c[2], s0), p3 = __shfl_sync(0xffffffffu, c[3], s0);
    float q0 = __shfl_sync(0xffffffffu, c[0], s2), q1 = __shfl_sync(0xffffffffu, c[1], s2);
    float q2 = __shfl_sync(0xffffffffu, c[2], s2), q3 = __shfl_sync(0xffffffffu, c[3], s2);
    a[0] = f2tf32(odd ? p1 : p0);
    a[1] = f2tf32(odd ? p3 : p2);
    a[2] = f2tf32(odd ? q1 : q0);
    a[3] = f2tf32(odd ? q3 : q2);
}

// ---- attn smem layout (floats) ----
#define SXW  52      // s_x row stride
#define SKVW 100     // s_kv row stride
#define OFF_WQ   0                       // 144*52 tf32 (uint bits)
#define OFF_WP   (OFF_WQ  + 144*52)      // 48*52
#define OFF_RPB  (OFF_WP  + 48*52)       // 676
#define OFF_QKVB (OFF_RPB + 676)         // 144
#define OFF_PB   (OFF_QKVB+ 144)         // 48
#define OFF_SW1  (OFF_PB  + 48)          // 144
#define OFF_SB1  (OFF_SW1 + 144)         // 4
#define OFF_SW2  (OFF_SB1 + 4)           // 144
#define OFF_SB2  (OFF_SW2 + 144)         // 48
#define OFF_MEAN (OFF_SB2 + 48)          // 192
#define OFF_SE   (OFF_MEAN+ 192)         // 192
#define OFF_HH   (OFF_SE  + 192)         // 16
#define OFF_X    (OFF_HH  + 16)          // 4 * 64*52
#define OFF_KV   (OFF_X   + 4*64*SXW)    // 4 * 64*100
#define A_SMEM_FLOATS (OFF_KV + 4*64*SKVW)

__global__ void __launch_bounds__(256) attn_kernel(
    const float* __restrict__ x,
    const float* __restrict__ g1,   const float* __restrict__ b1,
    const float* __restrict__ qkvw, const float* __restrict__ qkvb,
    const float* __restrict__ rpbt, const float* __restrict__ wf,
    const float* __restrict__ sw1,  const float* __restrict__ sb1,
    const float* __restrict__ sw2,  const float* __restrict__ sb2,
    const float* __restrict__ pw,   const float* __restrict__ pb)
{
    extern __shared__ float sm[];
    uint32_t* s_wq = (uint32_t*)(sm + OFF_WQ);
    uint32_t* s_wp = (uint32_t*)(sm + OFF_WP);

    const int tid  = threadIdx.x;
    const int wid  = tid >> 5;
    const int lane = tid & 31;
    const int lr   = lane >> 2;
    const int lq   = lane & 3;

    // ---- stage weights (tf32) + tables -----------------------------------
    for (int i = tid; i < 144*48; i += 256)
        s_wq[(i/48)*SXW + (i%48)] = f2tf32(qkvw[i]);
    for (int i = tid; i < 48*48; i += 256)
        s_wp[(i/48)*SXW + (i%48)] = f2tf32(pw[i]);
    for (int i = tid; i < 675; i += 256) sm[OFF_RPB + i] = __ldg(rpbt + i);
    for (int i = tid; i < 144; i += 256) {
        sm[OFF_QKVB + i] = qkvb[i];
        sm[OFF_SW1  + i] = sw1[i];
        sm[OFF_SW2  + i] = sw2[i];
    }
    if (tid < 48) { sm[OFF_PB + tid] = pb[tid]; sm[OFF_SB2 + tid] = sb2[tid]; }
    if (tid < 3)  sm[OFF_SB1 + tid] = sb1[tid];

    // ---- LN1: thread = one token of one window ---------------------------
    {
        const int wl2 = tid >> 6, tok2 = tid & 63;
        const int wg2 = blockIdx.x*4 + wl2;
        const int b2 = wg2 >> 10, ww = wg2 & 1023;
        const int wy2 = ww >> 5, wx2 = ww & 31;
        const int gy = (wy2*8 + (tok2 >> 3) + 4) & 255;
        const int gx = (wx2*8 + (tok2 & 7) + 4) & 255;
        const float* xrow = x + (((size_t)b2 << 16) | (gy << 8) | gx) * CC;
        float v[48];
        float mu = 0.f, sq = 0.f;
        #pragma unroll
        for (int c = 0; c < 48; c += 4) {
            float4 t = __ldg((const float4*)(xrow + c));
            v[c]=t.x; v[c+1]=t.y; v[c+2]=t.z; v[c+3]=t.w;
            mu += t.x + t.y + t.z + t.w;
            sq += t.x*t.x + t.y*t.y + t.z*t.z + t.w*t.w;
        }
        mu *= (1.f/48.f);
        const float inv = rsqrtf(sq*(1.f/48.f) - mu*mu + 1e-5f);
        float* xw = sm + OFF_X + wl2*64*SXW + tok2*SXW;
        #pragma unroll
        for (int c = 0; c < 48; c++)
            xw[c] = __uint_as_float(f2tf32((v[c] - mu) * inv * __ldg(g1 + c) + __ldg(b1 + c)));
    }
    __syncthreads();

    // ---- SE: mean -> fc1+relu -> fc2+sigmoid ------------------------------
    if (tid < 192) {
        const int wl2 = tid / 48, c = tid % 48;
        const float* xw = sm + OFF_X + wl2*64*SXW;
        float s = 0.f;
        for (int t = 0; t < 64; t++) s += xw[t*SXW + c];
        sm[OFF_MEAN + wl2*48 + c] = s * (1.f/64.f);
    }
    __syncthreads();
    if (tid < 12) {
        const int wl2 = tid / 3, o = tid % 3;
        float a = sm[OFF_SB1 + o];
        #pragma unroll
        for (int c = 0; c < 48; c++) a += sm[OFF_MEAN + wl2*48 + c] * sm[OFF_SW1 + o*48 + c];
        sm[OFF_HH + wl2*4 + o] = fmaxf(a, 0.f);
    }
    __syncthreads();
    if (tid < 192) {
        const int wl2 = tid / 48, c = tid % 48;
        float a = sm[OFF_SB2 + c] + sm[OFF_HH + wl2*4 + 0]*sm[OFF_SW2 + c*3 + 0]
                                  + sm[OFF_HH + wl2*4 + 1]*sm[OFF_SW2 + c*3 + 1]
                                  + sm[OFF_HH + wl2*4 + 2]*sm[OFF_SW2 + c*3 + 2];
        sm[OFF_SE + wl2*48 + c] = 1.f/(1.f + __expf(-a));
    }
    __syncthreads();

    // ---- per-warp geometry -------------------------------------------------
    const int wl   = wid >> 1;          // window 0..3 in CTA
    const int half = wid & 1;           // token half: 0 -> 0..31, 1 -> 32..63
    const int wg = blockIdx.x*4 + wl;
    const int bimg = wg >> 10, ww = wg & 1023;
    const int wy = ww >> 5, wx = ww & 31;
    float* xw  = sm + OFF_X  + wl*64*SXW;
    float* kvw = sm + OFF_KV + wl*64*SKVW;

    // ---- qkv GEMM: A = xln[32x48] frags ------------------------------------
    uint32_t afr[2][6][4];
    #pragma unroll
    for (int mt = 0; mt < 2; mt++)
        #pragma unroll
        for (int kt = 0; kt < 6; kt++) {
            const float* bp = xw + (half*32 + mt*16 + lr)*SXW + kt*8 + lq;
            afr[mt][kt][0] = __float_as_uint(bp[0]);
            afr[mt][kt][1] = __float_as_uint(bp[8*SXW]);
            afr[mt][kt][2] = __float_as_uint(bp[4]);
            afr[mt][kt][3] = __float_as_uint(bp[8*SXW + 4]);
        }

    float qf[2][6][4];          // q C-frags (pre-scaled)
    for (int nt = 0; nt < 18; nt++) {
        float cf0[4] = {0.f,0.f,0.f,0.f}, cf1[4] = {0.f,0.f,0.f,0.f};
        #pragma unroll
        for (int kt = 0; kt < 6; kt++) {
            uint32_t bf[2];
            const uint32_t* wr = s_wq + (nt*8 + lr)*SXW + kt*8 + lq;
            bf[0] = wr[0]; bf[1] = wr[4];
            mma_tf32(cf0, afr[0][kt], bf);
            mma_tf32(cf1, afr[1][kt], bf);
        }
        const float be = sm[OFF_QKVB + nt*8 + 2*lq];
        const float bo = sm[OFF_QKVB + nt*8 + 2*lq + 1];
        if (nt < 6) {
            qf[0][nt][0]=(cf0[0]+be)*0.25f; qf[0][nt][1]=(cf0[1]+bo)*0.25f;
            qf[0][nt][2]=(cf0[2]+be)*0.25f; qf[0][nt][3]=(cf0[3]+bo)*0.25f;
            qf[1][nt][0]=(cf1[0]+be)*0.25f; qf[1][nt][1]=(cf1[1]+bo)*0.25f;
            qf[1][nt][2]=(cf1[2]+be)*0.25f; qf[1][nt][3]=(cf1[3]+bo)*0.25f;
        } else {
            const int col = (nt - 6)*8 + 2*lq;
            const int rA0 = half*32 + lr, rA1 = half*32 + 16 + lr;
            *(float2*)(kvw + rA0*SKVW + col) = make_float2(
                __uint_as_float(f2tf32(cf0[0]+be)), __uint_as_float(f2tf32(cf0[1]+bo)));
            *(float2*)(kvw + (rA0+8)*SKVW + col) = make_float2(
                __uint_as_float(f2tf32(cf0[2]+be)), __uint_as_float(f2tf32(cf0[3]+bo)));
            *(float2*)(kvw + rA1*SKVW + col) = make_float2(
                __uint_as_float(f2tf32(cf1[0]+be)), __uint_as_float(f2tf32(cf1[1]+bo)));
            *(float2*)(kvw + (rA1+8)*SKVW + col) = make_float2(
                __uint_as_float(f2tf32(cf1[2]+be)), __uint_as_float(f2tf32(cf1[3]+bo)));
        }
    }
    __syncthreads();   // k/v tiles visible to both warps of the window

    // ---- attention ----------------------------------------------------------
    float oacc[2][6][4];
    #pragma unroll
    for (int mt = 0; mt < 2; mt++)
        #pragma unroll
        for (int n = 0; n < 6; n++)
            #pragma unroll
            for (int r = 0; r < 4; r++) oacc[mt][n][r] = 0.f;

    const bool edge = (wy == 31) || (wx == 31);

    for (int h = 0; h < 3; h++) {
        uint32_t qa[2][2][4];
        #pragma unroll
        for (int mt = 0; mt < 2; mt++) {
            c2a(qf[mt][2*h+0], qa[mt][0], lane);
            c2a(qf[mt][2*h+1], qa[mt][1], lane);
        }
        float sf[2][8][4];
        #pragma unroll
        for (int mt = 0; mt < 2; mt++)
            #pragma unroll
            for (int nt = 0; nt < 8; nt++)
                #pragma unroll
                for (int r = 0; r < 4; r++) sf[mt][nt][r] = 0.f;

        #pragma unroll
        for (int nt = 0; nt < 8; nt++) {
            uint32_t bf[2][2];
            #pragma unroll
            for (int kt = 0; kt < 2; kt++) {
                const float* kb = kvw + (nt*8 + lr)*SKVW + h*16 + kt*8 + lq;
                bf[kt][0] = __float_as_uint(kb[0]);
                bf[kt][1] = __float_as_uint(kb[4]);
            }
            #pragma unroll
            for (int mt = 0; mt < 2; mt++) {
                mma_tf32(sf[mt][nt], qa[mt][0], bf[0]);
                mma_tf32(sf[mt][nt], qa[mt][1], bf[1]);
            }
        }

        // rpb + shift mask, then softmax per row
        #pragma unroll
        for (int mt = 0; mt < 2; mt++) {
            const int iA = half*32 + mt*16 + lr, iB = iA + 8;
            const int tiA = iA >> 3, tjA = iA & 7;
            const int tiB = iB >> 3, tjB = iB & 7;
            const int ryA = edge && (wy==31) ? (tiA >= 4 ? 2 : 1) : 0;
            const int rxA = edge && (wx==31) ? (tjA >= 4 ? 2 : 1) : 0;
            const int ryB = edge && (wy==31) ? (tiB >= 4 ? 2 : 1) : 0;
            const int rxB = edge && (wx==31) ? (tjB >= 4 ? 2 : 1) : 0;
            #pragma unroll
            for (int nt = 0; nt < 8; nt++) {
                #pragma unroll
                for (int e = 0; e < 2; e++) {
                    const int j = nt*8 + 2*lq + e;
                    const int rj = j >> 3, cj = j & 7;
                    const float bA = sm[OFF_RPB + ((tiA - rj + 7)*15 + (tjA - cj + 7))*3 + h];
                    const float bB = sm[OFF_RPB + ((tiB - rj + 7)*15 + (tjB - cj + 7))*3 + h];
                    float mA = 0.f, mB = 0.f;
                    if (edge) {
                        const int ryj = (wy==31) ? (rj >= 4 ? 2 : 1) : 0;
                        const int rxj = (wx==31) ? (cj >= 4 ? 2 : 1) : 0;
                        if (ryj != ryA || rxj != rxA) mA = -100.f;
                        if (ryj != ryB || rxj != rxB) mB = -100.f;
                    }
                    sf[mt][nt][e]   += bA + mA;
                    sf[mt][nt][e+2] += bB + mB;
                }
            }
            float mxA = -1e30f, mxB = -1e30f;
            #pragma unroll
            for (int nt = 0; nt < 8; nt++) {
                mxA = fmaxf(mxA, fmaxf(sf[mt][nt][0], sf[mt][nt][1]));
                mxB = fmaxf(mxB, fmaxf(sf[mt][nt][2], sf[mt][nt][3]));
            }
            mxA = fmaxf(mxA, __shfl_xor_sync(0xffffffffu, mxA, 1));
            mxA = fmaxf(mxA, __shfl_xor_sync(0xffffffffu, mxA, 2));
            mxB = fmaxf(mxB, __shfl_xor_sync(0xffffffffu, mxB, 1));
            mxB = fmaxf(mxB, __shfl_xor_sync(0xffffffffu, mxB, 2));
            float sA = 0.f, sB = 0.f;
            #pragma unroll
            for (int nt = 0; nt < 8; nt++) {
                sf[mt][nt][0] = __expf(sf[mt][nt][0] - mxA);
                sf[mt][nt][1] = __expf(sf[mt][nt][1] - mxA);
                sf[mt][nt][2] = __expf(sf[mt][nt][2] - mxB);
                sf[mt][nt][3] = __expf(sf[mt][nt][3] - mxB);
                sA += sf[mt][nt][0] + sf[mt][nt][1];
                sB += sf[mt][nt][2] + sf[mt][nt][3];
            }
            sA += __shfl_xor_sync(0xffffffffu, sA, 1);
            sA += __shfl_xor_sync(0xffffffffu, sA, 2);
            sB += __shfl_xor_sync(0xffffffffu, sB, 1);
            sB += __shfl_xor_sync(0xffffffffu, sB, 2);
            const float rAi = 1.f / sA, rBi = 1.f / sB;
            #pragma unroll
            for (int nt = 0; nt < 8; nt++) {
                sf[mt][nt][0] *= rAi; sf[mt][nt][1] *= rAi;
                sf[mt][nt][2] *= rBi; sf[mt][nt][3] *= rBi;
            }
        }

        // P.V : A-frags from sf n-tiles, B from v (stored [key][dim])
        #pragma unroll
        for (int kt = 0; kt < 8; kt++) {
            uint32_t pa[2][4];
            c2a(sf[0][kt], pa[0], lane);
            c2a(sf[1][kt], pa[1], lane);
            #pragma unroll
            for (int nt2 = 0; nt2 < 2; nt2++) {
                uint32_t bf[2];
                bf[0] = __float_as_uint(kvw[(kt*8 + lq  )*SKVW + 48 + h*16 + nt2*8 + lr]);
                bf[1] = __float_as_uint(kvw[(kt*8 + lq+4)*SKVW + 48 + h*16 + nt2*8 + lr]);
                mma_tf32(oacc[0][2*h + nt2], pa[0], bf);
                mma_tf32(oacc[1][2*h + nt2], pa[1], bf);
            }
        }
    }

    // ---- SE add --------------------------------------------------------------
    {
        const float wfv = __ldg(wf);
        const float* sew = sm + OFF_SE + wl*48;
        #pragma unroll
        for (int mt = 0; mt < 2; mt++) {
            const int rA = half*32 + mt*16 + lr, rB = rA + 8;
            #pragma unroll
            for (int n = 0; n < 6; n++) {
                const int c0 = n*8 + 2*lq;
                oacc[mt][n][0] += wfv * xw[rA*SXW + c0    ] * sew[c0];
                oacc[mt][n][1] += wfv * xw[rA*SXW + c0 + 1] * sew[c0+1];
                oacc[mt][n][2] += wfv * xw[rB*SXW + c0    ] * sew[c0];
                oacc[mt][n][3] += wfv * xw[rB*SXW + c0 + 1] * sew[c0+1];
            }
        }
    }

    // ---- proj GEMM -------------------------------------------------------------
    uint32_t oa[2][6][4];
    #pragma unroll
    for (int mt = 0; mt < 2; mt++)
        #pragma unroll
        for (int kt = 0; kt < 6; kt++) c2a(oacc[mt][kt], oa[mt][kt], lane);

    #pragma unroll
    for (int nt = 0; nt < 6; nt++) {
        float pf0[4] = {0.f,0.f,0.f,0.f}, pf1[4] = {0.f,0.f,0.f,0.f};
        #pragma unroll
        for (int kt = 0; kt < 6; kt++) {
            uint32_t bf[2];
            const uint32_t* wr = s_wp + (nt*8 + lr)*SXW + kt*8 + lq;
            bf[0] = wr[0]; bf[1] = wr[4];
            mma_tf32(pf0, oa[0][kt], bf);
            mma_tf32(pf1, oa[1][kt], bf);
        }
        const float be = sm[OFF_PB + nt*8 + 2*lq];
        const float bo = sm[OFF_PB + nt*8 + 2*lq + 1];
        const int rA0 = half*32 + lr, rA1 = rA0 + 16;
        *(float2*)(xw + rA0*SXW     + nt*8 + 2*lq) = make_float2(pf0[0]+be, pf0[1]+bo);
        *(float2*)(xw + (rA0+8)*SXW + nt*8 + 2*lq) = make_float2(pf0[2]+be, pf0[3]+bo);
        *(float2*)(xw + rA1*SXW     + nt*8 + 2*lq) = make_float2(pf1[0]+be, pf1[1]+bo);
        *(float2*)(xw + (rA1+8)*SXW + nt*8 + 2*lq) = make_float2(pf1[2]+be, pf1[3]+bo);
    }
    __syncwarp();

    // ---- coalesced scatter to g_attn -------------------------------------------
    {
        const int tok = half*32 + lane;
        const int gy = (wy*8 + (tok >> 3) + 4) & 255;
        const int gx = (wx*8 + (tok & 7) + 4) & 255;
        float* orow = g_attn + (((size_t)bimg << 16) | (gy << 8) | gx) * CC;
        const float* srow = xw + tok*SXW;
        #pragma unroll
        for (int c = 0; c < 48; c += 4)
            *(float4*)(orow + c) = *(const float4*)(srow + c);
    }
}

// ===========================================================================
// MLP: tf32 mma.sync tensor-core pipeline (unchanged from R7).
// ===========================================================================
#define XS  52
#define W1S 52
#define W2S 196
#define B_SMEM_FLOATS (192*W1S + 48*W2S + 192 + 48 + 48 + 48 + 8*32*XS)

__global__ void __launch_bounds__(256) mlp_kernel(
    const float* __restrict__ x,
    const float* __restrict__ g2,   const float* __restrict__ b2,
    const float* __restrict__ f1w,  const float* __restrict__ f1b,
    const float* __restrict__ f2w,  const float* __restrict__ f2b,
    float* __restrict__ out)
{
    extern __shared__ float sm[];
    uint32_t* s_w1 = (uint32_t*)sm;
    uint32_t* s_w2 = (uint32_t*)(sm + 192*W1S);
    float* s_b1 = sm + 192*W1S + 48*W2S;
    float* s_2b = s_b1 + 192;
    float* s_g2 = s_2b + 48;
    float* s_b2 = s_g2 + 48;
    float* s_xg = s_b2 + 48;

    const int tid  = threadIdx.x;
    const int wid  = tid >> 5;
    const int lane = tid & 31;
    const int lr   = lane >> 2;
    const int lq   = lane & 3;
    const bool odd = lane & 1;

    for (int i = tid; i < 192*48; i += 256) {
        s_w1[(i/48)*W1S + (i%48)]   = f2tf32(f1w[i]);
        s_w2[(i/192)*W2S + (i%192)] = f2tf32(f2w[i]);
    }
    for (int i = tid; i < 192; i += 256) s_b1[i] = f1b[i];
    if (tid < 48) { s_2b[tid] = f2b[tid]; s_g2[tid] = g2[tid]; s_b2[tid] = b2[tid]; }
    __syncthreads();

    const size_t tok = (size_t)blockIdx.x*256 + tid;
    const float* xrow = x      + tok*48;
    const float* hrow = g_attn + tok*48;
    float* orow = out + tok*48;

    {
        float v[48];
        float mu = 0.f, sq = 0.f;
        #pragma unroll
        for (int c = 0; c < 48; c += 4) {
            float4 a = __ldg((const float4*)(xrow + c));
            float4 h = *(const float4*)(hrow + c);
            float4 s;
            s.x = a.x + h.x; s.y = a.y + h.y; s.z = a.z + h.z; s.w = a.w + h.w;
            *(float4*)(orow + c) = s;
            v[c]=s.x; v[c+1]=s.y; v[c+2]=s.z; v[c+3]=s.w;
            mu += s.x + s.y + s.z + s.w;
            sq += s.x*s.x + s.y*s.y + s.z*s.z + s.w*s.w;
        }
        mu *= (1.f/48.f);
        const float inv = rsqrtf(sq*(1.f/48.f) - mu*mu + 1e-5f);
        uint32_t* myx = (uint32_t*)(s_xg + (size_t)wid*32*XS + lane*XS);
        #pragma unroll
        for (int c = 0; c < 48; c++)
            myx[c] = f2tf32((v[c] - mu) * inv * s_g2[c] + s_b2[c]);
    }
    __syncthreads();

    uint32_t afr[2][6][4];
    {
        const uint32_t* wx = (const uint32_t*)(s_xg + (size_t)wid*32*XS);
        #pragma unroll
        for (int mt = 0; mt < 2; mt++)
            #pragma unroll
            for (int kt = 0; kt < 6; kt++) {
                const int r = mt*16 + lr, c = kt*8 + lq;
                afr[mt][kt][0] = wx[r*XS + c];
                afr[mt][kt][1] = wx[(r+8)*XS + c];
                afr[mt][kt][2] = wx[r*XS + c + 4];
                afr[mt][kt][3] = wx[(r+8)*XS + c + 4];
            }
    }

    float yacc[2][6][4];
    #pragma unroll
    for (int mt = 0; mt < 2; mt++)
        #pragma unroll
        for (int nt = 0; nt < 6; nt++)
            #pragma unroll
            for (int r = 0; r < 4; r++) yacc[mt][nt][r] = 0.f;

    for (int nt = 0; nt < 24; nt++) {
        uint32_t bf[6][2];
        #pragma unroll
        for (int kt = 0; kt < 6; kt++) {
            const uint32_t* wr = s_w1 + (8*nt + lr)*W1S + kt*8 + lq;
            bf[kt][0] = wr[0];
            bf[kt][1] = wr[4];
        }
        float h[2][4] = {{0.f,0.f,0.f,0.f},{0.f,0.f,0.f,0.f}};
        #pragma unroll
        for (int kt = 0; kt < 6; kt++) {
            mma_tf32(h[0], afr[0][kt], bf[kt]);
            mma_tf32(h[1], afr[1][kt], bf[kt]);
        }
        const float2 bb = *(const float2*)(s_b1 + 8*nt + 2*lq);
        #pragma unroll
        for (int mt = 0; mt < 2; mt++)
            #pragma unroll
            for (int r = 0; r < 4; r++) {
                const float hs = h[mt][r] + ((r & 1) ? bb.y : bb.x);
                h[mt][r] = 0.5f * hs * (1.f + erff(hs * 0.7071067811865476f));
            }
        uint32_t ga[2][4];
        const int s0 = (lane & ~3) | ((lane & 3) >> 1);
        const int s2 = s0 + 2;
        #pragma unroll
        for (int mt = 0; mt < 2; mt++) {
            const float p0 = __shfl_sync(0xffffffffu, h[mt][0], s0);
            const float p1 = __shfl_sync(0xffffffffu, h[mt][1], s0);
            const float p2 = __shfl_sync(0xffffffffu, h[mt][2], s0);
            const float p3 = __shfl_sync(0xffffffffu, h[mt][3], s0);
            const float q0 = __shfl_sync(0xffffffffu, h[mt][0], s2);
            const float q1 = __shfl_sync(0xffffffffu, h[mt][1], s2);
            const float q2 = __shfl_sync(0xffffffffu, h[mt][2], s2);
            const float q3 = __shfl_sync(0xffffffffu, h[mt][3], s2);
            ga[mt][0] = f2tf32(odd ? p1 : p0);
            ga[mt][1] = f2tf32(odd ? p3 : p2);
            ga[mt][2] = f2tf32(odd ? q1 : q0);
            ga[mt][3] = f2tf32(odd ? q3 : q2);
        }
        #pragma unroll
        for (int nt2 = 0; nt2 < 6; nt2++) {
            uint32_t b2f[2];
            const uint32_t* wr = s_w2 + (8*nt2 + lr)*W2S + 8*nt + lq;
            b2f[0] = wr[0];
            b2f[1] = wr[4];
            mma_tf32(yacc[0][nt2], ga[0], b2f);
            mma_tf32(yacc[1][nt2], ga[1], b2f);
        }
    }

    __syncwarp();
    float* wy = s_xg + (size_t)wid*32*XS;
    #pragma unroll
    for (int mt = 0; mt < 2; mt++)
        #pragma unroll
        for (int nt2 = 0; nt2 < 6; nt2++) {
            const int r = mt*16 + lr;
            const int c = 8*nt2 + 2*lq;
            *(float2*)(wy + r*XS + c)     = make_float2(yacc[mt][nt2][0], yacc[mt][nt2][1]);
            *(float2*)(wy + (r+8)*XS + c) = make_float2(yacc[mt][nt2][2], yacc[mt][nt2][3]);
        }
    __syncwarp();

    #pragma unroll
    for (int c = 0; c < 48; c += 4) {
        float4 yv  = *(float4*)(wy + lane*XS + c);
        float4 res = __ldcg((const float4*)(orow + c));
        float4 r;
        r.x = res.x + yv.x + s_2b[c];
        r.y = res.y + yv.y + s_2b[c+1];
        r.z = res.z + yv.z + s_2b[c+2];
        r.w = res.w + yv.w + s_2b[c+3];
        *(float4*)(orow + c) = r;
    }
}

// ===========================================================================
extern "C" void kernel_launch(void* const* d_in, const int* in_sizes, int n_in,
                              void* d_out, int out_size)
{
    const float* x      = (const float*)d_in[0];
    const float* g1     = (const float*)d_in[1];
    const float* b1     = (const float*)d_in[2];
    const float* qkvw   = (const float*)d_in[3];
    const float* qkvb   = (const float*)d_in[4];
    const float* rpbt   = (const float*)d_in[5];
    const float* wf     = (const float*)d_in[6];
    const float* sw1    = (const float*)d_in[7];
    const float* sb1    = (const float*)d_in[8];
    const float* sw2    = (const float*)d_in[9];
    const float* sb2    = (const float*)d_in[10];
    const float* pw     = (const float*)d_in[11];
    const float* pb     = (const float*)d_in[12];
    const float* g2     = (const float*)d_in[13];
    const float* b2     = (const float*)d_in[14];
    const float* f1w    = (const float*)d_in[15];
    const float* f1b    = (const float*)d_in[16];
    const float* f2w    = (const float*)d_in[17];
    const float* f2b    = (const float*)d_in[18];
    float* out = (float*)d_out;

    const int a_smem = A_SMEM_FLOATS * 4;   // ~197 KB
    const int b_smem = B_SMEM_FLOATS * 4;   // ~132 KB
    cudaFuncSetAttribute(attn_kernel, cudaFuncAttributeMaxDynamicSharedMemorySize, a_smem);
    cudaFuncSetAttribute(mlp_kernel,  cudaFuncAttributeMaxDynamicSharedMemorySize, b_smem);

    attn_kernel<<<BN/4, 256, a_smem>>>(x, g1, b1, qkvw, qkvb, rpbt, wf,
                                       sw1, sb1, sw2, sb2, pw, pb);

    mlp_kernel<<<(BB*HH*WWD)/256, 256, b_smem>>>(x, g2, b2, f1w, f1b, f2w, f2b, out);
}

// round 9
// speedup vs baseline: 2.4789x; 1.0538x over previous
#include <cuda_runtime.h>
#include <math.h>
#include <stdint.h>

// ---------------------------------------------------------------------------
// Swin block: B=8, H=W=256, C=48, NH=3 (hd=16), WS=8 (N=64), SS=4, HID=192
// Kernel A: 512 thr = 4 windows x 4 warps (16 query rows each). All GEMMs
//           (qkv, q.k^T, P.V, proj) on tf32 mma.sync.
// Kernel B: 512 thr = 16 warps x 16 tokens. tf32 tensor-core MLP.
// ---------------------------------------------------------------------------

#define BB    8
#define HH    256
#define WWD   256
#define CC    48
#define NWIN  1024
#define BN    8192

__device__ float g_attn[(size_t)BB * HH * WWD * CC];

__device__ __forceinline__ uint32_t f2tf32(float v) {
    uint32_t t;
    asm("cvt.rna.tf32.f32 %0, %1;" : "=r"(t) : "f"(v));
    return t;
}
__device__ __forceinline__ void mma_tf32(float* c, const uint32_t* a, const uint32_t* b) {
    asm volatile("mma.sync.aligned.m16n8k8.row.col.f32.tf32.tf32.f32 "
        "{%0,%1,%2,%3}, {%4,%5,%6,%7}, {%8,%9}, {%0,%1,%2,%3};"
        : "+f"(c[0]), "+f"(c[1]), "+f"(c[2]), "+f"(c[3])
        : "r"(a[0]), "r"(a[1]), "r"(a[2]), "r"(a[3]), "r"(b[0]), "r"(b[1]));
}
// C-fragment (m16n8) -> A-fragment (m16k8).
__device__ __forceinline__ void c2a(const float* c, uint32_t* a, int lane) {
    const int s0 = (lane & ~3) | ((lane & 3) >> 1);
    const int s2 = s0 + 2;
    const bool odd = lane & 1;
    float p0 = __shfl_sync(0xffffffffu, c[0], s0), p1 = __shfl_sync(0xffffffffu, c[1], s0);
    float p2 = __shfl_sync(0xffffffffu, c[2], s0), p3 = __shfl_sync(0xffffffffu, c[3], s0);
    float q0 = __shfl_sync(0xffffffffu, c[0], s2), q1 = __shfl_sync(0xffffffffu, c[1], s2);
    float q2 = __shfl_sync(0xffffffffu, c[2], s2), q3 = __shfl_sync(0xffffffffu, c[3], s2);
    a[0] = f2tf32(odd ? p1 : p0);
    a[1] = f2tf32(odd ? p3 : p2);
    a[2] = f2tf32(odd ? q1 : q0);
    a[3] = f2tf32(odd ? q3 : q2);
}

// ---- attn smem layout (floats) ----
#define SXW  52
#define SKVW 100
#define OFF_WQ   0
#define OFF_WP   (OFF_WQ  + 144*52)
#define OFF_RPB  (OFF_WP  + 48*52)
#define OFF_QKVB (OFF_RPB + 676)
#define OFF_PB   (OFF_QKVB+ 144)
#define OFF_SW1  (OFF_PB  + 48)
#define OFF_SB1  (OFF_SW1 + 144)
#define OFF_SW2  (OFF_SB1 + 4)
#define OFF_SB2  (OFF_SW2 + 144)
#define OFF_MEAN (OFF_SB2 + 48)
#define OFF_SE   (OFF_MEAN+ 192)
#define OFF_HH   (OFF_SE  + 192)
#define OFF_X    (OFF_HH  + 16)
#define OFF_KV   (OFF_X   + 4*64*SXW)
#define A_SMEM_FLOATS (OFF_KV + 4*64*SKVW)

__global__ void __launch_bounds__(512) attn_kernel(
    const float* __restrict__ x,
    const float* __restrict__ g1,   const float* __restrict__ b1,
    const float* __restrict__ qkvw, const float* __restrict__ qkvb,
    const float* __restrict__ rpbt, const float* __restrict__ wf,
    const float* __restrict__ sw1,  const float* __restrict__ sb1,
    const float* __restrict__ sw2,  const float* __restrict__ sb2,
    const float* __restrict__ pw,   const float* __restrict__ pb)
{
    extern __shared__ float sm[];
    uint32_t* s_wq = (uint32_t*)(sm + OFF_WQ);
    uint32_t* s_wp = (uint32_t*)(sm + OFF_WP);

    const int tid  = threadIdx.x;
    const int wid  = tid >> 5;
    const int lane = tid & 31;
    const int lr   = lane >> 2;
    const int lq   = lane & 3;

    // ---- stage weights (tf32) + tables -----------------------------------
    for (int i = tid; i < 144*48; i += 512)
        s_wq[(i/48)*SXW + (i%48)] = f2tf32(qkvw[i]);
    for (int i = tid; i < 48*48; i += 512)
        s_wp[(i/48)*SXW + (i%48)] = f2tf32(pw[i]);
    for (int i = tid; i < 675; i += 512) sm[OFF_RPB + i] = __ldg(rpbt + i);
    for (int i = tid; i < 144; i += 512) {
        sm[OFF_QKVB + i] = qkvb[i];
        sm[OFF_SW1  + i] = sw1[i];
        sm[OFF_SW2  + i] = sw2[i];
    }
    if (tid < 48) { sm[OFF_PB + tid] = pb[tid]; sm[OFF_SB2 + tid] = sb2[tid]; }
    if (tid < 3)  sm[OFF_SB1 + tid] = sb1[tid];

    // ---- LN1: threads 0..255 = one token of one window --------------------
    if (tid < 256) {
        const int wl2 = tid >> 6, tok2 = tid & 63;
        const int wg2 = blockIdx.x*4 + wl2;
        const int b2 = wg2 >> 10, ww = wg2 & 1023;
        const int wy2 = ww >> 5, wx2 = ww & 31;
        const int gy = (wy2*8 + (tok2 >> 3) + 4) & 255;
        const int gx = (wx2*8 + (tok2 & 7) + 4) & 255;
        const float* xrow = x + (((size_t)b2 << 16) | (gy << 8) | gx) * CC;
        float v[48];
        float mu = 0.f, sq = 0.f;
        #pragma unroll
        for (int c = 0; c < 48; c += 4) {
            float4 t = __ldg((const float4*)(xrow + c));
            v[c]=t.x; v[c+1]=t.y; v[c+2]=t.z; v[c+3]=t.w;
            mu += t.x + t.y + t.z + t.w;
            sq += t.x*t.x + t.y*t.y + t.z*t.z + t.w*t.w;
        }
        mu *= (1.f/48.f);
        const float inv = rsqrtf(sq*(1.f/48.f) - mu*mu + 1e-5f);
        float* xw = sm + OFF_X + wl2*64*SXW + tok2*SXW;
        #pragma unroll
        for (int c = 0; c < 48; c++)
            xw[c] = __uint_as_float(f2tf32((v[c] - mu) * inv * __ldg(g1 + c) + __ldg(b1 + c)));
    }
    __syncthreads();

    // ---- SE: mean -> fc1+relu -> fc2+sigmoid ------------------------------
    if (tid < 192) {
        const int wl2 = tid / 48, c = tid % 48;
        const float* xw = sm + OFF_X + wl2*64*SXW;
        float s = 0.f;
        for (int t = 0; t < 64; t++) s += xw[t*SXW + c];
        sm[OFF_MEAN + wl2*48 + c] = s * (1.f/64.f);
    }
    __syncthreads();
    if (tid < 12) {
        const int wl2 = tid / 3, o = tid % 3;
        float a = sm[OFF_SB1 + o];
        #pragma unroll
        for (int c = 0; c < 48; c++) a += sm[OFF_MEAN + wl2*48 + c] * sm[OFF_SW1 + o*48 + c];
        sm[OFF_HH + wl2*4 + o] = fmaxf(a, 0.f);
    }
    __syncthreads();
    if (tid < 192) {
        const int wl2 = tid / 48, c = tid % 48;
        float a = sm[OFF_SB2 + c] + sm[OFF_HH + wl2*4 + 0]*sm[OFF_SW2 + c*3 + 0]
                                  + sm[OFF_HH + wl2*4 + 1]*sm[OFF_SW2 + c*3 + 1]
                                  + sm[OFF_HH + wl2*4 + 2]*sm[OFF_SW2 + c*3 + 2];
        sm[OFF_SE + wl2*48 + c] = 1.f/(1.f + __expf(-a));
    }
    __syncthreads();

    // ---- per-warp geometry: 4 warps per window, 16 query rows each --------
    const int wl = wid >> 2;            // window 0..3 in CTA
    const int rowbase = (wid & 3) * 16; // query-row slice
    const int wg = blockIdx.x*4 + wl;
    const int bimg = wg >> 10, ww = wg & 1023;
    const int wy = ww >> 5, wx = ww & 31;
    float* xw  = sm + OFF_X  + wl*64*SXW;
    float* kvw = sm + OFF_KV + wl*64*SKVW;

    // ---- qkv GEMM: A = xln[16x48] frags ------------------------------------
    uint32_t afr[6][4];
    #pragma unroll
    for (int kt = 0; kt < 6; kt++) {
        const float* bp = xw + (rowbase + lr)*SXW + kt*8 + lq;
        afr[kt][0] = __float_as_uint(bp[0]);
        afr[kt][1] = __float_as_uint(bp[8*SXW]);
        afr[kt][2] = __float_as_uint(bp[4]);
        afr[kt][3] = __float_as_uint(bp[8*SXW + 4]);
    }

    float qf[6][4];
    for (int nt = 0; nt < 18; nt++) {
        float cf[4] = {0.f,0.f,0.f,0.f};
        #pragma unroll
        for (int kt = 0; kt < 6; kt++) {
            uint32_t bf[2];
            const uint32_t* wr = s_wq + (nt*8 + lr)*SXW + kt*8 + lq;
            bf[0] = wr[0]; bf[1] = wr[4];
            mma_tf32(cf, afr[kt], bf);
        }
        const float be = sm[OFF_QKVB + nt*8 + 2*lq];
        const float bo = sm[OFF_QKVB + nt*8 + 2*lq + 1];
        if (nt < 6) {
            qf[nt][0]=(cf[0]+be)*0.25f; qf[nt][1]=(cf[1]+bo)*0.25f;
            qf[nt][2]=(cf[2]+be)*0.25f; qf[nt][3]=(cf[3]+bo)*0.25f;
        } else {
            const int col = (nt - 6)*8 + 2*lq;
            const int r0 = rowbase + lr;
            *(float2*)(kvw + r0*SKVW + col) = make_float2(
                __uint_as_float(f2tf32(cf[0]+be)), __uint_as_float(f2tf32(cf[1]+bo)));
            *(float2*)(kvw + (r0+8)*SKVW + col) = make_float2(
                __uint_as_float(f2tf32(cf[2]+be)), __uint_as_float(f2tf32(cf[3]+bo)));
        }
    }
    __syncthreads();   // all 64 k/v rows of each window visible

    // ---- attention ----------------------------------------------------------
    float oacc[6][4];
    #pragma unroll
    for (int n = 0; n < 6; n++)
        #pragma unroll
        for (int r = 0; r < 4; r++) oacc[n][r] = 0.f;

    const bool edge = (wy == 31) || (wx == 31);

    for (int h = 0; h < 3; h++) {
        uint32_t qa[2][4];
        c2a(qf[2*h+0], qa[0], lane);
        c2a(qf[2*h+1], qa[1], lane);

        float sf[8][4];
        #pragma unroll
        for (int nt = 0; nt < 8; nt++)
            #pragma unroll
            for (int r = 0; r < 4; r++) sf[nt][r] = 0.f;

        #pragma unroll
        for (int nt = 0; nt < 8; nt++) {
            uint32_t bf[2][2];
            #pragma unroll
            for (int kt = 0; kt < 2; kt++) {
                const float* kb = kvw + (nt*8 + lr)*SKVW + h*16 + kt*8 + lq;
                bf[kt][0] = __float_as_uint(kb[0]);
                bf[kt][1] = __float_as_uint(kb[4]);
            }
            mma_tf32(sf[nt], qa[0], bf[0]);
            mma_tf32(sf[nt], qa[1], bf[1]);
        }

        // rpb + shift mask + softmax
        {
            const int iA = rowbase + lr, iB = iA + 8;
            const int tiA = iA >> 3, tjA = iA & 7;
            const int tiB = iB >> 3, tjB = iB & 7;
            const int ryA = (wy==31) ? (tiA >= 4 ? 2 : 1) : 0;
            const int rxA = (wx==31) ? (tjA >= 4 ? 2 : 1) : 0;
            const int ryB = (wy==31) ? (tiB >= 4 ? 2 : 1) : 0;
            const int rxB = (wx==31) ? (tjB >= 4 ? 2 : 1) : 0;
            #pragma unroll
            for (int nt = 0; nt < 8; nt++) {
                #pragma unroll
                for (int e = 0; e < 2; e++) {
                    const int j = nt*8 + 2*lq + e;
                    const int rj = j >> 3, cj = j & 7;
                    const float bA = sm[OFF_RPB + ((tiA - rj + 7)*15 + (tjA - cj + 7))*3 + h];
                    const float bB = sm[OFF_RPB + ((tiB - rj + 7)*15 + (tjB - cj + 7))*3 + h];
                    float mA = 0.f, mB = 0.f;
                    if (edge) {
                        const int ryj = (wy==31) ? (rj >= 4 ? 2 : 1) : 0;
                        const int rxj = (wx==31) ? (cj >= 4 ? 2 : 1) : 0;
                        if (ryj != ryA || rxj != rxA) mA = -100.f;
                        if (ryj != ryB || rxj != rxB) mB = -100.f;
                    }
                    sf[nt][e]   += bA + mA;
                    sf[nt][e+2] += bB + mB;
                }
            }
            float mxA = -1e30f, mxB = -1e30f;
            #pragma unroll
            for (int nt = 0; nt < 8; nt++) {
                mxA = fmaxf(mxA, fmaxf(sf[nt][0], sf[nt][1]));
                mxB = fmaxf(mxB, fmaxf(sf[nt][2], sf[nt][3]));
            }
            mxA = fmaxf(mxA, __shfl_xor_sync(0xffffffffu, mxA, 1));
            mxA = fmaxf(mxA, __shfl_xor_sync(0xffffffffu, mxA, 2));
            mxB = fmaxf(mxB, __shfl_xor_sync(0xffffffffu, mxB, 1));
            mxB = fmaxf(mxB, __shfl_xor_sync(0xffffffffu, mxB, 2));
            float sA = 0.f, sB = 0.f;
            #pragma unroll
            for (int nt = 0; nt < 8; nt++) {
                sf[nt][0] = __expf(sf[nt][0] - mxA);
                sf[nt][1] = __expf(sf[nt][1] - mxA);
                sf[nt][2] = __expf(sf[nt][2] - mxB);
                sf[nt][3] = __expf(sf[nt][3] - mxB);
                sA += sf[nt][0] + sf[nt][1];
                sB += sf[nt][2] + sf[nt][3];
            }
            sA += __shfl_xor_sync(0xffffffffu, sA, 1);
            sA += __shfl_xor_sync(0xffffffffu, sA, 2);
            sB += __shfl_xor_sync(0xffffffffu, sB, 1);
            sB += __shfl_xor_sync(0xffffffffu, sB, 2);
            const float rAi = 1.f / sA, rBi = 1.f / sB;
            #pragma unroll
            for (int nt = 0; nt < 8; nt++) {
                sf[nt][0] *= rAi; sf[nt][1] *= rAi;
                sf[nt][2] *= rBi; sf[nt][3] *= rBi;
            }
        }

        // P.V
        #pragma unroll
        for (int kt = 0; kt < 8; kt++) {
            uint32_t pa[4];
            c2a(sf[kt], pa, lane);
            #pragma unroll
            for (int nt2 = 0; nt2 < 2; nt2++) {
                uint32_t bf[2];
                bf[0] = __float_as_uint(kvw[(kt*8 + lq  )*SKVW + 48 + h*16 + nt2*8 + lr]);
                bf[1] = __float_as_uint(kvw[(kt*8 + lq+4)*SKVW + 48 + h*16 + nt2*8 + lr]);
                mma_tf32(oacc[2*h + nt2], pa, bf);
            }
        }
    }

    // ---- SE add --------------------------------------------------------------
    {
        const float wfv = __ldg(wf);
        const float* sew = sm + OFF_SE + wl*48;
        const int rA = rowbase + lr, rB = rA + 8;
        #pragma unroll
        for (int n = 0; n < 6; n++) {
            const int c0 = n*8 + 2*lq;
            oacc[n][0] += wfv * xw[rA*SXW + c0    ] * sew[c0];
            oacc[n][1] += wfv * xw[rA*SXW + c0 + 1] * sew[c0+1];
            oacc[n][2] += wfv * xw[rB*SXW + c0    ] * sew[c0];
            oacc[n][3] += wfv * xw[rB*SXW + c0 + 1] * sew[c0+1];
        }
    }

    // ---- proj GEMM -------------------------------------------------------------
    uint32_t oa[6][4];
    #pragma unroll
    for (int kt = 0; kt < 6; kt++) c2a(oacc[kt], oa[kt], lane);

    #pragma unroll
    for (int nt = 0; nt < 6; nt++) {
        float pf[4] = {0.f,0.f,0.f,0.f};
        #pragma unroll
        for (int kt = 0; kt < 6; kt++) {
            uint32_t bf[2];
            const uint32_t* wr = s_wp + (nt*8 + lr)*SXW + kt*8 + lq;
            bf[0] = wr[0]; bf[1] = wr[4];
            mma_tf32(pf, oa[kt], bf);
        }
        const float be = sm[OFF_PB + nt*8 + 2*lq];
        const float bo = sm[OFF_PB + nt*8 + 2*lq + 1];
        const int r0 = rowbase + lr;
        *(float2*)(xw + r0*SXW     + nt*8 + 2*lq) = make_float2(pf[0]+be, pf[1]+bo);
        *(float2*)(xw + (r0+8)*SXW + nt*8 + 2*lq) = make_float2(pf[2]+be, pf[3]+bo);
    }
    __syncwarp();

    // ---- coalesced scatter of this warp's 16 rows ------------------------------
    #pragma unroll
    for (int i = lane; i < 192; i += 32) {
        const int r  = rowbase + i/12;
        const int c4 = (i%12)*4;
        const int gy = (wy*8 + (r >> 3) + 4) & 255;
        const int gx = (wx*8 + (r & 7) + 4) & 255;
        float* orow = g_attn + (((size_t)bimg << 16) | (gy << 8) | gx) * CC;
        *(float4*)(orow + c4) = *(const float4*)(xw + r*SXW + c4);
    }
}

// ===========================================================================
// MLP: tf32 mma.sync, 512 thr = 16 warps x 16 tokens (256 tokens/CTA).
// ===========================================================================
#define XS  52
#define W1S 52
#define W2S 196
#define B_SMEM_FLOATS (192*W1S + 48*W2S + 192 + 48 + 48 + 48 + 16*16*XS)

__global__ void __launch_bounds__(512) mlp_kernel(
    const float* __restrict__ x,
    const float* __restrict__ g2,   const float* __restrict__ b2,
    const float* __restrict__ f1w,  const float* __restrict__ f1b,
    const float* __restrict__ f2w,  const float* __restrict__ f2b,
    float* __restrict__ out)
{
    extern __shared__ float sm[];
    uint32_t* s_w1 = (uint32_t*)sm;
    uint32_t* s_w2 = (uint32_t*)(sm + 192*W1S);
    float* s_b1 = sm + 192*W1S + 48*W2S;
    float* s_2b = s_b1 + 192;
    float* s_g2 = s_2b + 48;
    float* s_b2 = s_g2 + 48;
    float* s_xg = s_b2 + 48;                    // 16 warps x 16 x XS

    const int tid  = threadIdx.x;
    const int wid  = tid >> 5;
    const int lane = tid & 31;
    const int lr   = lane >> 2;
    const int lq   = lane & 3;

    for (int i = tid; i < 192*48; i += 512) {
        s_w1[(i/48)*W1S + (i%48)]   = f2tf32(f1w[i]);
        s_w2[(i/192)*W2S + (i%192)] = f2tf32(f2w[i]);
    }
    if (tid < 192) s_b1[tid] = f1b[tid];
    if (tid < 48) { s_2b[tid] = f2b[tid]; s_g2[tid] = g2[tid]; s_b2[tid] = b2[tid]; }
    __syncthreads();

    const size_t tokbase = (size_t)blockIdx.x * 256;

    // ---- residual + LN2: threads 0..255, one token each --------------------
    if (tid < 256) {
        const size_t tok = tokbase + tid;
        const float* xrow = x      + tok*48;
        const float* hrow = g_attn + tok*48;
        float* orow = out + tok*48;
        float v[48];
        float mu = 0.f, sq = 0.f;
        #pragma unroll
        for (int c = 0; c < 48; c += 4) {
            float4 a = __ldg((const float4*)(xrow + c));
            float4 h = *(const float4*)(hrow + c);
            float4 s;
            s.x = a.x + h.x; s.y = a.y + h.y; s.z = a.z + h.z; s.w = a.w + h.w;
            *(float4*)(orow + c) = s;              // residual parked in out
            v[c]=s.x; v[c+1]=s.y; v[c+2]=s.z; v[c+3]=s.w;
            mu += s.x + s.y + s.z + s.w;
            sq += s.x*s.x + s.y*s.y + s.z*s.z + s.w*s.w;
        }
        mu *= (1.f/48.f);
        const float inv = rsqrtf(sq*(1.f/48.f) - mu*mu + 1e-5f);
        uint32_t* myx = (uint32_t*)(s_xg + (tid >> 4)*16*XS + (tid & 15)*XS);
        #pragma unroll
        for (int c = 0; c < 48; c++)
            myx[c] = f2tf32((v[c] - mu) * inv * s_g2[c] + s_b2[c]);
    }
    __syncthreads();

    // ---- A (xln 16x48) fragments --------------------------------------------
    uint32_t afr[6][4];
    {
        const uint32_t* wx = (const uint32_t*)(s_xg + wid*16*XS);
        #pragma unroll
        for (int kt = 0; kt < 6; kt++) {
            const int c = kt*8 + lq;
            afr[kt][0] = wx[lr*XS + c];
            afr[kt][1] = wx[(lr+8)*XS + c];
            afr[kt][2] = wx[lr*XS + c + 4];
            afr[kt][3] = wx[(lr+8)*XS + c + 4];
        }
    }

    float yacc[6][4];
    #pragma unroll
    for (int nt = 0; nt < 6; nt++)
        #pragma unroll
        for (int r = 0; r < 4; r++) yacc[nt][r] = 0.f;

    for (int nt = 0; nt < 24; nt++) {
        uint32_t bf[6][2];
        #pragma unroll
        for (int kt = 0; kt < 6; kt++) {
            const uint32_t* wr = s_w1 + (8*nt + lr)*W1S + kt*8 + lq;
            bf[kt][0] = wr[0];
            bf[kt][1] = wr[4];
        }
        float h[4] = {0.f,0.f,0.f,0.f};
        #pragma unroll
        for (int kt = 0; kt < 6; kt++) mma_tf32(h, afr[kt], bf[kt]);

        const float2 bb = *(const float2*)(s_b1 + 8*nt + 2*lq);
        #pragma unroll
        for (int r = 0; r < 4; r++) {
            const float hs = h[r] + ((r & 1) ? bb.y : bb.x);
            h[r] = 0.5f * hs * (1.f + erff(hs * 0.7071067811865476f));
        }
        uint32_t ga[4];
        c2a(h, ga, lane);
        #pragma unroll
        for (int nt2 = 0; nt2 < 6; nt2++) {
            uint32_t b2f[2];
            const uint32_t* wr = s_w2 + (8*nt2 + lr)*W2S + 8*nt + lq;
            b2f[0] = wr[0];
            b2f[1] = wr[4];
            mma_tf32(yacc[nt2], ga, b2f);
        }
    }

    // ---- epilogue: stage Y, coalesced residual add ---------------------------
    __syncwarp();
    float* wy = s_xg + wid*16*XS;
    #pragma unroll
    for (int nt2 = 0; nt2 < 6; nt2++) {
        const int c = 8*nt2 + 2*lq;
        *(float2*)(wy + lr*XS + c)     = make_float2(yacc[nt2][0], yacc[nt2][1]);
        *(float2*)(wy + (lr+8)*XS + c) = make_float2(yacc[nt2][2], yacc[nt2][3]);
    }
    __syncwarp();

    {
        const int row = lane >> 1;               // 0..15
        const int c0  = (lane & 1) * 24;         // half-row of 24 floats
        const size_t tok = tokbase + wid*16 + row;
        float* orow = out + tok*48;
        #pragma unroll
        for (int k = 0; k < 6; k++) {
            const int c = c0 + k*4;
            float4 yv  = *(float4*)(wy + row*XS + c);
            float4 res = __ldcg((const float4*)(orow + c));
            float4 r;
            r.x = res.x + yv.x + s_2b[c];
            r.y = res.y + yv.y + s_2b[c+1];
            r.z = res.z + yv.z + s_2b[c+2];
            r.w = res.w + yv.w + s_2b[c+3];
            *(float4*)(orow + c) = r;
        }
    }
}

// ===========================================================================
extern "C" void kernel_launch(void* const* d_in, const int* in_sizes, int n_in,
                              void* d_out, int out_size)
{
    const float* x      = (const float*)d_in[0];
    const float* g1     = (const float*)d_in[1];
    const float* b1     = (const float*)d_in[2];
    const float* qkvw   = (const float*)d_in[3];
    const float* qkvb   = (const float*)d_in[4];
    const float* rpbt   = (const float*)d_in[5];
    const float* wf     = (const float*)d_in[6];
    const float* sw1    = (const float*)d_in[7];
    const float* sb1    = (const float*)d_in[8];
    const float* sw2    = (const float*)d_in[9];
    const float* sb2    = (const float*)d_in[10];
    const float* pw     = (const float*)d_in[11];
    const float* pb     = (const float*)d_in[12];
    const float* g2     = (const float*)d_in[13];
    const float* b2     = (const float*)d_in[14];
    const float* f1w    = (const float*)d_in[15];
    const float* f1b    = (const float*)d_in[16];
    const float* f2w    = (const float*)d_in[17];
    const float* f2b    = (const float*)d_in[18];
    float* out = (float*)d_out;

    const int a_smem = A_SMEM_FLOATS * 4;   // ~197 KB
    const int b_smem = B_SMEM_FLOATS * 4;   // ~132 KB
    cudaFuncSetAttribute(attn_kernel, cudaFuncAttributeMaxDynamicSharedMemorySize, a_smem);
    cudaFuncSetAttribute(mlp_kernel,  cudaFuncAttributeMaxDynamicSharedMemorySize, b_smem);

    attn_kernel<<<BN/4, 512, a_smem>>>(x, g1, b1, qkvw, qkvb, rpbt, wf,
                                       sw1, sb1, sw2, sb2, pw, pb);

    mlp_kernel<<<(BB*HH*WWD)/256, 512, b_smem>>>(x, g2, b2, f1w, f1b, f2w, f2b, out);
}

// round 10
// speedup vs baseline: 2.7557x; 1.1117x over previous
#include <cuda_runtime.h>
#include <math.h>
#include <stdint.h>

// ---------------------------------------------------------------------------
// Swin block: B=8, H=W=256, C=48, NH=3 (hd=16), WS=8 (N=64), SS=4, HID=192
// Kernel A: 512 thr = 4 windows x 4 warps (16 query rows each). tf32 mma.
// Kernel B: 512 thr = 16 warps x 16 tokens. bf16 m16n8k16 MLP, shuffle-free
//           GEMM1->GELU->GEMM2 chaining (C-frag == A-frag layout), 2 CTAs/SM.
// ---------------------------------------------------------------------------

#define BB    8
#define HH    256
#define WWD   256
#define CC    48
#define NWIN  1024
#define BN    8192

__device__ float g_attn[(size_t)BB * HH * WWD * CC];

__device__ __forceinline__ uint32_t f2tf32(float v) {
    uint32_t t;
    asm("cvt.rna.tf32.f32 %0, %1;" : "=r"(t) : "f"(v));
    return t;
}
__device__ __forceinline__ void mma_tf32(float* c, const uint32_t* a, const uint32_t* b) {
    asm volatile("mma.sync.aligned.m16n8k8.row.col.f32.tf32.tf32.f32 "
        "{%0,%1,%2,%3}, {%4,%5,%6,%7}, {%8,%9}, {%0,%1,%2,%3};"
        : "+f"(c[0]), "+f"(c[1]), "+f"(c[2]), "+f"(c[3])
        : "r"(a[0]), "r"(a[1]), "r"(a[2]), "r"(a[3]), "r"(b[0]), "r"(b[1]));
}
__device__ __forceinline__ void mma_bf16(float* c, const uint32_t* a, const uint32_t* b) {
    asm volatile("mma.sync.aligned.m16n8k16.row.col.f32.bf16.bf16.f32 "
        "{%0,%1,%2,%3}, {%4,%5,%6,%7}, {%8,%9}, {%0,%1,%2,%3};"
        : "+f"(c[0]), "+f"(c[1]), "+f"(c[2]), "+f"(c[3])
        : "r"(a[0]), "r"(a[1]), "r"(a[2]), "r"(a[3]), "r"(b[0]), "r"(b[1]));
}
// pack two floats into bf16x2: lo in low 16 bits, hi in high 16 bits
__device__ __forceinline__ uint32_t pack_bf16(float lo, float hi) {
    uint32_t r;
    asm("cvt.rn.bf16x2.f32 %0, %1, %2;" : "=r"(r) : "f"(hi), "f"(lo));
    return r;
}
// C-fragment (m16n8) -> tf32 A-fragment (m16k8).
__device__ __forceinline__ void c2a(const float* c, uint32_t* a, int lane) {
    const int s0 = (lane & ~3) | ((lane & 3) >> 1);
    const int s2 = s0 + 2;
    const bool odd = lane & 1;
    float p0 = __shfl_sync(0xffffffffu, c[0], s0), p1 = __shfl_sync(0xffffffffu, c[1], s0);
    float p2 = __shfl_sync(0xffffffffu, c[2], s0), p3 = __shfl_sync(0xffffffffu, c[3], s0);
    float q0 = __shfl_sync(0xffffffffu, c[0], s2), q1 = __shfl_sync(0xffffffffu, c[1], s2);
    float q2 = __shfl_sync(0xffffffffu, c[2], s2), q3 = __shfl_sync(0xffffffffu, c[3], s2);
    a[0] = f2tf32(odd ? p1 : p0);
    a[1] = f2tf32(odd ? p3 : p2);
    a[2] = f2tf32(odd ? q1 : q0);
    a[3] = f2tf32(odd ? q3 : q2);
}

// ---- attn smem layout (floats) ----
#define SXW  52
#define SKVW 100
#define OFF_WQ   0
#define OFF_WP   (OFF_WQ  + 144*52)
#define OFF_RPB  (OFF_WP  + 48*52)
#define OFF_QKVB (OFF_RPB + 676)
#define OFF_PB   (OFF_QKVB+ 144)
#define OFF_SW1  (OFF_PB  + 48)
#define OFF_SB1  (OFF_SW1 + 144)
#define OFF_SW2  (OFF_SB1 + 4)
#define OFF_SB2  (OFF_SW2 + 144)
#define OFF_MEAN (OFF_SB2 + 48)
#define OFF_SE   (OFF_MEAN+ 192)
#define OFF_HH   (OFF_SE  + 192)
#define OFF_X    (OFF_HH  + 16)
#define OFF_KV   (OFF_X   + 4*64*SXW)
#define A_SMEM_FLOATS (OFF_KV + 4*64*SKVW)

__global__ void __launch_bounds__(512) attn_kernel(
    const float* __restrict__ x,
    const float* __restrict__ g1,   const float* __restrict__ b1,
    const float* __restrict__ qkvw, const float* __restrict__ qkvb,
    const float* __restrict__ rpbt, const float* __restrict__ wf,
    const float* __restrict__ sw1,  const float* __restrict__ sb1,
    const float* __restrict__ sw2,  const float* __restrict__ sb2,
    const float* __restrict__ pw,   const float* __restrict__ pb)
{
    extern __shared__ float sm[];
    uint32_t* s_wq = (uint32_t*)(sm + OFF_WQ);
    uint32_t* s_wp = (uint32_t*)(sm + OFF_WP);

    const int tid  = threadIdx.x;
    const int wid  = tid >> 5;
    const int lane = tid & 31;
    const int lr   = lane >> 2;
    const int lq   = lane & 3;

    for (int i = tid; i < 144*48; i += 512)
        s_wq[(i/48)*SXW + (i%48)] = f2tf32(qkvw[i]);
    for (int i = tid; i < 48*48; i += 512)
        s_wp[(i/48)*SXW + (i%48)] = f2tf32(pw[i]);
    for (int i = tid; i < 675; i += 512) sm[OFF_RPB + i] = __ldg(rpbt + i);
    for (int i = tid; i < 144; i += 512) {
        sm[OFF_QKVB + i] = qkvb[i];
        sm[OFF_SW1  + i] = sw1[i];
        sm[OFF_SW2  + i] = sw2[i];
    }
    if (tid < 48) { sm[OFF_PB + tid] = pb[tid]; sm[OFF_SB2 + tid] = sb2[tid]; }
    if (tid < 3)  sm[OFF_SB1 + tid] = sb1[tid];

    if (tid < 256) {
        const int wl2 = tid >> 6, tok2 = tid & 63;
        const int wg2 = blockIdx.x*4 + wl2;
        const int b2 = wg2 >> 10, ww = wg2 & 1023;
        const int wy2 = ww >> 5, wx2 = ww & 31;
        const int gy = (wy2*8 + (tok2 >> 3) + 4) & 255;
        const int gx = (wx2*8 + (tok2 & 7) + 4) & 255;
        const float* xrow = x + (((size_t)b2 << 16) | (gy << 8) | gx) * CC;
        float v[48];
        float mu = 0.f, sq = 0.f;
        #pragma unroll
        for (int c = 0; c < 48; c += 4) {
            float4 t = __ldg((const float4*)(xrow + c));
            v[c]=t.x; v[c+1]=t.y; v[c+2]=t.z; v[c+3]=t.w;
            mu += t.x + t.y + t.z + t.w;
            sq += t.x*t.x + t.y*t.y + t.z*t.z + t.w*t.w;
        }
        mu *= (1.f/48.f);
        const float inv = rsqrtf(sq*(1.f/48.f) - mu*mu + 1e-5f);
        float* xw = sm + OFF_X + wl2*64*SXW + tok2*SXW;
        #pragma unroll
        for (int c = 0; c < 48; c++)
            xw[c] = __uint_as_float(f2tf32((v[c] - mu) * inv * __ldg(g1 + c) + __ldg(b1 + c)));
    }
    __syncthreads();

    if (tid < 192) {
        const int wl2 = tid / 48, c = tid % 48;
        const float* xw = sm + OFF_X + wl2*64*SXW;
        float s = 0.f;
        for (int t = 0; t < 64; t++) s += xw[t*SXW + c];
        sm[OFF_MEAN + wl2*48 + c] = s * (1.f/64.f);
    }
    __syncthreads();
    if (tid < 12) {
        const int wl2 = tid / 3, o = tid % 3;
        float a = sm[OFF_SB1 + o];
        #pragma unroll
        for (int c = 0; c < 48; c++) a += sm[OFF_MEAN + wl2*48 + c] * sm[OFF_SW1 + o*48 + c];
        sm[OFF_HH + wl2*4 + o] = fmaxf(a, 0.f);
    }
    __syncthreads();
    if (tid < 192) {
        const int wl2 = tid / 48, c = tid % 48;
        float a = sm[OFF_SB2 + c] + sm[OFF_HH + wl2*4 + 0]*sm[OFF_SW2 + c*3 + 0]
                                  + sm[OFF_HH + wl2*4 + 1]*sm[OFF_SW2 + c*3 + 1]
                                  + sm[OFF_HH + wl2*4 + 2]*sm[OFF_SW2 + c*3 + 2];
        sm[OFF_SE + wl2*48 + c] = 1.f/(1.f + __expf(-a));
    }
    __syncthreads();

    const int wl = wid >> 2;
    const int rowbase = (wid & 3) * 16;
    const int wg = blockIdx.x*4 + wl;
    const int bimg = wg >> 10, ww = wg & 1023;
    const int wy = ww >> 5, wx = ww & 31;
    float* xw  = sm + OFF_X  + wl*64*SXW;
    float* kvw = sm + OFF_KV + wl*64*SKVW;

    uint32_t afr[6][4];
    #pragma unroll
    for (int kt = 0; kt < 6; kt++) {
        const float* bp = xw + (rowbase + lr)*SXW + kt*8 + lq;
        afr[kt][0] = __float_as_uint(bp[0]);
        afr[kt][1] = __float_as_uint(bp[8*SXW]);
        afr[kt][2] = __float_as_uint(bp[4]);
        afr[kt][3] = __float_as_uint(bp[8*SXW + 4]);
    }

    float qf[6][4];
    for (int nt = 0; nt < 18; nt++) {
        float cf[4] = {0.f,0.f,0.f,0.f};
        #pragma unroll
        for (int kt = 0; kt < 6; kt++) {
            uint32_t bf[2];
            const uint32_t* wr = s_wq + (nt*8 + lr)*SXW + kt*8 + lq;
            bf[0] = wr[0]; bf[1] = wr[4];
            mma_tf32(cf, afr[kt], bf);
        }
        const float be = sm[OFF_QKVB + nt*8 + 2*lq];
        const float bo = sm[OFF_QKVB + nt*8 + 2*lq + 1];
        if (nt < 6) {
            qf[nt][0]=(cf[0]+be)*0.25f; qf[nt][1]=(cf[1]+bo)*0.25f;
            qf[nt][2]=(cf[2]+be)*0.25f; qf[nt][3]=(cf[3]+bo)*0.25f;
        } else {
            const int col = (nt - 6)*8 + 2*lq;
            const int r0 = rowbase + lr;
            *(float2*)(kvw + r0*SKVW + col) = make_float2(
                __uint_as_float(f2tf32(cf[0]+be)), __uint_as_float(f2tf32(cf[1]+bo)));
            *(float2*)(kvw + (r0+8)*SKVW + col) = make_float2(
                __uint_as_float(f2tf32(cf[2]+be)), __uint_as_float(f2tf32(cf[3]+bo)));
        }
    }
    __syncthreads();

    float oacc[6][4];
    #pragma unroll
    for (int n = 0; n < 6; n++)
        #pragma unroll
        for (int r = 0; r < 4; r++) oacc[n][r] = 0.f;

    const bool edge = (wy == 31) || (wx == 31);

    for (int h = 0; h < 3; h++) {
        uint32_t qa[2][4];
        c2a(qf[2*h+0], qa[0], lane);
        c2a(qf[2*h+1], qa[1], lane);

        float sf[8][4];
        #pragma unroll
        for (int nt = 0; nt < 8; nt++)
            #pragma unroll
            for (int r = 0; r < 4; r++) sf[nt][r] = 0.f;

        #pragma unroll
        for (int nt = 0; nt < 8; nt++) {
            uint32_t bf[2][2];
            #pragma unroll
            for (int kt = 0; kt < 2; kt++) {
                const float* kb = kvw + (nt*8 + lr)*SKVW + h*16 + kt*8 + lq;
                bf[kt][0] = __float_as_uint(kb[0]);
                bf[kt][1] = __float_as_uint(kb[4]);
            }
            mma_tf32(sf[nt], qa[0], bf[0]);
            mma_tf32(sf[nt], qa[1], bf[1]);
        }

        {
            const int iA = rowbase + lr, iB = iA + 8;
            const int tiA = iA >> 3, tjA = iA & 7;
            const int tiB = iB >> 3, tjB = iB & 7;
            const int ryA = (wy==31) ? (tiA >= 4 ? 2 : 1) : 0;
            const int rxA = (wx==31) ? (tjA >= 4 ? 2 : 1) : 0;
            const int ryB = (wy==31) ? (tiB >= 4 ? 2 : 1) : 0;
            const int rxB = (wx==31) ? (tjB >= 4 ? 2 : 1) : 0;
            #pragma unroll
            for (int nt = 0; nt < 8; nt++) {
                #pragma unroll
                for (int e = 0; e < 2; e++) {
                    const int j = nt*8 + 2*lq + e;
                    const int rj = j >> 3, cj = j & 7;
                    const float bA = sm[OFF_RPB + ((tiA - rj + 7)*15 + (tjA - cj + 7))*3 + h];
                    const float bB = sm[OFF_RPB + ((tiB - rj + 7)*15 + (tjB - cj + 7))*3 + h];
                    float mA = 0.f, mB = 0.f;
                    if (edge) {
                        const int ryj = (wy==31) ? (rj >= 4 ? 2 : 1) : 0;
                        const int rxj = (wx==31) ? (cj >= 4 ? 2 : 1) : 0;
                        if (ryj != ryA || rxj != rxA) mA = -100.f;
                        if (ryj != ryB || rxj != rxB) mB = -100.f;
                    }
                    sf[nt][e]   += bA + mA;
                    sf[nt][e+2] += bB + mB;
                }
            }
            float mxA = -1e30f, mxB = -1e30f;
            #pragma unroll
            for (int nt = 0; nt < 8; nt++) {
                mxA = fmaxf(mxA, fmaxf(sf[nt][0], sf[nt][1]));
                mxB = fmaxf(mxB, fmaxf(sf[nt][2], sf[nt][3]));
            }
            mxA = fmaxf(mxA, __shfl_xor_sync(0xffffffffu, mxA, 1));
            mxA = fmaxf(mxA, __shfl_xor_sync(0xffffffffu, mxA, 2));
            mxB = fmaxf(mxB, __shfl_xor_sync(0xffffffffu, mxB, 1));
            mxB = fmaxf(mxB, __shfl_xor_sync(0xffffffffu, mxB, 2));
            float sA = 0.f, sB = 0.f;
            #pragma unroll
            for (int nt = 0; nt < 8; nt++) {
                sf[nt][0] = __expf(sf[nt][0] - mxA);
                sf[nt][1] = __expf(sf[nt][1] - mxA);
                sf[nt][2] = __expf(sf[nt][2] - mxB);
                sf[nt][3] = __expf(sf[nt][3] - mxB);
                sA += sf[nt][0] + sf[nt][1];
                sB += sf[nt][2] + sf[nt][3];
            }
            sA += __shfl_xor_sync(0xffffffffu, sA, 1);
            sA += __shfl_xor_sync(0xffffffffu, sA, 2);
            sB += __shfl_xor_sync(0xffffffffu, sB, 1);
            sB += __shfl_xor_sync(0xffffffffu, sB, 2);
            const float rAi = 1.f / sA, rBi = 1.f / sB;
            #pragma unroll
            for (int nt = 0; nt < 8; nt++) {
                sf[nt][0] *= rAi; sf[nt][1] *= rAi;
                sf[nt][2] *= rBi; sf[nt][3] *= rBi;
            }
        }

        #pragma unroll
        for (int kt = 0; kt < 8; kt++) {
            uint32_t pa[4];
            c2a(sf[kt], pa, lane);
            #pragma unroll
            for (int nt2 = 0; nt2 < 2; nt2++) {
                uint32_t bf[2];
                bf[0] = __float_as_uint(kvw[(kt*8 + lq  )*SKVW + 48 + h*16 + nt2*8 + lr]);
                bf[1] = __float_as_uint(kvw[(kt*8 + lq+4)*SKVW + 48 + h*16 + nt2*8 + lr]);
                mma_tf32(oacc[2*h + nt2], pa, bf);
            }
        }
    }

    {
        const float wfv = __ldg(wf);
        const float* sew = sm + OFF_SE + wl*48;
        const int rA = rowbase + lr, rB = rA + 8;
        #pragma unroll
        for (int n = 0; n < 6; n++) {
            const int c0 = n*8 + 2*lq;
            oacc[n][0] += wfv * xw[rA*SXW + c0    ] * sew[c0];
            oacc[n][1] += wfv * xw[rA*SXW + c0 + 1] * sew[c0+1];
            oacc[n][2] += wfv * xw[rB*SXW + c0    ] * sew[c0];
            oacc[n][3] += wfv * xw[rB*SXW + c0 + 1] * sew[c0+1];
        }
    }

    uint32_t oa[6][4];
    #pragma unroll
    for (int kt = 0; kt < 6; kt++) c2a(oacc[kt], oa[kt], lane);

    #pragma unroll
    for (int nt = 0; nt < 6; nt++) {
        float pf[4] = {0.f,0.f,0.f,0.f};
        #pragma unroll
        for (int kt = 0; kt < 6; kt++) {
            uint32_t bf[2];
            const uint32_t* wr = s_wp + (nt*8 + lr)*SXW + kt*8 + lq;
            bf[0] = wr[0]; bf[1] = wr[4];
            mma_tf32(pf, oa[kt], bf);
        }
        const float be = sm[OFF_PB + nt*8 + 2*lq];
        const float bo = sm[OFF_PB + nt*8 + 2*lq + 1];
        const int r0 = rowbase + lr;
        *(float2*)(xw + r0*SXW     + nt*8 + 2*lq) = make_float2(pf[0]+be, pf[1]+bo);
        *(float2*)(xw + (r0+8)*SXW + nt*8 + 2*lq) = make_float2(pf[2]+be, pf[3]+bo);
    }
    __syncwarp();

    #pragma unroll
    for (int i = lane; i < 192; i += 32) {
        const int r  = rowbase + i/12;
        const int c4 = (i%12)*4;
        const int gy = (wy*8 + (r >> 3) + 4) & 255;
        const int gx = (wx*8 + (r & 7) + 4) & 255;
        float* orow = g_attn + (((size_t)bimg << 16) | (gy << 8) | gx) * CC;
        *(float4*)(orow + c4) = *(const float4*)(xw + r*SXW + c4);
    }
}

// ===========================================================================
// MLP: bf16 m16n8k16, 512 thr = 16 warps x 16 tokens, 2 CTAs/SM.
//   s_w1: [24 ch-pairs][192 hid] stride 200  (bf16x2 words)
//   s_w2: [96 hid-pairs][48 ch]  stride 56   (bf16x2 words)
//   s_xg: per-warp [16 tokens][52 words]; xln bf16x2 in words 0..23,
//         Y fp32 staging reuses words 0..47 after A-frag load.
// ===========================================================================
#define XS   52
#define W1S  200
#define W2S  56
#define B_SMEM_FLOATS (24*W1S + 96*W2S + 192 + 48 + 48 + 48 + 16*16*XS)

__global__ void __launch_bounds__(512, 2) mlp_kernel(
    const float* __restrict__ x,
    const float* __restrict__ g2,   const float* __restrict__ b2,
    const float* __restrict__ f1w,  const float* __restrict__ f1b,
    const float* __restrict__ f2w,  const float* __restrict__ f2b,
    float* __restrict__ out)
{
    extern __shared__ float sm[];
    uint32_t* s_w1 = (uint32_t*)sm;                    // 24*200 bf16x2
    uint32_t* s_w2 = (uint32_t*)(sm + 24*W1S);         // 96*56  bf16x2
    float* s_b1 = sm + 24*W1S + 96*W2S;                // 192
    float* s_2b = s_b1 + 192;                          // 48
    float* s_g2 = s_2b + 48;                           // 48
    float* s_b2 = s_g2 + 48;                           // 48
    float* s_xg = s_b2 + 48;                           // 16 warps x 16 x XS

    const int tid  = threadIdx.x;
    const int wid  = tid >> 5;
    const int lane = tid & 31;
    const int lr   = lane >> 2;
    const int lq   = lane & 3;

    // ---- stage weights packed bf16x2 --------------------------------------
    for (int i = tid; i < 24*192; i += 512) {
        const int p = i / 192, o = i % 192;
        s_w1[p*W1S + o] = pack_bf16(f1w[o*48 + 2*p], f1w[o*48 + 2*p + 1]);
    }
    for (int i = tid; i < 96*48; i += 512) {
        const int hp = i / 48, ch = i % 48;
        s_w2[hp*W2S + ch] = pack_bf16(f2w[ch*192 + 2*hp], f2w[ch*192 + 2*hp + 1]);
    }
    if (tid < 192) s_b1[tid] = f1b[tid];
    if (tid < 48) { s_2b[tid] = f2b[tid]; s_g2[tid] = g2[tid]; s_b2[tid] = b2[tid]; }
    __syncthreads();

    const size_t tokbase = (size_t)blockIdx.x * 256;

    // ---- residual + LN2: threads 0..255, one token each --------------------
    if (tid < 256) {
        const size_t tok = tokbase + tid;
        const float* xrow = x      + tok*48;
        const float* hrow = g_attn + tok*48;
        float* orow = out + tok*48;
        float v[48];
        float mu = 0.f, sq = 0.f;
        #pragma unroll
        for (int c = 0; c < 48; c += 4) {
            float4 a = __ldg((const float4*)(xrow + c));
            float4 h = *(const float4*)(hrow + c);
            float4 s;
            s.x = a.x + h.x; s.y = a.y + h.y; s.z = a.z + h.z; s.w = a.w + h.w;
            *(float4*)(orow + c) = s;              // residual parked in out
            v[c]=s.x; v[c+1]=s.y; v[c+2]=s.z; v[c+3]=s.w;
            mu += s.x + s.y + s.z + s.w;
            sq += s.x*s.x + s.y*s.y + s.z*s.z + s.w*s.w;
        }
        mu *= (1.f/48.f);
        const float inv = rsqrtf(sq*(1.f/48.f) - mu*mu + 1e-5f);
        uint32_t* myx = (uint32_t*)(s_xg + (tid >> 4)*16*XS + (tid & 15)*XS);
        #pragma unroll
        for (int p = 0; p < 24; p++) {
            const float e0 = (v[2*p]   - mu) * inv * s_g2[2*p]   + s_b2[2*p];
            const float e1 = (v[2*p+1] - mu) * inv * s_g2[2*p+1] + s_b2[2*p+1];
            myx[p] = pack_bf16(e0, e1);
        }
    }
    __syncthreads();

    // ---- A (xln 16x48 bf16) fragments: 3 k16-tiles -------------------------
    uint32_t afr[3][4];
    {
        const uint32_t* wx = (const uint32_t*)(s_xg + wid*16*XS);
        #pragma unroll
        for (int kt = 0; kt < 3; kt++) {
            afr[kt][0] = wx[lr*XS     + 8*kt + lq];
            afr[kt][1] = wx[(lr+8)*XS + 8*kt + lq];
            afr[kt][2] = wx[lr*XS     + 8*kt + lq + 4];
            afr[kt][3] = wx[(lr+8)*XS + 8*kt + lq + 4];
        }
    }

    float yacc[6][4];
    #pragma unroll
    for (int nt = 0; nt < 6; nt++)
        #pragma unroll
        for (int r = 0; r < 4; r++) yacc[nt][r] = 0.f;

    // ---- main loop: 12 chunks of 16 hidden ---------------------------------
    for (int it = 0; it < 12; it++) {
        float h0[4] = {0.f,0.f,0.f,0.f}, h1[4] = {0.f,0.f,0.f,0.f};
        #pragma unroll
        for (int kt = 0; kt < 3; kt++) {
            const uint32_t* wA = s_w1 + (8*kt + lq  )*W1S + 16*it;
            const uint32_t* wB = s_w1 + (8*kt + lq+4)*W1S + 16*it;
            uint32_t b0[2], b1[2];
            b0[0] = wA[lr];     b0[1] = wB[lr];        // hid 16it + lr
            b1[0] = wA[8 + lr]; b1[1] = wB[8 + lr];    // hid 16it+8 + lr
            mma_bf16(h0, afr[kt], b0);
            mma_bf16(h1, afr[kt], b1);
        }
        // bias + exact GELU
        const float2 bbA = *(const float2*)(s_b1 + 16*it + 2*lq);
        const float2 bbB = *(const float2*)(s_b1 + 16*it + 8 + 2*lq);
        #pragma unroll
        for (int r = 0; r < 4; r++) {
            float hs = h0[r] + ((r & 1) ? bbA.y : bbA.x);
            h0[r] = 0.5f * hs * (1.f + erff(hs * 0.7071067811865476f));
            hs = h1[r] + ((r & 1) ? bbB.y : bbB.x);
            h1[r] = 0.5f * hs * (1.f + erff(hs * 0.7071067811865476f));
        }
        // C-frag -> bf16 A-frag: pure pack, no shuffles
        uint32_t ga[4];
        ga[0] = pack_bf16(h0[0], h0[1]);
        ga[1] = pack_bf16(h0[2], h0[3]);
        ga[2] = pack_bf16(h1[0], h1[1]);
        ga[3] = pack_bf16(h1[2], h1[3]);
        // GEMM2: Y[16x48] += G[16x16] * W2chunk[16x48]
        const uint32_t* w2A = s_w2 + (8*it + lq  )*W2S;
        const uint32_t* w2B = s_w2 + (8*it + lq+4)*W2S;
        #pragma unroll
        for (int nt2 = 0; nt2 < 6; nt2++) {
            uint32_t bb[2];
            bb[0] = w2A[nt2*8 + lr];
            bb[1] = w2B[nt2*8 + lr];
            mma_bf16(yacc[nt2], ga, bb);
        }
    }

    // ---- epilogue: stage Y, coalesced residual add ---------------------------
    __syncwarp();
    float* wy = s_xg + wid*16*XS;
    #pragma unroll
    for (int nt2 = 0; nt2 < 6; nt2++) {
        const int c = 8*nt2 + 2*lq;
        *(float2*)(wy + lr*XS + c)     = make_float2(yacc[nt2][0], yacc[nt2][1]);
        *(float2*)(wy + (lr+8)*XS + c) = make_float2(yacc[nt2][2], yacc[nt2][3]);
    }
    __syncwarp();

    {
        const int row = lane >> 1;               // 0..15
        const int c0  = (lane & 1) * 24;         // half-row of 24 floats
        const size_t tok = tokbase + wid*16 + row;
        float* orow = out + tok*48;
        #pragma unroll
        for (int k = 0; k < 6; k++) {
            const int c = c0 + k*4;
            float4 yv  = *(float4*)(wy + row*XS + c);
            float4 res = __ldcg((const float4*)(orow + c));
            float4 r;
            r.x = res.x + yv.x + s_2b[c];
            r.y = res.y + yv.y + s_2b[c+1];
            r.z = res.z + yv.z + s_2b[c+2];
            r.w = res.w + yv.w + s_2b[c+3];
            *(float4*)(orow + c) = r;
        }
    }
}

// ===========================================================================
extern "C" void kernel_launch(void* const* d_in, const int* in_sizes, int n_in,
                              void* d_out, int out_size)
{
    const float* x      = (const float*)d_in[0];
    const float* g1     = (const float*)d_in[1];
    const float* b1     = (const float*)d_in[2];
    const float* qkvw   = (const float*)d_in[3];
    const float* qkvb   = (const float*)d_in[4];
    const float* rpbt   = (const float*)d_in[5];
    const float* wf     = (const float*)d_in[6];
    const float* sw1    = (const float*)d_in[7];
    const float* sb1    = (const float*)d_in[8];
    const float* sw2    = (const float*)d_in[9];
    const float* sb2    = (const float*)d_in[10];
    const float* pw     = (const float*)d_in[11];
    const float* pb     = (const float*)d_in[12];
    const float* g2     = (const float*)d_in[13];
    const float* b2     = (const float*)d_in[14];
    const float* f1w    = (const float*)d_in[15];
    const float* f1b    = (const float*)d_in[16];
    const float* f2w    = (const float*)d_in[17];
    const float* f2b    = (const float*)d_in[18];
    float* out = (float*)d_out;

    const int a_smem = A_SMEM_FLOATS * 4;   // ~197 KB
    const int b_smem = B_SMEM_FLOATS * 4;   // ~95 KB -> 2 CTAs/SM
    cudaFuncSetAttribute(attn_kernel, cudaFuncAttributeMaxDynamicSharedMemorySize, a_smem);
    cudaFuncSetAttribute(mlp_kernel,  cudaFuncAttributeMaxDynamicSharedMemorySize, b_smem);

    attn_kernel<<<BN/4, 512, a_smem>>>(x, g1, b1, qkvw, qkvb, rpbt, wf,
                                       sw1, sb1, sw2, sb2, pw, pb);

    mlp_kernel<<<(BB*HH*WWD)/256, 512, b_smem>>>(x, g2, b2, f1w, f1b, f2w, f2b, out);
}

// round 13
// speedup vs baseline: 3.5889x; 1.3023x over previous
#include <cuda_runtime.h>
#include <cuda_fp16.h>
#include <math.h>
#include <stdint.h>

// ---------------------------------------------------------------------------
// Swin block: B=8, H=W=256, C=48, NH=3 (hd=16), WS=8 (N=64), SS=4, HID=192
// Kernel A: 512 thr = 4 windows x 4 warps (16 query rows each). fp16 m16n8k16
//           for qkv / q.k^T / P.V / proj; C-frag -> A-frag via pure cvt packs.
//           FIX vs R11/R12: VT tile gets stride 36 (rows are 32 words wide;
//           the old stride-28 rows overflowed into each other).
// Kernel B: 512 thr = 16 warps x 16 tokens. fp16 m16n8k16 MLP, 2 CTAs/SM.
// ---------------------------------------------------------------------------

#define BB    8
#define HH    256
#define WWD   256
#define CC    48
#define NWIN  1024
#define BN    8192

__device__ float g_attn[(size_t)BB * HH * WWD * CC];

__device__ __forceinline__ void mma_f16(float* c, const uint32_t* a, const uint32_t* b) {
    asm volatile("mma.sync.aligned.m16n8k16.row.col.f32.f16.f16.f32 "
        "{%0,%1,%2,%3}, {%4,%5,%6,%7}, {%8,%9}, {%0,%1,%2,%3};"
        : "+f"(c[0]), "+f"(c[1]), "+f"(c[2]), "+f"(c[3])
        : "r"(a[0]), "r"(a[1]), "r"(a[2]), "r"(a[3]), "r"(b[0]), "r"(b[1]));
}
// pack two floats into f16x2: first arg -> low 16 bits
__device__ __forceinline__ uint32_t pack_f16(float lo, float hi) {
    uint32_t r;
    asm("cvt.rn.f16x2.f32 %0, %1, %2;" : "=r"(r) : "f"(hi), "f"(lo));
    return r;
}
__device__ __forceinline__ float h_lo(uint32_t w) {
    return __low2float(*reinterpret_cast<const __half2*>(&w));
}
__device__ __forceinline__ float h_hi(uint32_t w) {
    return __high2float(*reinterpret_cast<const __half2*>(&w));
}

// ---- attn smem layout (32-bit words) ----
#define SK   28     // xln / k row stride (rows hold <=24 words)
#define SV   25     // v packed row stride (repack staging only, 24 words)
#define SVT  36     // VT row stride (rows hold 32 keypair words; 36 -> conflict-free)
#define OFF_WQ   0                        // 144 x 28 (f16x2) qkv weights [out][chpair]
#define OFF_WP   (OFF_WQ  + 144*SK)       // 48 x 28  proj weights  [out][chpair]
#define OFF_RPB  (OFF_WP  + 48*SK)        // 676
#define OFF_QKVB (OFF_RPB + 676)          // 144
#define OFF_PB   (OFF_QKVB+ 144)          // 48
#define OFF_SW1  (OFF_PB  + 48)           // 144
#define OFF_SB1  (OFF_SW1 + 144)          // 4
#define OFF_SW2  (OFF_SB1 + 4)            // 144
#define OFF_SB2  (OFF_SW2 + 144)          // 48
#define OFF_MEAN (OFF_SB2 + 48)           // 192
#define OFF_SE   (OFF_MEAN+ 192)          // 192
#define OFF_HH   (OFF_SE  + 192)          // 16
#define OFF_XLN  (OFF_HH  + 16)           // 4 windows x 64 x SK (f16x2 xln)
#define OFF_K    (OFF_XLN + 4*64*SK)      // 4 x 64 x SK  k [token][dimpair]
#define OFF_V    (OFF_K   + 4*64*SK)      // 4 x 64 x SV  v [token][dimpair]
#define OFF_VT   (OFF_V   + 4*64*SV)      // 4 x 48 x SVT v^T [dim][keypair 0..31]
#define A_SMEM_FLOATS (OFF_VT + 4*48*SVT)

__global__ void __launch_bounds__(512) attn_kernel(
    const float* __restrict__ x,
    const float* __restrict__ g1,   const float* __restrict__ b1,
    const float* __restrict__ qkvw, const float* __restrict__ qkvb,
    const float* __restrict__ rpbt, const float* __restrict__ wf,
    const float* __restrict__ sw1,  const float* __restrict__ sb1,
    const float* __restrict__ sw2,  const float* __restrict__ sb2,
    const float* __restrict__ pw,   const float* __restrict__ pb)
{
    extern __shared__ float sm[];
    uint32_t* s_wq = (uint32_t*)(sm + OFF_WQ);
    uint32_t* s_wp = (uint32_t*)(sm + OFF_WP);

    const int tid  = threadIdx.x;
    const int wid  = tid >> 5;
    const int lane = tid & 31;
    const int lr   = lane >> 2;
    const int lq   = lane & 3;

    // ---- stage weights packed f16x2 + tables -------------------------------
    for (int i = tid; i < 144*24; i += 512) {
        const int o = i / 24, p = i % 24;
        s_wq[o*SK + p] = pack_f16(qkvw[o*48 + 2*p], qkvw[o*48 + 2*p + 1]);
    }
    for (int i = tid; i < 48*24; i += 512) {
        const int o = i / 24, p = i % 24;
        s_wp[o*SK + p] = pack_f16(pw[o*48 + 2*p], pw[o*48 + 2*p + 1]);
    }
    for (int i = tid; i < 675; i += 512) sm[OFF_RPB + i] = __ldg(rpbt + i);
    for (int i = tid; i < 144; i += 512) {
        sm[OFF_QKVB + i] = qkvb[i];
        sm[OFF_SW1  + i] = sw1[i];
        sm[OFF_SW2  + i] = sw2[i];
    }
    if (tid < 48) { sm[OFF_PB + tid] = pb[tid]; sm[OFF_SB2 + tid] = sb2[tid]; }
    if (tid < 3)  sm[OFF_SB1 + tid] = sb1[tid];

    // ---- LN1: threads 0..255 = one token of one window (pack f16) ---------
    if (tid < 256) {
        const int wl2 = tid >> 6, tok2 = tid & 63;
        const int wg2 = blockIdx.x*4 + wl2;
        const int b2 = wg2 >> 10, ww = wg2 & 1023;
        const int wy2 = ww >> 5, wx2 = ww & 31;
        const int gy = (wy2*8 + (tok2 >> 3) + 4) & 255;
        const int gx = (wx2*8 + (tok2 & 7) + 4) & 255;
        const float* xrow = x + (((size_t)b2 << 16) | (gy << 8) | gx) * CC;
        float v[48];
        float mu = 0.f, sq = 0.f;
        #pragma unroll
        for (int c = 0; c < 48; c += 4) {
            float4 t = __ldg((const float4*)(xrow + c));
            v[c]=t.x; v[c+1]=t.y; v[c+2]=t.z; v[c+3]=t.w;
            mu += t.x + t.y + t.z + t.w;
            sq += t.x*t.x + t.y*t.y + t.z*t.z + t.w*t.w;
        }
        mu *= (1.f/48.f);
        const float inv = rsqrtf(sq*(1.f/48.f) - mu*mu + 1e-5f);
        uint32_t* myx = (uint32_t*)(sm + OFF_XLN) + (wl2*64 + tok2)*SK;
        #pragma unroll
        for (int p = 0; p < 24; p++) {
            const float e0 = (v[2*p]   - mu) * inv * __ldg(g1 + 2*p)   + __ldg(b1 + 2*p);
            const float e1 = (v[2*p+1] - mu) * inv * __ldg(g1 + 2*p+1) + __ldg(b1 + 2*p+1);
            myx[p] = pack_f16(e0, e1);
        }
    }
    __syncthreads();

    // ---- SE: mean (of f16 xln) -> fc1+relu -> fc2+sigmoid ------------------
    if (tid < 192) {
        const int wl2 = tid / 48, c = tid % 48;
        const uint32_t* xw = (const uint32_t*)(sm + OFF_XLN) + wl2*64*SK;
        float s = 0.f;
        for (int t = 0; t < 64; t++) {
            const uint32_t w = xw[t*SK + (c >> 1)];
            s += (c & 1) ? h_hi(w) : h_lo(w);
        }
        sm[OFF_MEAN + wl2*48 + c] = s * (1.f/64.f);
    }
    __syncthreads();
    if (tid < 12) {
        const int wl2 = tid / 3, o = tid % 3;
        float a = sm[OFF_SB1 + o];
        #pragma unroll
        for (int c = 0; c < 48; c++) a += sm[OFF_MEAN + wl2*48 + c] * sm[OFF_SW1 + o*48 + c];
        sm[OFF_HH + wl2*4 + o] = fmaxf(a, 0.f);
    }
    __syncthreads();
    if (tid < 192) {
        const int wl2 = tid / 48, c = tid % 48;
        float a = sm[OFF_SB2 + c] + sm[OFF_HH + wl2*4 + 0]*sm[OFF_SW2 + c*3 + 0]
                                  + sm[OFF_HH + wl2*4 + 1]*sm[OFF_SW2 + c*3 + 1]
                                  + sm[OFF_HH + wl2*4 + 2]*sm[OFF_SW2 + c*3 + 2];
        sm[OFF_SE + wl2*48 + c] = 1.f/(1.f + __expf(-a));
    }
    __syncthreads();

    // ---- per-warp geometry: 4 warps per window, 16 query rows each ---------
    const int wl = wid >> 2;
    const int rowbase = (wid & 3) * 16;
    const int wg = blockIdx.x*4 + wl;
    const int bimg = wg >> 10, ww = wg & 1023;
    const int wy = ww >> 5, wx = ww & 31;
    uint32_t* xlw = (uint32_t*)(sm + OFF_XLN) + wl*64*SK;
    uint32_t* kw  = (uint32_t*)(sm + OFF_K)   + wl*64*SK;
    uint32_t* vw  = (uint32_t*)(sm + OFF_V)   + wl*64*SV;
    uint32_t* vtw = (uint32_t*)(sm + OFF_VT)  + wl*48*SVT;
    const int r0 = rowbase + lr;

    // ---- qkv GEMM: A = xln[16x48] f16 (3 k16 tiles) -------------------------
    uint32_t afr[3][4];
    #pragma unroll
    for (int kt = 0; kt < 3; kt++) {
        afr[kt][0] = xlw[r0*SK     + 8*kt + lq];
        afr[kt][1] = xlw[(r0+8)*SK + 8*kt + lq];
        afr[kt][2] = xlw[r0*SK     + 8*kt + lq + 4];
        afr[kt][3] = xlw[(r0+8)*SK + 8*kt + lq + 4];
    }

    float qf[6][4];
    #pragma unroll
    for (int nt = 0; nt < 18; nt++) {
        float cf[4] = {0.f,0.f,0.f,0.f};
        #pragma unroll
        for (int kt = 0; kt < 3; kt++) {
            uint32_t bf[2];
            bf[0] = s_wq[(nt*8 + lr)*SK + 8*kt + lq];
            bf[1] = s_wq[(nt*8 + lr)*SK + 8*kt + lq + 4];
            mma_f16(cf, afr[kt], bf);
        }
        const float be = sm[OFF_QKVB + nt*8 + 2*lq];
        const float bo = sm[OFF_QKVB + nt*8 + 2*lq + 1];
        if (nt < 6) {
            qf[nt][0]=(cf[0]+be)*0.25f; qf[nt][1]=(cf[1]+bo)*0.25f;
            qf[nt][2]=(cf[2]+be)*0.25f; qf[nt][3]=(cf[3]+bo)*0.25f;
        } else if (nt < 12) {
            const int dp = (nt - 6)*4 + lq;
            kw[r0*SK     + dp] = pack_f16(cf[0]+be, cf[1]+bo);
            kw[(r0+8)*SK + dp] = pack_f16(cf[2]+be, cf[3]+bo);
        } else {
            const int dp = (nt - 12)*4 + lq;
            vw[r0*SV     + dp] = pack_f16(cf[0]+be, cf[1]+bo);
            vw[(r0+8)*SV + dp] = pack_f16(cf[2]+be, cf[3]+bo);
        }
    }
    __syncthreads();

    // ---- V repack: [token][dimpair] -> VT [dim][keypair] (stride SVT) ------
    {
        const int rwarp = wid & 3;          // 6 dimpairs per warp
        #pragma unroll
        for (int i = 0; i < 6; i++) {
            const int dp = rwarp*6 + i;     // 0..23
            const uint32_t wa = vw[(2*lane)*SV + dp];
            const uint32_t wb = vw[(2*lane+1)*SV + dp];
            vtw[(2*dp)*SVT   + lane] = __byte_perm(wa, wb, 0x5410);  // dim 2dp
            vtw[(2*dp+1)*SVT + lane] = __byte_perm(wa, wb, 0x7632);  // dim 2dp+1
        }
    }
    __syncthreads();

    // ---- attention -----------------------------------------------------------
    float oacc[6][4];
    #pragma unroll
    for (int n = 0; n < 6; n++)
        #pragma unroll
        for (int r = 0; r < 4; r++) oacc[n][r] = 0.f;

    const bool edge = (wy == 31) || (wx == 31);

    #pragma unroll
    for (int h = 0; h < 3; h++) {
        // q A-frag: pure pack from qkv C-frags (k16 = full head dim)
        uint32_t qa[4];
        qa[0] = pack_f16(qf[2*h][0],   qf[2*h][1]);
        qa[1] = pack_f16(qf[2*h][2],   qf[2*h][3]);
        qa[2] = pack_f16(qf[2*h+1][0], qf[2*h+1][1]);
        qa[3] = pack_f16(qf[2*h+1][2], qf[2*h+1][3]);

        float sf[8][4];
        #pragma unroll
        for (int nt = 0; nt < 8; nt++) {
            #pragma unroll
            for (int r = 0; r < 4; r++) sf[nt][r] = 0.f;
            uint32_t bf[2];
            bf[0] = kw[(nt*8 + lr)*SK + h*8 + lq];
            bf[1] = kw[(nt*8 + lr)*SK + h*8 + lq + 4];
            mma_f16(sf[nt], qa, bf);
        }

        // rpb + shift mask + softmax (fp32 in C-frags)
        {
            const int iA = r0, iB = r0 + 8;
            const int tiA = iA >> 3, tjA = iA & 7;
            const int tiB = iB >> 3, tjB = iB & 7;
            const int ryA = (wy==31) ? (tiA >= 4 ? 2 : 1) : 0;
            const int rxA = (wx==31) ? (tjA >= 4 ? 2 : 1) : 0;
            const int ryB = (wy==31) ? (tiB >= 4 ? 2 : 1) : 0;
            const int rxB = (wx==31) ? (tjB >= 4 ? 2 : 1) : 0;
            #pragma unroll
            for (int nt = 0; nt < 8; nt++) {
                #pragma unroll
                for (int e = 0; e < 2; e++) {
                    const int j = nt*8 + 2*lq + e;
                    const int rj = j >> 3, cj = j & 7;
                    const float bA = sm[OFF_RPB + ((tiA - rj + 7)*15 + (tjA - cj + 7))*3 + h];
                    const float bB = sm[OFF_RPB + ((tiB - rj + 7)*15 + (tjB - cj + 7))*3 + h];
                    float mA = 0.f, mB = 0.f;
                    if (edge) {
                        const int ryj = (wy==31) ? (rj >= 4 ? 2 : 1) : 0;
                        const int rxj = (wx==31) ? (cj >= 4 ? 2 : 1) : 0;
                        if (ryj != ryA || rxj != rxA) mA = -100.f;
                        if (ryj != ryB || rxj != rxB) mB = -100.f;
                    }
                    sf[nt][e]   += bA + mA;
                    sf[nt][e+2] += bB + mB;
                }
            }
            float mxA = -1e30f, mxB = -1e30f;
            #pragma unroll
            for (int nt = 0; nt < 8; nt++) {
                mxA = fmaxf(mxA, fmaxf(sf[nt][0], sf[nt][1]));
                mxB = fmaxf(mxB, fmaxf(sf[nt][2], sf[nt][3]));
            }
            mxA = fmaxf(mxA, __shfl_xor_sync(0xffffffffu, mxA, 1));
            mxA = fmaxf(mxA, __shfl_xor_sync(0xffffffffu, mxA, 2));
            mxB = fmaxf(mxB, __shfl_xor_sync(0xffffffffu, mxB, 1));
            mxB = fmaxf(mxB, __shfl_xor_sync(0xffffffffu, mxB, 2));
            float sA = 0.f, sB = 0.f;
            #pragma unroll
            for (int nt = 0; nt < 8; nt++) {
                sf[nt][0] = __expf(sf[nt][0] - mxA);
                sf[nt][1] = __expf(sf[nt][1] - mxA);
                sf[nt][2] = __expf(sf[nt][2] - mxB);
                sf[nt][3] = __expf(sf[nt][3] - mxB);
                sA += sf[nt][0] + sf[nt][1];
                sB += sf[nt][2] + sf[nt][3];
            }
            sA += __shfl_xor_sync(0xffffffffu, sA, 1);
            sA += __shfl_xor_sync(0xffffffffu, sA, 2);
            sB += __shfl_xor_sync(0xffffffffu, sB, 1);
            sB += __shfl_xor_sync(0xffffffffu, sB, 2);
            const float rAi = 1.f / sA, rBi = 1.f / sB;
            #pragma unroll
            for (int nt = 0; nt < 8; nt++) {
                sf[nt][0] *= rAi; sf[nt][1] *= rAi;
                sf[nt][2] *= rBi; sf[nt][3] *= rBi;
            }
        }

        // P.V: A-frags packed from prob C-frags; B from VT [dim][keypair]
        #pragma unroll
        for (int kt = 0; kt < 4; kt++) {
            uint32_t pa[4];
            pa[0] = pack_f16(sf[2*kt][0],   sf[2*kt][1]);
            pa[1] = pack_f16(sf[2*kt][2],   sf[2*kt][3]);
            pa[2] = pack_f16(sf[2*kt+1][0], sf[2*kt+1][1]);
            pa[3] = pack_f16(sf[2*kt+1][2], sf[2*kt+1][3]);
            #pragma unroll
            for (int nt2 = 0; nt2 < 2; nt2++) {
                uint32_t bf[2];
                bf[0] = vtw[(h*16 + nt2*8 + lr)*SVT + 8*kt + lq];
                bf[1] = vtw[(h*16 + nt2*8 + lr)*SVT + 8*kt + lq + 4];
                mma_f16(oacc[2*h + nt2], pa, bf);
            }
        }
    }

    // ---- SE add ----------------------------------------------------------------
    {
        const float wfv = __ldg(wf);
        const float* sew = sm + OFF_SE + wl*48;
        #pragma unroll
        for (int n = 0; n < 6; n++) {
            const int c0 = n*8 + 2*lq;
            const uint32_t wA = xlw[r0*SK     + n*4 + lq];
            const uint32_t wB = xlw[(r0+8)*SK + n*4 + lq];
            oacc[n][0] += wfv * h_lo(wA) * sew[c0];
            oacc[n][1] += wfv * h_hi(wA) * sew[c0+1];
            oacc[n][2] += wfv * h_lo(wB) * sew[c0];
            oacc[n][3] += wfv * h_hi(wB) * sew[c0+1];
        }
    }

    // ---- proj GEMM + direct scatter ---------------------------------------------
    uint32_t pa[3][4];
    #pragma unroll
    for (int kt = 0; kt < 3; kt++) {
        pa[kt][0] = pack_f16(oacc[2*kt][0],   oacc[2*kt][1]);
        pa[kt][1] = pack_f16(oacc[2*kt][2],   oacc[2*kt][3]);
        pa[kt][2] = pack_f16(oacc[2*kt+1][0], oacc[2*kt+1][1]);
        pa[kt][3] = pack_f16(oacc[2*kt+1][2], oacc[2*kt+1][3]);
    }

    const int gyA = (wy*8 + (r0 >> 3) + 4) & 255;
    const int gxA = (wx*8 + (r0 & 7) + 4) & 255;
    const int gyB = (wy*8 + ((r0+8) >> 3) + 4) & 255;
    const int gxB = (wx*8 + ((r0+8) & 7) + 4) & 255;
    float* orowA = g_attn + (((size_t)bimg << 16) | (gyA << 8) | gxA) * CC;
    float* orowB = g_attn + (((size_t)bimg << 16) | (gyB << 8) | gxB) * CC;

    #pragma unroll
    for (int nt = 0; nt < 6; nt++) {
        float pf[4] = {0.f,0.f,0.f,0.f};
        #pragma unroll
        for (int kt = 0; kt < 3; kt++) {
            uint32_t bf[2];
            bf[0] = s_wp[(nt*8 + lr)*SK + 8*kt + lq];
            bf[1] = s_wp[(nt*8 + lr)*SK + 8*kt + lq + 4];
            mma_f16(pf, pa[kt], bf);
        }
        const float be = sm[OFF_PB + nt*8 + 2*lq];
        const float bo = sm[OFF_PB + nt*8 + 2*lq + 1];
        *(float2*)(orowA + nt*8 + 2*lq) = make_float2(pf[0]+be, pf[1]+bo);
        *(float2*)(orowB + nt*8 + 2*lq) = make_float2(pf[2]+be, pf[3]+bo);
    }
}

// ===========================================================================
// MLP: fp16 m16n8k16, 512 thr = 16 warps x 16 tokens, 2 CTAs/SM.
// ===========================================================================
#define XS   52
#define W1S  200
#define W2S  56
#define B_SMEM_FLOATS (24*W1S + 96*W2S + 192 + 48 + 48 + 48 + 16*16*XS)

__global__ void __launch_bounds__(512, 2) mlp_kernel(
    const float* __restrict__ x,
    const float* __restrict__ g2,   const float* __restrict__ b2,
    const float* __restrict__ f1w,  const float* __restrict__ f1b,
    const float* __restrict__ f2w,  const float* __restrict__ f2b,
    float* __restrict__ out)
{
    extern __shared__ float sm[];
    uint32_t* s_w1 = (uint32_t*)sm;
    uint32_t* s_w2 = (uint32_t*)(sm + 24*W1S);
    float* s_b1 = sm + 24*W1S + 96*W2S;
    float* s_2b = s_b1 + 192;
    float* s_g2 = s_2b + 48;
    float* s_b2 = s_g2 + 48;
    float* s_xg = s_b2 + 48;

    const int tid  = threadIdx.x;
    const int wid  = tid >> 5;
    const int lane = tid & 31;
    const int lr   = lane >> 2;
    const int lq   = lane & 3;

    for (int i = tid; i < 24*192; i += 512) {
        const int p = i / 192, o = i % 192;
        s_w1[p*W1S + o] = pack_f16(f1w[o*48 + 2*p], f1w[o*48 + 2*p + 1]);
    }
    for (int i = tid; i < 96*48; i += 512) {
        const int hp = i / 48, ch = i % 48;
        s_w2[hp*W2S + ch] = pack_f16(f2w[ch*192 + 2*hp], f2w[ch*192 + 2*hp + 1]);
    }
    if (tid < 192) s_b1[tid] = f1b[tid];
    if (tid < 48) { s_2b[tid] = f2b[tid]; s_g2[tid] = g2[tid]; s_b2[tid] = b2[tid]; }
    __syncthreads();

    const size_t tokbase = (size_t)blockIdx.x * 256;

    if (tid < 256) {
        const size_t tok = tokbase + tid;
        const float* xrow = x      + tok*48;
        const float* hrow = g_attn + tok*48;
        float* orow = out + tok*48;
        float v[48];
        float mu = 0.f, sq = 0.f;
        #pragma unroll
        for (int c = 0; c < 48; c += 4) {
            float4 a = __ldg((const float4*)(xrow + c));
            float4 h = *(const float4*)(hrow + c);
            float4 s;
            s.x = a.x + h.x; s.y = a.y + h.y; s.z = a.z + h.z; s.w = a.w + h.w;
            *(float4*)(orow + c) = s;
            v[c]=s.x; v[c+1]=s.y; v[c+2]=s.z; v[c+3]=s.w;
            mu += s.x + s.y + s.z + s.w;
            sq += s.x*s.x + s.y*s.y + s.z*s.z + s.w*s.w;
        }
        mu *= (1.f/48.f);
        const float inv = rsqrtf(sq*(1.f/48.f) - mu*mu + 1e-5f);
        uint32_t* myx = (uint32_t*)(s_xg + (tid >> 4)*16*XS + (tid & 15)*XS);
        #pragma unroll
        for (int p = 0; p < 24; p++) {
            const float e0 = (v[2*p]   - mu) * inv * s_g2[2*p]   + s_b2[2*p];
            const float e1 = (v[2*p+1] - mu) * inv * s_g2[2*p+1] + s_b2[2*p+1];
            myx[p] = pack_f16(e0, e1);
        }
    }
    __syncthreads();

    uint32_t afr[3][4];
    {
        const uint32_t* wx = (const uint32_t*)(s_xg + wid*16*XS);
        #pragma unroll
        for (int kt = 0; kt < 3; kt++) {
            afr[kt][0] = wx[lr*XS     + 8*kt + lq];
            afr[kt][1] = wx[(lr+8)*XS + 8*kt + lq];
            afr[kt][2] = wx[lr*XS     + 8*kt + lq + 4];
            afr[kt][3] = wx[(lr+8)*XS + 8*kt + lq + 4];
        }
    }

    float yacc[6][4];
    #pragma unroll
    for (int nt = 0; nt < 6; nt++)
        #pragma unroll
        for (int r = 0; r < 4; r++) yacc[nt][r] = 0.f;

    for (int it = 0; it < 12; it++) {
        float h0[4] = {0.f,0.f,0.f,0.f}, h1[4] = {0.f,0.f,0.f,0.f};
        #pragma unroll
        for (int kt = 0; kt < 3; kt++) {
            const uint32_t* wA = s_w1 + (8*kt + lq  )*W1S + 16*it;
            const uint32_t* wB = s_w1 + (8*kt + lq+4)*W1S + 16*it;
            uint32_t b0[2], b1[2];
            b0[0] = wA[lr];     b0[1] = wB[lr];
            b1[0] = wA[8 + lr]; b1[1] = wB[8 + lr];
            mma_f16(h0, afr[kt], b0);
            mma_f16(h1, afr[kt], b1);
        }
        const float2 bbA = *(const float2*)(s_b1 + 16*it + 2*lq);
        const float2 bbB = *(const float2*)(s_b1 + 16*it + 8 + 2*lq);
        #pragma unroll
        for (int r = 0; r < 4; r++) {
            float hs = h0[r] + ((r & 1) ? bbA.y : bbA.x);
            h0[r] = 0.5f * hs * (1.f + erff(hs * 0.7071067811865476f));
            hs = h1[r] + ((r & 1) ? bbB.y : bbB.x);
            h1[r] = 0.5f * hs * (1.f + erff(hs * 0.7071067811865476f));
        }
        uint32_t ga[4];
        ga[0] = pack_f16(h0[0], h0[1]);
        ga[1] = pack_f16(h0[2], h0[3]);
        ga[2] = pack_f16(h1[0], h1[1]);
        ga[3] = pack_f16(h1[2], h1[3]);
        const uint32_t* w2A = s_w2 + (8*it + lq  )*W2S;
        const uint32_t* w2B = s_w2 + (8*it + lq+4)*W2S;
        #pragma unroll
        for (int nt2 = 0; nt2 < 6; nt2++) {
            uint32_t bb[2];
            bb[0] = w2A[nt2*8 + lr];
            bb[1] = w2B[nt2*8 + lr];
            mma_f16(yacc[nt2], ga, bb);
        }
    }

    __syncwarp();
    float* wy = s_xg + wid*16*XS;
    #pragma unroll
    for (int nt2 = 0; nt2 < 6; nt2++) {
        const int c = 8*nt2 + 2*lq;
        *(float2*)(wy + lr*XS + c)     = make_float2(yacc[nt2][0], yacc[nt2][1]);
        *(float2*)(wy + (lr+8)*XS + c) = make_float2(yacc[nt2][2], yacc[nt2][3]);
    }
    __syncwarp();

    {
        const int row = lane >> 1;
        const int c0  = (lane & 1) * 24;
        const size_t tok = tokbase + wid*16 + row;
        float* orow = out + tok*48;
        #pragma unroll
        for (int k = 0; k < 6; k++) {
            const int c = c0 + k*4;
            float4 yv  = *(float4*)(wy + row*XS + c);
            float4 res = __ldcg((const float4*)(orow + c));
            float4 r;
            r.x = res.x + yv.x + s_2b[c];
            r.y = res.y + yv.y + s_2b[c+1];
            r.z = res.z + yv.z + s_2b[c+2];
            r.w = res.w + yv.w + s_2b[c+3];
            *(float4*)(orow + c) = r;
        }
    }
}

// ===========================================================================
extern "C" void kernel_launch(void* const* d_in, const int* in_sizes, int n_in,
                              void* d_out, int out_size)
{
    const float* x      = (const float*)d_in[0];
    const float* g1     = (const float*)d_in[1];
    const float* b1     = (const float*)d_in[2];
    const float* qkvw   = (const float*)d_in[3];
    const float* qkvb   = (const float*)d_in[4];
    const float* rpbt   = (const float*)d_in[5];
    const float* wf     = (const float*)d_in[6];
    const float* sw1    = (const float*)d_in[7];
    const float* sb1    = (const float*)d_in[8];
    const float* sw2    = (const float*)d_in[9];
    const float* sb2    = (const float*)d_in[10];
    const float* pw     = (const float*)d_in[11];
    const float* pb     = (const float*)d_in[12];
    const float* g2     = (const float*)d_in[13];
    const float* b2     = (const float*)d_in[14];
    const float* f1w    = (const float*)d_in[15];
    const float* f1b    = (const float*)d_in[16];
    const float* f2w    = (const float*)d_in[17];
    const float* f2b    = (const float*)d_in[18];
    float* out = (float*)d_out;

    const int a_smem = A_SMEM_FLOATS * 4;   // ~138 KB
    const int b_smem = B_SMEM_FLOATS * 4;   // ~95 KB -> 2 CTAs/SM
    cudaFuncSetAttribute(attn_kernel, cudaFuncAttributeMaxDynamicSharedMemorySize, a_smem);
    cudaFuncSetAttribute(mlp_kernel,  cudaFuncAttributeMaxDynamicSharedMemorySize, b_smem);

    attn_kernel<<<BN/4, 512, a_smem>>>(x, g1, b1, qkvw, qkvb, rpbt, wf,
                                       sw1, sb1, sw2, sb2, pw, pb);

    mlp_kernel<<<(BB*HH*WWD)/256, 512, b_smem>>>(x, g2, b2, f1w, f1b, f2w, f2b, out);
}

// round 14
// speedup vs baseline: 3.6790x; 1.0251x over previous
#include <cuda_runtime.h>
#include <cuda_fp16.h>
#include <math.h>
#include <stdint.h>

// ---------------------------------------------------------------------------
// Swin block: B=8, H=W=256, C=48, NH=3 (hd=16), WS=8 (N=64), SS=4, HID=192
// Kernel A: 512 thr = 4 windows x 4 warps (16 query rows each). fp16 m16n8k16
//           for qkv / q.k^T / P.V / proj; C-frag -> A-frag via pure cvt packs.
// Kernel B: 512 thr = 16 warps x 16 tokens. fp16 m16n8k16 MLP, 2 CTAs/SM.
//           R14: GELU via tanh-form sigmoid (1 MUFU.EX2) instead of erff.
// ---------------------------------------------------------------------------

#define BB    8
#define HH    256
#define WWD   256
#define CC    48
#define NWIN  1024
#define BN    8192

__device__ float g_attn[(size_t)BB * HH * WWD * CC];

__device__ __forceinline__ void mma_f16(float* c, const uint32_t* a, const uint32_t* b) {
    asm volatile("mma.sync.aligned.m16n8k16.row.col.f32.f16.f16.f32 "
        "{%0,%1,%2,%3}, {%4,%5,%6,%7}, {%8,%9}, {%0,%1,%2,%3};"
        : "+f"(c[0]), "+f"(c[1]), "+f"(c[2]), "+f"(c[3])
        : "r"(a[0]), "r"(a[1]), "r"(a[2]), "r"(a[3]), "r"(b[0]), "r"(b[1]));
}
// pack two floats into f16x2: first arg -> low 16 bits
__device__ __forceinline__ uint32_t pack_f16(float lo, float hi) {
    uint32_t r;
    asm("cvt.rn.f16x2.f32 %0, %1, %2;" : "=r"(r) : "f"(hi), "f"(lo));
    return r;
}
__device__ __forceinline__ float h_lo(uint32_t w) {
    return __low2float(*reinterpret_cast<const __half2*>(&w));
}
__device__ __forceinline__ float h_hi(uint32_t w) {
    return __high2float(*reinterpret_cast<const __half2*>(&w));
}
// tanh-form GELU as a sigmoid: x * sigmoid(2z), 2z = 1.59577x + 0.0713548x^3.
// |error vs exact erf-GELU| <= ~1.5e-4 abs (<=5e-5 on |x|<1, which is our range).
__device__ __forceinline__ float gelu_fast(float x) {
    const float t  = x * x;
    const float z2 = x * (1.5957691216f + 0.0713548162f * t);
    return x * __fdividef(1.f, 1.f + __expf(-z2));
}

// ---- attn smem layout (32-bit words) ----
#define SK   28     // xln / k row stride (rows hold <=24 words)
#define SV   25     // v packed row stride (repack staging only, 24 words)
#define SVT  36     // VT row stride (rows hold 32 keypair words)
#define OFF_WQ   0                        // 144 x 28 (f16x2) qkv weights [out][chpair]
#define OFF_WP   (OFF_WQ  + 144*SK)       // 48 x 28  proj weights  [out][chpair]
#define OFF_RPB  (OFF_WP  + 48*SK)        // 676
#define OFF_QKVB (OFF_RPB + 676)          // 144
#define OFF_PB   (OFF_QKVB+ 144)          // 48
#define OFF_SW1  (OFF_PB  + 48)           // 144
#define OFF_SB1  (OFF_SW1 + 144)          // 4
#define OFF_SW2  (OFF_SB1 + 4)            // 144
#define OFF_SB2  (OFF_SW2 + 144)          // 48
#define OFF_MEAN (OFF_SB2 + 48)           // 192
#define OFF_SE   (OFF_MEAN+ 192)          // 192
#define OFF_HH   (OFF_SE  + 192)          // 16
#define OFF_XLN  (OFF_HH  + 16)           // 4 windows x 64 x SK (f16x2 xln)
#define OFF_K    (OFF_XLN + 4*64*SK)      // 4 x 64 x SK  k [token][dimpair]
#define OFF_V    (OFF_K   + 4*64*SK)      // 4 x 64 x SV  v [token][dimpair]
#define OFF_VT   (OFF_V   + 4*64*SV)      // 4 x 48 x SVT v^T [dim][keypair 0..31]
#define A_SMEM_FLOATS (OFF_VT + 4*48*SVT)

__global__ void __launch_bounds__(512) attn_kernel(
    const float* __restrict__ x,
    const float* __restrict__ g1,   const float* __restrict__ b1,
    const float* __restrict__ qkvw, const float* __restrict__ qkvb,
    const float* __restrict__ rpbt, const float* __restrict__ wf,
    const float* __restrict__ sw1,  const float* __restrict__ sb1,
    const float* __restrict__ sw2,  const float* __restrict__ sb2,
    const float* __restrict__ pw,   const float* __restrict__ pb)
{
    extern __shared__ float sm[];
    uint32_t* s_wq = (uint32_t*)(sm + OFF_WQ);
    uint32_t* s_wp = (uint32_t*)(sm + OFF_WP);

    const int tid  = threadIdx.x;
    const int wid  = tid >> 5;
    const int lane = tid & 31;
    const int lr   = lane >> 2;
    const int lq   = lane & 3;

    // ---- stage weights packed f16x2 + tables -------------------------------
    for (int i = tid; i < 144*24; i += 512) {
        const int o = i / 24, p = i % 24;
        s_wq[o*SK + p] = pack_f16(qkvw[o*48 + 2*p], qkvw[o*48 + 2*p + 1]);
    }
    for (int i = tid; i < 48*24; i += 512) {
        const int o = i / 24, p = i % 24;
        s_wp[o*SK + p] = pack_f16(pw[o*48 + 2*p], pw[o*48 + 2*p + 1]);
    }
    for (int i = tid; i < 675; i += 512) sm[OFF_RPB + i] = __ldg(rpbt + i);
    for (int i = tid; i < 144; i += 512) {
        sm[OFF_QKVB + i] = qkvb[i];
        sm[OFF_SW1  + i] = sw1[i];
        sm[OFF_SW2  + i] = sw2[i];
    }
    if (tid < 48) { sm[OFF_PB + tid] = pb[tid]; sm[OFF_SB2 + tid] = sb2[tid]; }
    if (tid < 3)  sm[OFF_SB1 + tid] = sb1[tid];

    // ---- LN1: threads 0..255 = one token of one window (pack f16) ---------
    if (tid < 256) {
        const int wl2 = tid >> 6, tok2 = tid & 63;
        const int wg2 = blockIdx.x*4 + wl2;
        const int b2 = wg2 >> 10, ww = wg2 & 1023;
        const int wy2 = ww >> 5, wx2 = ww & 31;
        const int gy = (wy2*8 + (tok2 >> 3) + 4) & 255;
        const int gx = (wx2*8 + (tok2 & 7) + 4) & 255;
        const float* xrow = x + (((size_t)b2 << 16) | (gy << 8) | gx) * CC;
        float v[48];
        float mu = 0.f, sq = 0.f;
        #pragma unroll
        for (int c = 0; c < 48; c += 4) {
            float4 t = __ldg((const float4*)(xrow + c));
            v[c]=t.x; v[c+1]=t.y; v[c+2]=t.z; v[c+3]=t.w;
            mu += t.x + t.y + t.z + t.w;
            sq += t.x*t.x + t.y*t.y + t.z*t.z + t.w*t.w;
        }
        mu *= (1.f/48.f);
        const float inv = rsqrtf(sq*(1.f/48.f) - mu*mu + 1e-5f);
        uint32_t* myx = (uint32_t*)(sm + OFF_XLN) + (wl2*64 + tok2)*SK;
        #pragma unroll
        for (int p = 0; p < 24; p++) {
            const float e0 = (v[2*p]   - mu) * inv * __ldg(g1 + 2*p)   + __ldg(b1 + 2*p);
            const float e1 = (v[2*p+1] - mu) * inv * __ldg(g1 + 2*p+1) + __ldg(b1 + 2*p+1);
            myx[p] = pack_f16(e0, e1);
        }
    }
    __syncthreads();

    // ---- SE: mean (of f16 xln) -> fc1+relu -> fc2+sigmoid ------------------
    if (tid < 192) {
        const int wl2 = tid / 48, c = tid % 48;
        const uint32_t* xw = (const uint32_t*)(sm + OFF_XLN) + wl2*64*SK;
        float s = 0.f;
        for (int t = 0; t < 64; t++) {
            const uint32_t w = xw[t*SK + (c >> 1)];
            s += (c & 1) ? h_hi(w) : h_lo(w);
        }
        sm[OFF_MEAN + wl2*48 + c] = s * (1.f/64.f);
    }
    __syncthreads();
    if (tid < 12) {
        const int wl2 = tid / 3, o = tid % 3;
        float a = sm[OFF_SB1 + o];
        #pragma unroll
        for (int c = 0; c < 48; c++) a += sm[OFF_MEAN + wl2*48 + c] * sm[OFF_SW1 + o*48 + c];
        sm[OFF_HH + wl2*4 + o] = fmaxf(a, 0.f);
    }
    __syncthreads();
    if (tid < 192) {
        const int wl2 = tid / 48, c = tid % 48;
        float a = sm[OFF_SB2 + c] + sm[OFF_HH + wl2*4 + 0]*sm[OFF_SW2 + c*3 + 0]
                                  + sm[OFF_HH + wl2*4 + 1]*sm[OFF_SW2 + c*3 + 1]
                                  + sm[OFF_HH + wl2*4 + 2]*sm[OFF_SW2 + c*3 + 2];
        sm[OFF_SE + wl2*48 + c] = 1.f/(1.f + __expf(-a));
    }
    __syncthreads();

    // ---- per-warp geometry: 4 warps per window, 16 query rows each ---------
    const int wl = wid >> 2;
    const int rowbase = (wid & 3) * 16;
    const int wg = blockIdx.x*4 + wl;
    const int bimg = wg >> 10, ww = wg & 1023;
    const int wy = ww >> 5, wx = ww & 31;
    uint32_t* xlw = (uint32_t*)(sm + OFF_XLN) + wl*64*SK;
    uint32_t* kw  = (uint32_t*)(sm + OFF_K)   + wl*64*SK;
    uint32_t* vw  = (uint32_t*)(sm + OFF_V)   + wl*64*SV;
    uint32_t* vtw = (uint32_t*)(sm + OFF_VT)  + wl*48*SVT;
    const int r0 = rowbase + lr;

    // ---- qkv GEMM: A = xln[16x48] f16 (3 k16 tiles) -------------------------
    uint32_t afr[3][4];
    #pragma unroll
    for (int kt = 0; kt < 3; kt++) {
        afr[kt][0] = xlw[r0*SK     + 8*kt + lq];
        afr[kt][1] = xlw[(r0+8)*SK + 8*kt + lq];
        afr[kt][2] = xlw[r0*SK     + 8*kt + lq + 4];
        afr[kt][3] = xlw[(r0+8)*SK + 8*kt + lq + 4];
    }

    float qf[6][4];
    #pragma unroll
    for (int nt = 0; nt < 18; nt++) {
        float cf[4] = {0.f,0.f,0.f,0.f};
        #pragma unroll
        for (int kt = 0; kt < 3; kt++) {
            uint32_t bf[2];
            bf[0] = s_wq[(nt*8 + lr)*SK + 8*kt + lq];
            bf[1] = s_wq[(nt*8 + lr)*SK + 8*kt + lq + 4];
            mma_f16(cf, afr[kt], bf);
        }
        const float be = sm[OFF_QKVB + nt*8 + 2*lq];
        const float bo = sm[OFF_QKVB + nt*8 + 2*lq + 1];
        if (nt < 6) {
            qf[nt][0]=(cf[0]+be)*0.25f; qf[nt][1]=(cf[1]+bo)*0.25f;
            qf[nt][2]=(cf[2]+be)*0.25f; qf[nt][3]=(cf[3]+bo)*0.25f;
        } else if (nt < 12) {
            const int dp = (nt - 6)*4 + lq;
            kw[r0*SK     + dp] = pack_f16(cf[0]+be, cf[1]+bo);
            kw[(r0+8)*SK + dp] = pack_f16(cf[2]+be, cf[3]+bo);
        } else {
            const int dp = (nt - 12)*4 + lq;
            vw[r0*SV     + dp] = pack_f16(cf[0]+be, cf[1]+bo);
            vw[(r0+8)*SV + dp] = pack_f16(cf[2]+be, cf[3]+bo);
        }
    }
    __syncthreads();

    // ---- V repack: [token][dimpair] -> VT [dim][keypair] (stride SVT) ------
    {
        const int rwarp = wid & 3;          // 6 dimpairs per warp
        #pragma unroll
        for (int i = 0; i < 6; i++) {
            const int dp = rwarp*6 + i;     // 0..23
            const uint32_t wa = vw[(2*lane)*SV + dp];
            const uint32_t wb = vw[(2*lane+1)*SV + dp];
            vtw[(2*dp)*SVT   + lane] = __byte_perm(wa, wb, 0x5410);  // dim 2dp
            vtw[(2*dp+1)*SVT + lane] = __byte_perm(wa, wb, 0x7632);  // dim 2dp+1
        }
    }
    __syncthreads();

    // ---- attention -----------------------------------------------------------
    float oacc[6][4];
    #pragma unroll
    for (int n = 0; n < 6; n++)
        #pragma unroll
        for (int r = 0; r < 4; r++) oacc[n][r] = 0.f;

    const bool edge = (wy == 31) || (wx == 31);

    #pragma unroll
    for (int h = 0; h < 3; h++) {
        // q A-frag: pure pack from qkv C-frags (k16 = full head dim)
        uint32_t qa[4];
        qa[0] = pack_f16(qf[2*h][0],   qf[2*h][1]);
        qa[1] = pack_f16(qf[2*h][2],   qf[2*h][3]);
        qa[2] = pack_f16(qf[2*h+1][0], qf[2*h+1][1]);
        qa[3] = pack_f16(qf[2*h+1][2], qf[2*h+1][3]);

        float sf[8][4];
        #pragma unroll
        for (int nt = 0; nt < 8; nt++) {
            #pragma unroll
            for (int r = 0; r < 4; r++) sf[nt][r] = 0.f;
            uint32_t bf[2];
            bf[0] = kw[(nt*8 + lr)*SK + h*8 + lq];
            bf[1] = kw[(nt*8 + lr)*SK + h*8 + lq + 4];
            mma_f16(sf[nt], qa, bf);
        }

        // rpb + shift mask + softmax (fp32 in C-frags)
        {
            const int iA = r0, iB = r0 + 8;
            const int tiA = iA >> 3, tjA = iA & 7;
            const int tiB = iB >> 3, tjB = iB & 7;
            const int ryA = (wy==31) ? (tiA >= 4 ? 2 : 1) : 0;
            const int rxA = (wx==31) ? (tjA >= 4 ? 2 : 1) : 0;
            const int ryB = (wy==31) ? (tiB >= 4 ? 2 : 1) : 0;
            const int rxB = (wx==31) ? (tjB >= 4 ? 2 : 1) : 0;
            #pragma unroll
            for (int nt = 0; nt < 8; nt++) {
                #pragma unroll
                for (int e = 0; e < 2; e++) {
                    const int j = nt*8 + 2*lq + e;
                    const int rj = j >> 3, cj = j & 7;
                    const float bA = sm[OFF_RPB + ((tiA - rj + 7)*15 + (tjA - cj + 7))*3 + h];
                    const float bB = sm[OFF_RPB + ((tiB - rj + 7)*15 + (tjB - cj + 7))*3 + h];
                    float mA = 0.f, mB = 0.f;
                    if (edge) {
                        const int ryj = (wy==31) ? (rj >= 4 ? 2 : 1) : 0;
                        const int rxj = (wx==31) ? (cj >= 4 ? 2 : 1) : 0;
                        if (ryj != ryA || rxj != rxA) mA = -100.f;
                        if (ryj != ryB || rxj != rxB) mB = -100.f;
                    }
                    sf[nt][e]   += bA + mA;
                    sf[nt][e+2] += bB + mB;
                }
            }
            float mxA = -1e30f, mxB = -1e30f;
            #pragma unroll
            for (int nt = 0; nt < 8; nt++) {
                mxA = fmaxf(mxA, fmaxf(sf[nt][0], sf[nt][1]));
                mxB = fmaxf(mxB, fmaxf(sf[nt][2], sf[nt][3]));
            }
            mxA = fmaxf(mxA, __shfl_xor_sync(0xffffffffu, mxA, 1));
            mxA = fmaxf(mxA, __shfl_xor_sync(0xffffffffu, mxA, 2));
            mxB = fmaxf(mxB, __shfl_xor_sync(0xffffffffu, mxB, 1));
            mxB = fmaxf(mxB, __shfl_xor_sync(0xffffffffu, mxB, 2));
            float sA = 0.f, sB = 0.f;
            #pragma unroll
            for (int nt = 0; nt < 8; nt++) {
                sf[nt][0] = __expf(sf[nt][0] - mxA);
                sf[nt][1] = __expf(sf[nt][1] - mxA);
                sf[nt][2] = __expf(sf[nt][2] - mxB);
                sf[nt][3] = __expf(sf[nt][3] - mxB);
                sA += sf[nt][0] + sf[nt][1];
                sB += sf[nt][2] + sf[nt][3];
            }
            sA += __shfl_xor_sync(0xffffffffu, sA, 1);
            sA += __shfl_xor_sync(0xffffffffu, sA, 2);
            sB += __shfl_xor_sync(0xffffffffu, sB, 1);
            sB += __shfl_xor_sync(0xffffffffu, sB, 2);
            const float rAi = 1.f / sA, rBi = 1.f / sB;
            #pragma unroll
            for (int nt = 0; nt < 8; nt++) {
                sf[nt][0] *= rAi; sf[nt][1] *= rAi;
                sf[nt][2] *= rBi; sf[nt][3] *= rBi;
            }
        }

        // P.V: A-frags packed from prob C-frags; B from VT [dim][keypair]
        #pragma unroll
        for (int kt = 0; kt < 4; kt++) {
            uint32_t pa[4];
            pa[0] = pack_f16(sf[2*kt][0],   sf[2*kt][1]);
            pa[1] = pack_f16(sf[2*kt][2],   sf[2*kt][3]);
            pa[2] = pack_f16(sf[2*kt+1][0], sf[2*kt+1][1]);
            pa[3] = pack_f16(sf[2*kt+1][2], sf[2*kt+1][3]);
            #pragma unroll
            for (int nt2 = 0; nt2 < 2; nt2++) {
                uint32_t bf[2];
                bf[0] = vtw[(h*16 + nt2*8 + lr)*SVT + 8*kt + lq];
                bf[1] = vtw[(h*16 + nt2*8 + lr)*SVT + 8*kt + lq + 4];
                mma_f16(oacc[2*h + nt2], pa, bf);
            }
        }
    }

    // ---- SE add ----------------------------------------------------------------
    {
        const float wfv = __ldg(wf);
        const float* sew = sm + OFF_SE + wl*48;
        #pragma unroll
        for (int n = 0; n < 6; n++) {
            const int c0 = n*8 + 2*lq;
            const uint32_t wA = xlw[r0*SK     + n*4 + lq];
            const uint32_t wB = xlw[(r0+8)*SK + n*4 + lq];
            oacc[n][0] += wfv * h_lo(wA) * sew[c0];
            oacc[n][1] += wfv * h_hi(wA) * sew[c0+1];
            oacc[n][2] += wfv * h_lo(wB) * sew[c0];
            oacc[n][3] += wfv * h_hi(wB) * sew[c0+1];
        }
    }

    // ---- proj GEMM + direct scatter ---------------------------------------------
    uint32_t pa[3][4];
    #pragma unroll
    for (int kt = 0; kt < 3; kt++) {
        pa[kt][0] = pack_f16(oacc[2*kt][0],   oacc[2*kt][1]);
        pa[kt][1] = pack_f16(oacc[2*kt][2],   oacc[2*kt][3]);
        pa[kt][2] = pack_f16(oacc[2*kt+1][0], oacc[2*kt+1][1]);
        pa[kt][3] = pack_f16(oacc[2*kt+1][2], oacc[2*kt+1][3]);
    }

    const int gyA = (wy*8 + (r0 >> 3) + 4) & 255;
    const int gxA = (wx*8 + (r0 & 7) + 4) & 255;
    const int gyB = (wy*8 + ((r0+8) >> 3) + 4) & 255;
    const int gxB = (wx*8 + ((r0+8) & 7) + 4) & 255;
    float* orowA = g_attn + (((size_t)bimg << 16) | (gyA << 8) | gxA) * CC;
    float* orowB = g_attn + (((size_t)bimg << 16) | (gyB << 8) | gxB) * CC;

    #pragma unroll
    for (int nt = 0; nt < 6; nt++) {
        float pf[4] = {0.f,0.f,0.f,0.f};
        #pragma unroll
        for (int kt = 0; kt < 3; kt++) {
            uint32_t bf[2];
            bf[0] = s_wp[(nt*8 + lr)*SK + 8*kt + lq];
            bf[1] = s_wp[(nt*8 + lr)*SK + 8*kt + lq + 4];
            mma_f16(pf, pa[kt], bf);
        }
        const float be = sm[OFF_PB + nt*8 + 2*lq];
        const float bo = sm[OFF_PB + nt*8 + 2*lq + 1];
        *(float2*)(orowA + nt*8 + 2*lq) = make_float2(pf[0]+be, pf[1]+bo);
        *(float2*)(orowB + nt*8 + 2*lq) = make_float2(pf[2]+be, pf[3]+bo);
    }
}

// ===========================================================================
// MLP: fp16 m16n8k16, 512 thr = 16 warps x 16 tokens, 2 CTAs/SM.
// ===========================================================================
#define XS   52
#define W1S  200
#define W2S  56
#define B_SMEM_FLOATS (24*W1S + 96*W2S + 192 + 48 + 48 + 48 + 16*16*XS)

__global__ void __launch_bounds__(512, 2) mlp_kernel(
    const float* __restrict__ x,
    const float* __restrict__ g2,   const float* __restrict__ b2,
    const float* __restrict__ f1w,  const float* __restrict__ f1b,
    const float* __restrict__ f2w,  const float* __restrict__ f2b,
    float* __restrict__ out)
{
    extern __shared__ float sm[];
    uint32_t* s_w1 = (uint32_t*)sm;
    uint32_t* s_w2 = (uint32_t*)(sm + 24*W1S);
    float* s_b1 = sm + 24*W1S + 96*W2S;
    float* s_2b = s_b1 + 192;
    float* s_g2 = s_2b + 48;
    float* s_b2 = s_g2 + 48;
    float* s_xg = s_b2 + 48;

    const int tid  = threadIdx.x;
    const int wid  = tid >> 5;
    const int lane = tid & 31;
    const int lr   = lane >> 2;
    const int lq   = lane & 3;

    for (int i = tid; i < 24*192; i += 512) {
        const int p = i / 192, o = i % 192;
        s_w1[p*W1S + o] = pack_f16(f1w[o*48 + 2*p], f1w[o*48 + 2*p + 1]);
    }
    for (int i = tid; i < 96*48; i += 512) {
        const int hp = i / 48, ch = i % 48;
        s_w2[hp*W2S + ch] = pack_f16(f2w[ch*192 + 2*hp], f2w[ch*192 + 2*hp + 1]);
    }
    if (tid < 192) s_b1[tid] = f1b[tid];
    if (tid < 48) { s_2b[tid] = f2b[tid]; s_g2[tid] = g2[tid]; s_b2[tid] = b2[tid]; }
    __syncthreads();

    const size_t tokbase = (size_t)blockIdx.x * 256;

    if (tid < 256) {
        const size_t tok = tokbase + tid;
        const float* xrow = x      + tok*48;
        const float* hrow = g_attn + tok*48;
        float* orow = out + tok*48;
        float v[48];
        float mu = 0.f, sq = 0.f;
        #pragma unroll
        for (int c = 0; c < 48; c += 4) {
            float4 a = __ldg((const float4*)(xrow + c));
            float4 h = *(const float4*)(hrow + c);
            float4 s;
            s.x = a.x + h.x; s.y = a.y + h.y; s.z = a.z + h.z; s.w = a.w + h.w;
            *(float4*)(orow + c) = s;
            v[c]=s.x; v[c+1]=s.y; v[c+2]=s.z; v[c+3]=s.w;
            mu += s.x + s.y + s.z + s.w;
            sq += s.x*s.x + s.y*s.y + s.z*s.z + s.w*s.w;
        }
        mu *= (1.f/48.f);
        const float inv = rsqrtf(sq*(1.f/48.f) - mu*mu + 1e-5f);
        uint32_t* myx = (uint32_t*)(s_xg + (tid >> 4)*16*XS + (tid & 15)*XS);
        #pragma unroll
        for (int p = 0; p < 24; p++) {
            const float e0 = (v[2*p]   - mu) * inv * s_g2[2*p]   + s_b2[2*p];
            const float e1 = (v[2*p+1] - mu) * inv * s_g2[2*p+1] + s_b2[2*p+1];
            myx[p] = pack_f16(e0, e1);
        }
    }
    __syncthreads();

    uint32_t afr[3][4];
    {
        const uint32_t* wx = (const uint32_t*)(s_xg + wid*16*XS);
        #pragma unroll
        for (int kt = 0; kt < 3; kt++) {
            afr[kt][0] = wx[lr*XS     + 8*kt + lq];
            afr[kt][1] = wx[(lr+8)*XS + 8*kt + lq];
            afr[kt][2] = wx[lr*XS     + 8*kt + lq + 4];
            afr[kt][3] = wx[(lr+8)*XS + 8*kt + lq + 4];
        }
    }

    float yacc[6][4];
    #pragma unroll
    for (int nt = 0; nt < 6; nt++)
        #pragma unroll
        for (int r = 0; r < 4; r++) yacc[nt][r] = 0.f;

    for (int it = 0; it < 12; it++) {
        float h0[4] = {0.f,0.f,0.f,0.f}, h1[4] = {0.f,0.f,0.f,0.f};
        #pragma unroll
        for (int kt = 0; kt < 3; kt++) {
            const uint32_t* wA = s_w1 + (8*kt + lq  )*W1S + 16*it;
            const uint32_t* wB = s_w1 + (8*kt + lq+4)*W1S + 16*it;
            uint32_t b0[2], b1[2];
            b0[0] = wA[lr];     b0[1] = wB[lr];
            b1[0] = wA[8 + lr]; b1[1] = wB[8 + lr];
            mma_f16(h0, afr[kt], b0);
            mma_f16(h1, afr[kt], b1);
        }
        const float2 bbA = *(const float2*)(s_b1 + 16*it + 2*lq);
        const float2 bbB = *(const float2*)(s_b1 + 16*it + 8 + 2*lq);
        #pragma unroll
        for (int r = 0; r < 4; r++) {
            h0[r] = gelu_fast(h0[r] + ((r & 1) ? bbA.y : bbA.x));
            h1[r] = gelu_fast(h1[r] + ((r & 1) ? bbB.y : bbB.x));
        }
        uint32_t ga[4];
        ga[0] = pack_f16(h0[0], h0[1]);
        ga[1] = pack_f16(h0[2], h0[3]);
        ga[2] = pack_f16(h1[0], h1[1]);
        ga[3] = pack_f16(h1[2], h1[3]);
        const uint32_t* w2A = s_w2 + (8*it + lq  )*W2S;
        const uint32_t* w2B = s_w2 + (8*it + lq+4)*W2S;
        #pragma unroll
        for (int nt2 = 0; nt2 < 6; nt2++) {
            uint32_t bb[2];
            bb[0] = w2A[nt2*8 + lr];
            bb[1] = w2B[nt2*8 + lr];
            mma_f16(yacc[nt2], ga, bb);
        }
    }

    __syncwarp();
    float* wy = s_xg + wid*16*XS;
    #pragma unroll
    for (int nt2 = 0; nt2 < 6; nt2++) {
        const int c = 8*nt2 + 2*lq;
        *(float2*)(wy + lr*XS + c)     = make_float2(yacc[nt2][0], yacc[nt2][1]);
        *(float2*)(wy + (lr+8)*XS + c) = make_float2(yacc[nt2][2], yacc[nt2][3]);
    }
    __syncwarp();

    {
        const int row = lane >> 1;
        const int c0  = (lane & 1) * 24;
        const size_t tok = tokbase + wid*16 + row;
        float* orow = out + tok*48;
        #pragma unroll
        for (int k = 0; k < 6; k++) {
            const int c = c0 + k*4;
            float4 yv  = *(float4*)(wy + row*XS + c);
            float4 res = __ldcg((const float4*)(orow + c));
            float4 r;
            r.x = res.x + yv.x + s_2b[c];
            r.y = res.y + yv.y + s_2b[c+1];
            r.z = res.z + yv.z + s_2b[c+2];
            r.w = res.w + yv.w + s_2b[c+3];
            *(float4*)(orow + c) = r;
        }
    }
}

// ===========================================================================
extern "C" void kernel_launch(void* const* d_in, const int* in_sizes, int n_in,
                              void* d_out, int out_size)
{
    const float* x      = (const float*)d_in[0];
    const float* g1     = (const float*)d_in[1];
    const float* b1     = (const float*)d_in[2];
    const float* qkvw   = (const float*)d_in[3];
    const float* qkvb   = (const float*)d_in[4];
    const float* rpbt   = (const float*)d_in[5];
    const float* wf     = (const float*)d_in[6];
    const float* sw1    = (const float*)d_in[7];
    const float* sb1    = (const float*)d_in[8];
    const float* sw2    = (const float*)d_in[9];
    const float* sb2    = (const float*)d_in[10];
    const float* pw     = (const float*)d_in[11];
    const float* pb     = (const float*)d_in[12];
    const float* g2     = (const float*)d_in[13];
    const float* b2     = (const float*)d_in[14];
    const float* f1w    = (const float*)d_in[15];
    const float* f1b    = (const float*)d_in[16];
    const float* f2w    = (const float*)d_in[17];
    const float* f2b    = (const float*)d_in[18];
    float* out = (float*)d_out;

    const int a_smem = A_SMEM_FLOATS * 4;   // ~138 KB
    const int b_smem = B_SMEM_FLOATS * 4;   // ~95 KB -> 2 CTAs/SM
    cudaFuncSetAttribute(attn_kernel, cudaFuncAttributeMaxDynamicSharedMemorySize, a_smem);
    cudaFuncSetAttribute(mlp_kernel,  cudaFuncAttributeMaxDynamicSharedMemorySize, b_smem);

    attn_kernel<<<BN/4, 512, a_smem>>>(x, g1, b1, qkvw, qkvb, rpbt, wf,
                                       sw1, sb1, sw2, sb2, pw, pb);

    mlp_kernel<<<(BB*HH*WWD)/256, 512, b_smem>>>(x, g2, b2, f1w, f1b, f2w, f2b, out);
}

// round 15
// speedup vs baseline: 3.8736x; 1.0529x over previous
#include <cuda_runtime.h>
#include <cuda_fp16.h>
#include <math.h>
#include <stdint.h>

// ---------------------------------------------------------------------------
// Swin block: B=8, H=W=256, C=48, NH=3 (hd=16), WS=8 (N=64), SS=4, HID=192
// Kernel A: 512 thr = 4 windows x 4 warps (16 query rows each). fp16 m16n8k16.
// Kernel B: 512 thr = 16 warps x 32 tokens (2 m-tiles). fp16 m16n8k16 MLP.
//           R15: 32 tokens/warp halves weight-LDS bytes per token (the mlp is
//           smem-crossbar bound, not issue bound).
// ---------------------------------------------------------------------------

#define BB    8
#define HH    256
#define WWD   256
#define CC    48
#define NWIN  1024
#define BN    8192

__device__ float g_attn[(size_t)BB * HH * WWD * CC];

__device__ __forceinline__ void mma_f16(float* c, const uint32_t* a, const uint32_t* b) {
    asm volatile("mma.sync.aligned.m16n8k16.row.col.f32.f16.f16.f32 "
        "{%0,%1,%2,%3}, {%4,%5,%6,%7}, {%8,%9}, {%0,%1,%2,%3};"
        : "+f"(c[0]), "+f"(c[1]), "+f"(c[2]), "+f"(c[3])
        : "r"(a[0]), "r"(a[1]), "r"(a[2]), "r"(a[3]), "r"(b[0]), "r"(b[1]));
}
// pack two floats into f16x2: first arg -> low 16 bits
__device__ __forceinline__ uint32_t pack_f16(float lo, float hi) {
    uint32_t r;
    asm("cvt.rn.f16x2.f32 %0, %1, %2;" : "=r"(r) : "f"(hi), "f"(lo));
    return r;
}
__device__ __forceinline__ float h_lo(uint32_t w) {
    return __low2float(*reinterpret_cast<const __half2*>(&w));
}
__device__ __forceinline__ float h_hi(uint32_t w) {
    return __high2float(*reinterpret_cast<const __half2*>(&w));
}
// tanh-form GELU via sigmoid: x * sigmoid(1.59577x + 0.0713548x^3)
__device__ __forceinline__ float gelu_fast(float x) {
    const float t  = x * x;
    const float z2 = x * (1.5957691216f + 0.0713548162f * t);
    return x * __fdividef(1.f, 1.f + __expf(-z2));
}

// ---- attn smem layout (32-bit words) ----
#define SK   28     // xln / k row stride (rows hold <=24 words)
#define SV   25     // v packed row stride (repack staging only, 24 words)
#define SVT  36     // VT row stride (rows hold 32 keypair words)
#define OFF_WQ   0                        // 144 x 28 (f16x2) qkv weights [out][chpair]
#define OFF_WP   (OFF_WQ  + 144*SK)       // 48 x 28  proj weights  [out][chpair]
#define OFF_RPB  (OFF_WP  + 48*SK)        // 676
#define OFF_QKVB (OFF_RPB + 676)          // 144
#define OFF_PB   (OFF_QKVB+ 144)          // 48
#define OFF_SW1  (OFF_PB  + 48)           // 144
#define OFF_SB1  (OFF_SW1 + 144)          // 4
#define OFF_SW2  (OFF_SB1 + 4)            // 144
#define OFF_SB2  (OFF_SW2 + 144)          // 48
#define OFF_MEAN (OFF_SB2 + 48)           // 192
#define OFF_SE   (OFF_MEAN+ 192)          // 192
#define OFF_HH   (OFF_SE  + 192)          // 16
#define OFF_XLN  (OFF_HH  + 16)           // 4 windows x 64 x SK (f16x2 xln)
#define OFF_K    (OFF_XLN + 4*64*SK)      // 4 x 64 x SK  k [token][dimpair]
#define OFF_V    (OFF_K   + 4*64*SK)      // 4 x 64 x SV  v [token][dimpair]
#define OFF_VT   (OFF_V   + 4*64*SV)      // 4 x 48 x SVT v^T [dim][keypair 0..31]
#define A_SMEM_FLOATS (OFF_VT + 4*48*SVT)

__global__ void __launch_bounds__(512) attn_kernel(
    const float* __restrict__ x,
    const float* __restrict__ g1,   const float* __restrict__ b1,
    const float* __restrict__ qkvw, const float* __restrict__ qkvb,
    const float* __restrict__ rpbt, const float* __restrict__ wf,
    const float* __restrict__ sw1,  const float* __restrict__ sb1,
    const float* __restrict__ sw2,  const float* __restrict__ sb2,
    const float* __restrict__ pw,   const float* __restrict__ pb)
{
    extern __shared__ float sm[];
    uint32_t* s_wq = (uint32_t*)(sm + OFF_WQ);
    uint32_t* s_wp = (uint32_t*)(sm + OFF_WP);

    const int tid  = threadIdx.x;
    const int wid  = tid >> 5;
    const int lane = tid & 31;
    const int lr   = lane >> 2;
    const int lq   = lane & 3;

    // ---- stage weights packed f16x2 + tables -------------------------------
    for (int i = tid; i < 144*24; i += 512) {
        const int o = i / 24, p = i % 24;
        s_wq[o*SK + p] = pack_f16(qkvw[o*48 + 2*p], qkvw[o*48 + 2*p + 1]);
    }
    for (int i = tid; i < 48*24; i += 512) {
        const int o = i / 24, p = i % 24;
        s_wp[o*SK + p] = pack_f16(pw[o*48 + 2*p], pw[o*48 + 2*p + 1]);
    }
    for (int i = tid; i < 675; i += 512) sm[OFF_RPB + i] = __ldg(rpbt + i);
    for (int i = tid; i < 144; i += 512) {
        sm[OFF_QKVB + i] = qkvb[i];
        sm[OFF_SW1  + i] = sw1[i];
        sm[OFF_SW2  + i] = sw2[i];
    }
    if (tid < 48) { sm[OFF_PB + tid] = pb[tid]; sm[OFF_SB2 + tid] = sb2[tid]; }
    if (tid < 3)  sm[OFF_SB1 + tid] = sb1[tid];

    // ---- LN1: threads 0..255 = one token of one window (pack f16) ---------
    if (tid < 256) {
        const int wl2 = tid >> 6, tok2 = tid & 63;
        const int wg2 = blockIdx.x*4 + wl2;
        const int b2 = wg2 >> 10, ww = wg2 & 1023;
        const int wy2 = ww >> 5, wx2 = ww & 31;
        const int gy = (wy2*8 + (tok2 >> 3) + 4) & 255;
        const int gx = (wx2*8 + (tok2 & 7) + 4) & 255;
        const float* xrow = x + (((size_t)b2 << 16) | (gy << 8) | gx) * CC;
        float v[48];
        float mu = 0.f, sq = 0.f;
        #pragma unroll
        for (int c = 0; c < 48; c += 4) {
            float4 t = __ldg((const float4*)(xrow + c));
            v[c]=t.x; v[c+1]=t.y; v[c+2]=t.z; v[c+3]=t.w;
            mu += t.x + t.y + t.z + t.w;
            sq += t.x*t.x + t.y*t.y + t.z*t.z + t.w*t.w;
        }
        mu *= (1.f/48.f);
        const float inv = rsqrtf(sq*(1.f/48.f) - mu*mu + 1e-5f);
        uint32_t* myx = (uint32_t*)(sm + OFF_XLN) + (wl2*64 + tok2)*SK;
        #pragma unroll
        for (int p = 0; p < 24; p++) {
            const float e0 = (v[2*p]   - mu) * inv * __ldg(g1 + 2*p)   + __ldg(b1 + 2*p);
            const float e1 = (v[2*p+1] - mu) * inv * __ldg(g1 + 2*p+1) + __ldg(b1 + 2*p+1);
            myx[p] = pack_f16(e0, e1);
        }
    }
    __syncthreads();

    // ---- SE: mean (of f16 xln) -> fc1+relu -> fc2+sigmoid ------------------
    if (tid < 192) {
        const int wl2 = tid / 48, c = tid % 48;
        const uint32_t* xw = (const uint32_t*)(sm + OFF_XLN) + wl2*64*SK;
        float s = 0.f;
        for (int t = 0; t < 64; t++) {
            const uint32_t w = xw[t*SK + (c >> 1)];
            s += (c & 1) ? h_hi(w) : h_lo(w);
        }
        sm[OFF_MEAN + wl2*48 + c] = s * (1.f/64.f);
    }
    __syncthreads();
    if (tid < 12) {
        const int wl2 = tid / 3, o = tid % 3;
        float a = sm[OFF_SB1 + o];
        #pragma unroll
        for (int c = 0; c < 48; c++) a += sm[OFF_MEAN + wl2*48 + c] * sm[OFF_SW1 + o*48 + c];
        sm[OFF_HH + wl2*4 + o] = fmaxf(a, 0.f);
    }
    __syncthreads();
    if (tid < 192) {
        const int wl2 = tid / 48, c = tid % 48;
        float a = sm[OFF_SB2 + c] + sm[OFF_HH + wl2*4 + 0]*sm[OFF_SW2 + c*3 + 0]
                                  + sm[OFF_HH + wl2*4 + 1]*sm[OFF_SW2 + c*3 + 1]
                                  + sm[OFF_HH + wl2*4 + 2]*sm[OFF_SW2 + c*3 + 2];
        sm[OFF_SE + wl2*48 + c] = 1.f/(1.f + __expf(-a));
    }
    __syncthreads();

    // ---- per-warp geometry: 4 warps per window, 16 query rows each ---------
    const int wl = wid >> 2;
    const int rowbase = (wid & 3) * 16;
    const int wg = blockIdx.x*4 + wl;
    const int bimg = wg >> 10, ww = wg & 1023;
    const int wy = ww >> 5, wx = ww & 31;
    uint32_t* xlw = (uint32_t*)(sm + OFF_XLN) + wl*64*SK;
    uint32_t* kw  = (uint32_t*)(sm + OFF_K)   + wl*64*SK;
    uint32_t* vw  = (uint32_t*)(sm + OFF_V)   + wl*64*SV;
    uint32_t* vtw = (uint32_t*)(sm + OFF_VT)  + wl*48*SVT;
    const int r0 = rowbase + lr;

    // ---- qkv GEMM: A = xln[16x48] f16 (3 k16 tiles) -------------------------
    uint32_t afr[3][4];
    #pragma unroll
    for (int kt = 0; kt < 3; kt++) {
        afr[kt][0] = xlw[r0*SK     + 8*kt + lq];
        afr[kt][1] = xlw[(r0+8)*SK + 8*kt + lq];
        afr[kt][2] = xlw[r0*SK     + 8*kt + lq + 4];
        afr[kt][3] = xlw[(r0+8)*SK + 8*kt + lq + 4];
    }

    float qf[6][4];
    #pragma unroll
    for (int nt = 0; nt < 18; nt++) {
        float cf[4] = {0.f,0.f,0.f,0.f};
        #pragma unroll
        for (int kt = 0; kt < 3; kt++) {
            uint32_t bf[2];
            bf[0] = s_wq[(nt*8 + lr)*SK + 8*kt + lq];
            bf[1] = s_wq[(nt*8 + lr)*SK + 8*kt + lq + 4];
            mma_f16(cf, afr[kt], bf);
        }
        const float be = sm[OFF_QKVB + nt*8 + 2*lq];
        const float bo = sm[OFF_QKVB + nt*8 + 2*lq + 1];
        if (nt < 6) {
            qf[nt][0]=(cf[0]+be)*0.25f; qf[nt][1]=(cf[1]+bo)*0.25f;
            qf[nt][2]=(cf[2]+be)*0.25f; qf[nt][3]=(cf[3]+bo)*0.25f;
        } else if (nt < 12) {
            const int dp = (nt - 6)*4 + lq;
            kw[r0*SK     + dp] = pack_f16(cf[0]+be, cf[1]+bo);
            kw[(r0+8)*SK + dp] = pack_f16(cf[2]+be, cf[3]+bo);
        } else {
            const int dp = (nt - 12)*4 + lq;
            vw[r0*SV     + dp] = pack_f16(cf[0]+be, cf[1]+bo);
            vw[(r0+8)*SV + dp] = pack_f16(cf[2]+be, cf[3]+bo);
        }
    }
    __syncthreads();

    // ---- V repack: [token][dimpair] -> VT [dim][keypair] (stride SVT) ------
    {
        const int rwarp = wid & 3;          // 6 dimpairs per warp
        #pragma unroll
        for (int i = 0; i < 6; i++) {
            const int dp = rwarp*6 + i;     // 0..23
            const uint32_t wa = vw[(2*lane)*SV + dp];
            const uint32_t wb = vw[(2*lane+1)*SV + dp];
            vtw[(2*dp)*SVT   + lane] = __byte_perm(wa, wb, 0x5410);  // dim 2dp
            vtw[(2*dp+1)*SVT + lane] = __byte_perm(wa, wb, 0x7632);  // dim 2dp+1
        }
    }
    __syncthreads();

    // ---- attention -----------------------------------------------------------
    float oacc[6][4];
    #pragma unroll
    for (int n = 0; n < 6; n++)
        #pragma unroll
        for (int r = 0; r < 4; r++) oacc[n][r] = 0.f;

    const bool edge = (wy == 31) || (wx == 31);

    #pragma unroll
    for (int h = 0; h < 3; h++) {
        // q A-frag: pure pack from qkv C-frags (k16 = full head dim)
        uint32_t qa[4];
        qa[0] = pack_f16(qf[2*h][0],   qf[2*h][1]);
        qa[1] = pack_f16(qf[2*h][2],   qf[2*h][3]);
        qa[2] = pack_f16(qf[2*h+1][0], qf[2*h+1][1]);
        qa[3] = pack_f16(qf[2*h+1][2], qf[2*h+1][3]);

        float sf[8][4];
        #pragma unroll
        for (int nt = 0; nt < 8; nt++) {
            #pragma unroll
            for (int r = 0; r < 4; r++) sf[nt][r] = 0.f;
            uint32_t bf[2];
            bf[0] = kw[(nt*8 + lr)*SK + h*8 + lq];
            bf[1] = kw[(nt*8 + lr)*SK + h*8 + lq + 4];
            mma_f16(sf[nt], qa, bf);
        }

        // rpb + shift mask + softmax (fp32 in C-frags)
        {
            const int iA = r0, iB = r0 + 8;
            const int tiA = iA >> 3, tjA = iA & 7;
            const int tiB = iB >> 3, tjB = iB & 7;
            const int ryA = (wy==31) ? (tiA >= 4 ? 2 : 1) : 0;
            const int rxA = (wx==31) ? (tjA >= 4 ? 2 : 1) : 0;
            const int ryB = (wy==31) ? (tiB >= 4 ? 2 : 1) : 0;
            const int rxB = (wx==31) ? (tjB >= 4 ? 2 : 1) : 0;
            #pragma unroll
            for (int nt = 0; nt < 8; nt++) {
                #pragma unroll
                for (int e = 0; e < 2; e++) {
                    const int j = nt*8 + 2*lq + e;
                    const int rj = j >> 3, cj = j & 7;
                    const float bA = sm[OFF_RPB + ((tiA - rj + 7)*15 + (tjA - cj + 7))*3 + h];
                    const float bB = sm[OFF_RPB + ((tiB - rj + 7)*15 + (tjB - cj + 7))*3 + h];
                    float mA = 0.f, mB = 0.f;
                    if (edge) {
                        const int ryj = (wy==31) ? (rj >= 4 ? 2 : 1) : 0;
                        const int rxj = (wx==31) ? (cj >= 4 ? 2 : 1) : 0;
                        if (ryj != ryA || rxj != rxA) mA = -100.f;
                        if (ryj != ryB || rxj != rxB) mB = -100.f;
                    }
                    sf[nt][e]   += bA + mA;
                    sf[nt][e+2] += bB + mB;
                }
            }
            float mxA = -1e30f, mxB = -1e30f;
            #pragma unroll
            for (int nt = 0; nt < 8; nt++) {
                mxA = fmaxf(mxA, fmaxf(sf[nt][0], sf[nt][1]));
                mxB = fmaxf(mxB, fmaxf(sf[nt][2], sf[nt][3]));
            }
            mxA = fmaxf(mxA, __shfl_xor_sync(0xffffffffu, mxA, 1));
            mxA = fmaxf(mxA, __shfl_xor_sync(0xffffffffu, mxA, 2));
            mxB = fmaxf(mxB, __shfl_xor_sync(0xffffffffu, mxB, 1));
            mxB = fmaxf(mxB, __shfl_xor_sync(0xffffffffu, mxB, 2));
            float sA = 0.f, sB = 0.f;
            #pragma unroll
            for (int nt = 0; nt < 8; nt++) {
                sf[nt][0] = __expf(sf[nt][0] - mxA);
                sf[nt][1] = __expf(sf[nt][1] - mxA);
                sf[nt][2] = __expf(sf[nt][2] - mxB);
                sf[nt][3] = __expf(sf[nt][3] - mxB);
                sA += sf[nt][0] + sf[nt][1];
                sB += sf[nt][2] + sf[nt][3];
            }
            sA += __shfl_xor_sync(0xffffffffu, sA, 1);
            sA += __shfl_xor_sync(0xffffffffu, sA, 2);
            sB += __shfl_xor_sync(0xffffffffu, sB, 1);
            sB += __shfl_xor_sync(0xffffffffu, sB, 2);
            const float rAi = 1.f / sA, rBi = 1.f / sB;
            #pragma unroll
            for (int nt = 0; nt < 8; nt++) {
                sf[nt][0] *= rAi; sf[nt][1] *= rAi;
                sf[nt][2] *= rBi; sf[nt][3] *= rBi;
            }
        }

        // P.V: A-frags packed from prob C-frags; B from VT [dim][keypair]
        #pragma unroll
        for (int kt = 0; kt < 4; kt++) {
            uint32_t pa[4];
            pa[0] = pack_f16(sf[2*kt][0],   sf[2*kt][1]);
            pa[1] = pack_f16(sf[2*kt][2],   sf[2*kt][3]);
            pa[2] = pack_f16(sf[2*kt+1][0], sf[2*kt+1][1]);
            pa[3] = pack_f16(sf[2*kt+1][2], sf[2*kt+1][3]);
            #pragma unroll
            for (int nt2 = 0; nt2 < 2; nt2++) {
                uint32_t bf[2];
                bf[0] = vtw[(h*16 + nt2*8 + lr)*SVT + 8*kt + lq];
                bf[1] = vtw[(h*16 + nt2*8 + lr)*SVT + 8*kt + lq + 4];
                mma_f16(oacc[2*h + nt2], pa, bf);
            }
        }
    }

    // ---- SE add ----------------------------------------------------------------
    {
        const float wfv = __ldg(wf);
        const float* sew = sm + OFF_SE + wl*48;
        #pragma unroll
        for (int n = 0; n < 6; n++) {
            const int c0 = n*8 + 2*lq;
            const uint32_t wA = xlw[r0*SK     + n*4 + lq];
            const uint32_t wB = xlw[(r0+8)*SK + n*4 + lq];
            oacc[n][0] += wfv * h_lo(wA) * sew[c0];
            oacc[n][1] += wfv * h_hi(wA) * sew[c0+1];
            oacc[n][2] += wfv * h_lo(wB) * sew[c0];
            oacc[n][3] += wfv * h_hi(wB) * sew[c0+1];
        }
    }

    // ---- proj GEMM + direct scatter ---------------------------------------------
    uint32_t pa[3][4];
    #pragma unroll
    for (int kt = 0; kt < 3; kt++) {
        pa[kt][0] = pack_f16(oacc[2*kt][0],   oacc[2*kt][1]);
        pa[kt][1] = pack_f16(oacc[2*kt][2],   oacc[2*kt][3]);
        pa[kt][2] = pack_f16(oacc[2*kt+1][0], oacc[2*kt+1][1]);
        pa[kt][3] = pack_f16(oacc[2*kt+1][2], oacc[2*kt+1][3]);
    }

    const int gyA = (wy*8 + (r0 >> 3) + 4) & 255;
    const int gxA = (wx*8 + (r0 & 7) + 4) & 255;
    const int gyB = (wy*8 + ((r0+8) >> 3) + 4) & 255;
    const int gxB = (wx*8 + ((r0+8) & 7) + 4) & 255;
    float* orowA = g_attn + (((size_t)bimg << 16) | (gyA << 8) | gxA) * CC;
    float* orowB = g_attn + (((size_t)bimg << 16) | (gyB << 8) | gxB) * CC;

    #pragma unroll
    for (int nt = 0; nt < 6; nt++) {
        float pf[4] = {0.f,0.f,0.f,0.f};
        #pragma unroll
        for (int kt = 0; kt < 3; kt++) {
            uint32_t bf[2];
            bf[0] = s_wp[(nt*8 + lr)*SK + 8*kt + lq];
            bf[1] = s_wp[(nt*8 + lr)*SK + 8*kt + lq + 4];
            mma_f16(pf, pa[kt], bf);
        }
        const float be = sm[OFF_PB + nt*8 + 2*lq];
        const float bo = sm[OFF_PB + nt*8 + 2*lq + 1];
        *(float2*)(orowA + nt*8 + 2*lq) = make_float2(pf[0]+be, pf[1]+bo);
        *(float2*)(orowB + nt*8 + 2*lq) = make_float2(pf[2]+be, pf[3]+bo);
    }
}

// ===========================================================================
// MLP: fp16 m16n8k16, 512 thr = 16 warps x 32 tokens (2 m-tiles).
// Weight B-fragments are loaded once per iter and feed BOTH m-tiles:
// weight-LDS bytes per token halve vs the 16-token/warp version.
// ===========================================================================
#define XS   52
#define W1S  200
#define W2S  56
#define B_SMEM_FLOATS (24*W1S + 96*W2S + 192 + 48 + 48 + 48 + 16*32*XS)

__global__ void __launch_bounds__(512) mlp_kernel(
    const float* __restrict__ x,
    const float* __restrict__ g2,   const float* __restrict__ b2,
    const float* __restrict__ f1w,  const float* __restrict__ f1b,
    const float* __restrict__ f2w,  const float* __restrict__ f2b,
    float* __restrict__ out)
{
    extern __shared__ float sm[];
    uint32_t* s_w1 = (uint32_t*)sm;
    uint32_t* s_w2 = (uint32_t*)(sm + 24*W1S);
    float* s_b1 = sm + 24*W1S + 96*W2S;
    float* s_2b = s_b1 + 192;
    float* s_g2 = s_2b + 48;
    float* s_b2 = s_g2 + 48;
    float* s_xg = s_b2 + 48;                     // 16 warps x 32 rows x XS

    const int tid  = threadIdx.x;
    const int wid  = tid >> 5;
    const int lane = tid & 31;
    const int lr   = lane >> 2;
    const int lq   = lane & 3;

    for (int i = tid; i < 24*192; i += 512) {
        const int p = i / 192, o = i % 192;
        s_w1[p*W1S + o] = pack_f16(f1w[o*48 + 2*p], f1w[o*48 + 2*p + 1]);
    }
    for (int i = tid; i < 96*48; i += 512) {
        const int hp = i / 48, ch = i % 48;
        s_w2[hp*W2S + ch] = pack_f16(f2w[ch*192 + 2*hp], f2w[ch*192 + 2*hp + 1]);
    }
    if (tid < 192) s_b1[tid] = f1b[tid];
    if (tid < 48) { s_2b[tid] = f2b[tid]; s_g2[tid] = g2[tid]; s_b2[tid] = b2[tid]; }
    __syncthreads();

    const size_t tokbase = (size_t)blockIdx.x * 512;

    // ---- residual + LN2: every thread owns one token ------------------------
    {
        const size_t tok = tokbase + tid;        // warp w rows = tokens w*32..w*32+31
        const float* xrow = x      + tok*48;
        const float* hrow = g_attn + tok*48;
        float* orow = out + tok*48;
        float v[48];
        float mu = 0.f, sq = 0.f;
        #pragma unroll
        for (int c = 0; c < 48; c += 4) {
            float4 a = __ldg((const float4*)(xrow + c));
            float4 h = *(const float4*)(hrow + c);
            float4 s;
            s.x = a.x + h.x; s.y = a.y + h.y; s.z = a.z + h.z; s.w = a.w + h.w;
            *(float4*)(orow + c) = s;            // residual parked in out
            v[c]=s.x; v[c+1]=s.y; v[c+2]=s.z; v[c+3]=s.w;
            mu += s.x + s.y + s.z + s.w;
            sq += s.x*s.x + s.y*s.y + s.z*s.z + s.w*s.w;
        }
        mu *= (1.f/48.f);
        const float inv = rsqrtf(sq*(1.f/48.f) - mu*mu + 1e-5f);
        uint32_t* myx = (uint32_t*)(s_xg + (size_t)tid*XS);
        #pragma unroll
        for (int p = 0; p < 24; p++) {
            const float e0 = (v[2*p]   - mu) * inv * s_g2[2*p]   + s_b2[2*p];
            const float e1 = (v[2*p+1] - mu) * inv * s_g2[2*p+1] + s_b2[2*p+1];
            myx[p] = pack_f16(e0, e1);
        }
    }
    __syncthreads();

    // ---- A (xln 32x48 f16) fragments: 2 m-tiles x 3 k16-tiles ----------------
    uint32_t afr[2][3][4];
    {
        const uint32_t* wx = (const uint32_t*)(s_xg + (size_t)wid*32*XS);
        #pragma unroll
        for (int mt = 0; mt < 2; mt++)
            #pragma unroll
            for (int kt = 0; kt < 3; kt++) {
                const int r = mt*16 + lr;
                afr[mt][kt][0] = wx[r*XS     + 8*kt + lq];
                afr[mt][kt][1] = wx[(r+8)*XS + 8*kt + lq];
                afr[mt][kt][2] = wx[r*XS     + 8*kt + lq + 4];
                afr[mt][kt][3] = wx[(r+8)*XS + 8*kt + lq + 4];
            }
    }

    float yacc[2][6][4];
    #pragma unroll
    for (int mt = 0; mt < 2; mt++)
        #pragma unroll
        for (int nt = 0; nt < 6; nt++)
            #pragma unroll
            for (int r = 0; r < 4; r++) yacc[mt][nt][r] = 0.f;

    // ---- main loop: 12 chunks of 16 hidden; B loads shared by both m-tiles ---
    for (int it = 0; it < 12; it++) {
        float h0[2][4] = {{0.f,0.f,0.f,0.f},{0.f,0.f,0.f,0.f}};
        float h1[2][4] = {{0.f,0.f,0.f,0.f},{0.f,0.f,0.f,0.f}};
        #pragma unroll
        for (int kt = 0; kt < 3; kt++) {
            const uint32_t* wA = s_w1 + (8*kt + lq  )*W1S + 16*it;
            const uint32_t* wB = s_w1 + (8*kt + lq+4)*W1S + 16*it;
            uint32_t b0[2], b1[2];
            b0[0] = wA[lr];     b0[1] = wB[lr];
            b1[0] = wA[8 + lr]; b1[1] = wB[8 + lr];
            #pragma unroll
            for (int mt = 0; mt < 2; mt++) {
                mma_f16(h0[mt], afr[mt][kt], b0);
                mma_f16(h1[mt], afr[mt][kt], b1);
            }
        }
        const float2 bbA = *(const float2*)(s_b1 + 16*it + 2*lq);
        const float2 bbB = *(const float2*)(s_b1 + 16*it + 8 + 2*lq);
        uint32_t ga[2][4];
        #pragma unroll
        for (int mt = 0; mt < 2; mt++) {
            #pragma unroll
            for (int r = 0; r < 4; r++) {
                h0[mt][r] = gelu_fast(h0[mt][r] + ((r & 1) ? bbA.y : bbA.x));
                h1[mt][r] = gelu_fast(h1[mt][r] + ((r & 1) ? bbB.y : bbB.x));
            }
            ga[mt][0] = pack_f16(h0[mt][0], h0[mt][1]);
            ga[mt][1] = pack_f16(h0[mt][2], h0[mt][3]);
            ga[mt][2] = pack_f16(h1[mt][0], h1[mt][1]);
            ga[mt][3] = pack_f16(h1[mt][2], h1[mt][3]);
        }
        const uint32_t* w2A = s_w2 + (8*it + lq  )*W2S;
        const uint32_t* w2B = s_w2 + (8*it + lq+4)*W2S;
        #pragma unroll
        for (int nt2 = 0; nt2 < 6; nt2++) {
            uint32_t bb[2];
            bb[0] = w2A[nt2*8 + lr];
            bb[1] = w2B[nt2*8 + lr];
            mma_f16(yacc[0][nt2], ga[0], bb);
            mma_f16(yacc[1][nt2], ga[1], bb);
        }
    }

    // ---- epilogue: stage Y, coalesced residual add ---------------------------
    __syncwarp();
    float* wy = s_xg + (size_t)wid*32*XS;
    #pragma unroll
    for (int mt = 0; mt < 2; mt++)
        #pragma unroll
        for (int nt2 = 0; nt2 < 6; nt2++) {
            const int r = mt*16 + lr;
            const int c = 8*nt2 + 2*lq;
            *(float2*)(wy + r*XS + c)     = make_float2(yacc[mt][nt2][0], yacc[mt][nt2][1]);
            *(float2*)(wy + (r+8)*XS + c) = make_float2(yacc[mt][nt2][2], yacc[mt][nt2][3]);
        }
    __syncwarp();

    {
        const size_t tok = tokbase + wid*32 + lane;     // row = lane
        float* orow = out + tok*48;
        const float* yrow = wy + lane*XS;
        #pragma unroll
        for (int k = 0; k < 12; k++) {
            const int c = k*4;
            float4 yv  = *(const float4*)(yrow + c);
            float4 res = __ldcg((const float4*)(orow + c));
            float4 r;
            r.x = res.x + yv.x + s_2b[c];
            r.y = res.y + yv.y + s_2b[c+1];
            r.z = res.z + yv.z + s_2b[c+2];
            r.w = res.w + yv.w + s_2b[c+3];
            *(float4*)(orow + c) = r;
        }
    }
}

// ===========================================================================
extern "C" void kernel_launch(void* const* d_in, const int* in_sizes, int n_in,
                              void* d_out, int out_size)
{
    const float* x      = (const float*)d_in[0];
    const float* g1     = (const float*)d_in[1];
    const float* b1     = (const float*)d_in[2];
    const float* qkvw   = (const float*)d_in[3];
    const float* qkvb   = (const float*)d_in[4];
    const float* rpbt   = (const float*)d_in[5];
    const float* wf     = (const float*)d_in[6];
    const float* sw1    = (const float*)d_in[7];
    const float* sb1    = (const float*)d_in[8];
    const float* sw2    = (const float*)d_in[9];
    const float* sb2    = (const float*)d_in[10];
    const float* pw     = (const float*)d_in[11];
    const float* pb     = (const float*)d_in[12];
    const float* g2     = (const float*)d_in[13];
    const float* b2     = (const float*)d_in[14];
    const float* f1w    = (const float*)d_in[15];
    const float* f1b    = (const float*)d_in[16];
    const float* f2w    = (const float*)d_in[17];
    const float* f2b    = (const float*)d_in[18];
    float* out = (float*)d_out;

    const int a_smem = A_SMEM_FLOATS * 4;   // ~138 KB
    const int b_smem = B_SMEM_FLOATS * 4;   // ~148 KB -> 1 CTA/SM, 16 warps
    cudaFuncSetAttribute(attn_kernel, cudaFuncAttributeMaxDynamicSharedMemorySize, a_smem);
    cudaFuncSetAttribute(mlp_kernel,  cudaFuncAttributeMaxDynamicSharedMemorySize, b_smem);

    attn_kernel<<<BN/4, 512, a_smem>>>(x, g1, b1, qkvw, qkvb, rpbt, wf,
                                       sw1, sb1, sw2, sb2, pw, pb);

    mlp_kernel<<<(BB*HH*WWD)/512, 512, b_smem>>>(x, g2, b2, f1w, f1b, f2w, f2b, out);
}

// round 16
// speedup vs baseline: 4.1456x; 1.0702x over previous
#include <cuda_runtime.h>
#include <cuda_fp16.h>
#include <math.h>
#include <stdint.h>

// ---------------------------------------------------------------------------
// Swin block: B=8, H=W=256, C=48, NH=3 (hd=16), WS=8 (N=64), SS=4, HID=192
// Kernel A: 512 thr = 4 windows x 4 warps (16 query rows each). fp16 m16n8k16.
//           R16: g_attn stored as packed f16x2 (halves scratch traffic).
// Kernel B: 512 thr = 16 warps x 32 tokens (2 m-tiles). fp16 m16n8k16 MLP.
//           R16: no residual park in out; epilogue recomputes x+g_attn from
//           L2-hot reads and writes out exactly once.
// ---------------------------------------------------------------------------

#define BB    8
#define HH    256
#define WWD   256
#define CC    48
#define NWIN  1024
#define BN    8192

// attention-branch output, packed f16x2: 24 words per pixel
__device__ uint32_t g_attn[(size_t)BB * HH * WWD * 24];

__device__ __forceinline__ void mma_f16(float* c, const uint32_t* a, const uint32_t* b) {
    asm volatile("mma.sync.aligned.m16n8k16.row.col.f32.f16.f16.f32 "
        "{%0,%1,%2,%3}, {%4,%5,%6,%7}, {%8,%9}, {%0,%1,%2,%3};"
        : "+f"(c[0]), "+f"(c[1]), "+f"(c[2]), "+f"(c[3])
        : "r"(a[0]), "r"(a[1]), "r"(a[2]), "r"(a[3]), "r"(b[0]), "r"(b[1]));
}
// pack two floats into f16x2: first arg -> low 16 bits
__device__ __forceinline__ uint32_t pack_f16(float lo, float hi) {
    uint32_t r;
    asm("cvt.rn.f16x2.f32 %0, %1, %2;" : "=r"(r) : "f"(hi), "f"(lo));
    return r;
}
__device__ __forceinline__ float h_lo(uint32_t w) {
    return __low2float(*reinterpret_cast<const __half2*>(&w));
}
__device__ __forceinline__ float h_hi(uint32_t w) {
    return __high2float(*reinterpret_cast<const __half2*>(&w));
}
// tanh-form GELU via sigmoid: x * sigmoid(1.59577x + 0.0713548x^3)
__device__ __forceinline__ float gelu_fast(float x) {
    const float t  = x * x;
    const float z2 = x * (1.5957691216f + 0.0713548162f * t);
    return x * __fdividef(1.f, 1.f + __expf(-z2));
}

// ---- attn smem layout (32-bit words) ----
#define SK   28     // xln / k row stride (rows hold <=24 words)
#define SV   25     // v packed row stride (repack staging only, 24 words)
#define SVT  36     // VT row stride (rows hold 32 keypair words)
#define OFF_WQ   0                        // 144 x 28 (f16x2) qkv weights [out][chpair]
#define OFF_WP   (OFF_WQ  + 144*SK)       // 48 x 28  proj weights  [out][chpair]
#define OFF_RPB  (OFF_WP  + 48*SK)        // 676
#define OFF_QKVB (OFF_RPB + 676)          // 144
#define OFF_PB   (OFF_QKVB+ 144)          // 48
#define OFF_SW1  (OFF_PB  + 48)           // 144
#define OFF_SB1  (OFF_SW1 + 144)          // 4
#define OFF_SW2  (OFF_SB1 + 4)            // 144
#define OFF_SB2  (OFF_SW2 + 144)          // 48
#define OFF_MEAN (OFF_SB2 + 48)           // 192
#define OFF_SE   (OFF_MEAN+ 192)          // 192
#define OFF_HH   (OFF_SE  + 192)          // 16
#define OFF_XLN  (OFF_HH  + 16)           // 4 windows x 64 x SK (f16x2 xln)
#define OFF_K    (OFF_XLN + 4*64*SK)      // 4 x 64 x SK  k [token][dimpair]
#define OFF_V    (OFF_K   + 4*64*SK)      // 4 x 64 x SV  v [token][dimpair]
#define OFF_VT   (OFF_V   + 4*64*SV)      // 4 x 48 x SVT v^T [dim][keypair 0..31]
#define A_SMEM_FLOATS (OFF_VT + 4*48*SVT)

__global__ void __launch_bounds__(512) attn_kernel(
    const float* __restrict__ x,
    const float* __restrict__ g1,   const float* __restrict__ b1,
    const float* __restrict__ qkvw, const float* __restrict__ qkvb,
    const float* __restrict__ rpbt, const float* __restrict__ wf,
    const float* __restrict__ sw1,  const float* __restrict__ sb1,
    const float* __restrict__ sw2,  const float* __restrict__ sb2,
    const float* __restrict__ pw,   const float* __restrict__ pb)
{
    extern __shared__ float sm[];
    uint32_t* s_wq = (uint32_t*)(sm + OFF_WQ);
    uint32_t* s_wp = (uint32_t*)(sm + OFF_WP);

    const int tid  = threadIdx.x;
    const int wid  = tid >> 5;
    const int lane = tid & 31;
    const int lr   = lane >> 2;
    const int lq   = lane & 3;

    // ---- stage weights packed f16x2 + tables -------------------------------
    for (int i = tid; i < 144*24; i += 512) {
        const int o = i / 24, p = i % 24;
        s_wq[o*SK + p] = pack_f16(qkvw[o*48 + 2*p], qkvw[o*48 + 2*p + 1]);
    }
    for (int i = tid; i < 48*24; i += 512) {
        const int o = i / 24, p = i % 24;
        s_wp[o*SK + p] = pack_f16(pw[o*48 + 2*p], pw[o*48 + 2*p + 1]);
    }
    for (int i = tid; i < 675; i += 512) sm[OFF_RPB + i] = __ldg(rpbt + i);
    for (int i = tid; i < 144; i += 512) {
        sm[OFF_QKVB + i] = qkvb[i];
        sm[OFF_SW1  + i] = sw1[i];
        sm[OFF_SW2  + i] = sw2[i];
    }
    if (tid < 48) { sm[OFF_PB + tid] = pb[tid]; sm[OFF_SB2 + tid] = sb2[tid]; }
    if (tid < 3)  sm[OFF_SB1 + tid] = sb1[tid];

    // ---- LN1: threads 0..255 = one token of one window (pack f16) ---------
    if (tid < 256) {
        const int wl2 = tid >> 6, tok2 = tid & 63;
        const int wg2 = blockIdx.x*4 + wl2;
        const int b2 = wg2 >> 10, ww = wg2 & 1023;
        const int wy2 = ww >> 5, wx2 = ww & 31;
        const int gy = (wy2*8 + (tok2 >> 3) + 4) & 255;
        const int gx = (wx2*8 + (tok2 & 7) + 4) & 255;
        const float* xrow = x + (((size_t)b2 << 16) | (gy << 8) | gx) * CC;
        float v[48];
        float mu = 0.f, sq = 0.f;
        #pragma unroll
        for (int c = 0; c < 48; c += 4) {
            float4 t = __ldg((const float4*)(xrow + c));
            v[c]=t.x; v[c+1]=t.y; v[c+2]=t.z; v[c+3]=t.w;
            mu += t.x + t.y + t.z + t.w;
            sq += t.x*t.x + t.y*t.y + t.z*t.z + t.w*t.w;
        }
        mu *= (1.f/48.f);
        const float inv = rsqrtf(sq*(1.f/48.f) - mu*mu + 1e-5f);
        uint32_t* myx = (uint32_t*)(sm + OFF_XLN) + (wl2*64 + tok2)*SK;
        #pragma unroll
        for (int p = 0; p < 24; p++) {
            const float e0 = (v[2*p]   - mu) * inv * __ldg(g1 + 2*p)   + __ldg(b1 + 2*p);
            const float e1 = (v[2*p+1] - mu) * inv * __ldg(g1 + 2*p+1) + __ldg(b1 + 2*p+1);
            myx[p] = pack_f16(e0, e1);
        }
    }
    __syncthreads();

    // ---- SE: mean (of f16 xln) -> fc1+relu -> fc2+sigmoid ------------------
    if (tid < 192) {
        const int wl2 = tid / 48, c = tid % 48;
        const uint32_t* xw = (const uint32_t*)(sm + OFF_XLN) + wl2*64*SK;
        float s = 0.f;
        for (int t = 0; t < 64; t++) {
            const uint32_t w = xw[t*SK + (c >> 1)];
            s += (c & 1) ? h_hi(w) : h_lo(w);
        }
        sm[OFF_MEAN + wl2*48 + c] = s * (1.f/64.f);
    }
    __syncthreads();
    if (tid < 12) {
        const int wl2 = tid / 3, o = tid % 3;
        float a = sm[OFF_SB1 + o];
        #pragma unroll
        for (int c = 0; c < 48; c++) a += sm[OFF_MEAN + wl2*48 + c] * sm[OFF_SW1 + o*48 + c];
        sm[OFF_HH + wl2*4 + o] = fmaxf(a, 0.f);
    }
    __syncthreads();
    if (tid < 192) {
        const int wl2 = tid / 48, c = tid % 48;
        float a = sm[OFF_SB2 + c] + sm[OFF_HH + wl2*4 + 0]*sm[OFF_SW2 + c*3 + 0]
                                  + sm[OFF_HH + wl2*4 + 1]*sm[OFF_SW2 + c*3 + 1]
                                  + sm[OFF_HH + wl2*4 + 2]*sm[OFF_SW2 + c*3 + 2];
        sm[OFF_SE + wl2*48 + c] = 1.f/(1.f + __expf(-a));
    }
    __syncthreads();

    // ---- per-warp geometry: 4 warps per window, 16 query rows each ---------
    const int wl = wid >> 2;
    const int rowbase = (wid & 3) * 16;
    const int wg = blockIdx.x*4 + wl;
    const int bimg = wg >> 10, ww = wg & 1023;
    const int wy = ww >> 5, wx = ww & 31;
    uint32_t* xlw = (uint32_t*)(sm + OFF_XLN) + wl*64*SK;
    uint32_t* kw  = (uint32_t*)(sm + OFF_K)   + wl*64*SK;
    uint32_t* vw  = (uint32_t*)(sm + OFF_V)   + wl*64*SV;
    uint32_t* vtw = (uint32_t*)(sm + OFF_VT)  + wl*48*SVT;
    const int r0 = rowbase + lr;

    // ---- qkv GEMM: A = xln[16x48] f16 (3 k16 tiles) -------------------------
    uint32_t afr[3][4];
    #pragma unroll
    for (int kt = 0; kt < 3; kt++) {
        afr[kt][0] = xlw[r0*SK     + 8*kt + lq];
        afr[kt][1] = xlw[(r0+8)*SK + 8*kt + lq];
        afr[kt][2] = xlw[r0*SK     + 8*kt + lq + 4];
        afr[kt][3] = xlw[(r0+8)*SK + 8*kt + lq + 4];
    }

    float qf[6][4];
    #pragma unroll
    for (int nt = 0; nt < 18; nt++) {
        float cf[4] = {0.f,0.f,0.f,0.f};
        #pragma unroll
        for (int kt = 0; kt < 3; kt++) {
            uint32_t bf[2];
            bf[0] = s_wq[(nt*8 + lr)*SK + 8*kt + lq];
            bf[1] = s_wq[(nt*8 + lr)*SK + 8*kt + lq + 4];
            mma_f16(cf, afr[kt], bf);
        }
        const float be = sm[OFF_QKVB + nt*8 + 2*lq];
        const float bo = sm[OFF_QKVB + nt*8 + 2*lq + 1];
        if (nt < 6) {
            qf[nt][0]=(cf[0]+be)*0.25f; qf[nt][1]=(cf[1]+bo)*0.25f;
            qf[nt][2]=(cf[2]+be)*0.25f; qf[nt][3]=(cf[3]+bo)*0.25f;
        } else if (nt < 12) {
            const int dp = (nt - 6)*4 + lq;
            kw[r0*SK     + dp] = pack_f16(cf[0]+be, cf[1]+bo);
            kw[(r0+8)*SK + dp] = pack_f16(cf[2]+be, cf[3]+bo);
        } else {
            const int dp = (nt - 12)*4 + lq;
            vw[r0*SV     + dp] = pack_f16(cf[0]+be, cf[1]+bo);
            vw[(r0+8)*SV + dp] = pack_f16(cf[2]+be, cf[3]+bo);
        }
    }
    __syncthreads();

    // ---- V repack: [token][dimpair] -> VT [dim][keypair] (stride SVT) ------
    {
        const int rwarp = wid & 3;          // 6 dimpairs per warp
        #pragma unroll
        for (int i = 0; i < 6; i++) {
            const int dp = rwarp*6 + i;     // 0..23
            const uint32_t wa = vw[(2*lane)*SV + dp];
            const uint32_t wb = vw[(2*lane+1)*SV + dp];
            vtw[(2*dp)*SVT   + lane] = __byte_perm(wa, wb, 0x5410);  // dim 2dp
            vtw[(2*dp+1)*SVT + lane] = __byte_perm(wa, wb, 0x7632);  // dim 2dp+1
        }
    }
    __syncthreads();

    // ---- attention -----------------------------------------------------------
    float oacc[6][4];
    #pragma unroll
    for (int n = 0; n < 6; n++)
        #pragma unroll
        for (int r = 0; r < 4; r++) oacc[n][r] = 0.f;

    const bool edge = (wy == 31) || (wx == 31);

    #pragma unroll
    for (int h = 0; h < 3; h++) {
        // q A-frag: pure pack from qkv C-frags (k16 = full head dim)
        uint32_t qa[4];
        qa[0] = pack_f16(qf[2*h][0],   qf[2*h][1]);
        qa[1] = pack_f16(qf[2*h][2],   qf[2*h][3]);
        qa[2] = pack_f16(qf[2*h+1][0], qf[2*h+1][1]);
        qa[3] = pack_f16(qf[2*h+1][2], qf[2*h+1][3]);

        float sf[8][4];
        #pragma unroll
        for (int nt = 0; nt < 8; nt++) {
            #pragma unroll
            for (int r = 0; r < 4; r++) sf[nt][r] = 0.f;
            uint32_t bf[2];
            bf[0] = kw[(nt*8 + lr)*SK + h*8 + lq];
            bf[1] = kw[(nt*8 + lr)*SK + h*8 + lq + 4];
            mma_f16(sf[nt], qa, bf);
        }

        // rpb + shift mask + softmax (fp32 in C-frags)
        {
            const int iA = r0, iB = r0 + 8;
            const int tiA = iA >> 3, tjA = iA & 7;
            const int tiB = iB >> 3, tjB = iB & 7;
            const int ryA = (wy==31) ? (tiA >= 4 ? 2 : 1) : 0;
            const int rxA = (wx==31) ? (tjA >= 4 ? 2 : 1) : 0;
            const int ryB = (wy==31) ? (tiB >= 4 ? 2 : 1) : 0;
            const int rxB = (wx==31) ? (tjB >= 4 ? 2 : 1) : 0;
            #pragma unroll
            for (int nt = 0; nt < 8; nt++) {
                #pragma unroll
                for (int e = 0; e < 2; e++) {
                    const int j = nt*8 + 2*lq + e;
                    const int rj = j >> 3, cj = j & 7;
                    const float bA = sm[OFF_RPB + ((tiA - rj + 7)*15 + (tjA - cj + 7))*3 + h];
                    const float bB = sm[OFF_RPB + ((tiB - rj + 7)*15 + (tjB - cj + 7))*3 + h];
                    float mA = 0.f, mB = 0.f;
                    if (edge) {
                        const int ryj = (wy==31) ? (rj >= 4 ? 2 : 1) : 0;
                        const int rxj = (wx==31) ? (cj >= 4 ? 2 : 1) : 0;
                        if (ryj != ryA || rxj != rxA) mA = -100.f;
                        if (ryj != ryB || rxj != rxB) mB = -100.f;
                    }
                    sf[nt][e]   += bA + mA;
                    sf[nt][e+2] += bB + mB;
                }
            }
            float mxA = -1e30f, mxB = -1e30f;
            #pragma unroll
            for (int nt = 0; nt < 8; nt++) {
                mxA = fmaxf(mxA, fmaxf(sf[nt][0], sf[nt][1]));
                mxB = fmaxf(mxB, fmaxf(sf[nt][2], sf[nt][3]));
            }
            mxA = fmaxf(mxA, __shfl_xor_sync(0xffffffffu, mxA, 1));
            mxA = fmaxf(mxA, __shfl_xor_sync(0xffffffffu, mxA, 2));
            mxB = fmaxf(mxB, __shfl_xor_sync(0xffffffffu, mxB, 1));
            mxB = fmaxf(mxB, __shfl_xor_sync(0xffffffffu, mxB, 2));
            float sA = 0.f, sB = 0.f;
            #pragma unroll
            for (int nt = 0; nt < 8; nt++) {
                sf[nt][0] = __expf(sf[nt][0] - mxA);
                sf[nt][1] = __expf(sf[nt][1] - mxA);
                sf[nt][2] = __expf(sf[nt][2] - mxB);
                sf[nt][3] = __expf(sf[nt][3] - mxB);
                sA += sf[nt][0] + sf[nt][1];
                sB += sf[nt][2] + sf[nt][3];
            }
            sA += __shfl_xor_sync(0xffffffffu, sA, 1);
            sA += __shfl_xor_sync(0xffffffffu, sA, 2);
            sB += __shfl_xor_sync(0xffffffffu, sB, 1);
            sB += __shfl_xor_sync(0xffffffffu, sB, 2);
            const float rAi = 1.f / sA, rBi = 1.f / sB;
            #pragma unroll
            for (int nt = 0; nt < 8; nt++) {
                sf[nt][0] *= rAi; sf[nt][1] *= rAi;
                sf[nt][2] *= rBi; sf[nt][3] *= rBi;
            }
        }

        // P.V: A-frags packed from prob C-frags; B from VT [dim][keypair]
        #pragma unroll
        for (int kt = 0; kt < 4; kt++) {
            uint32_t pa[4];
            pa[0] = pack_f16(sf[2*kt][0],   sf[2*kt][1]);
            pa[1] = pack_f16(sf[2*kt][2],   sf[2*kt][3]);
            pa[2] = pack_f16(sf[2*kt+1][0], sf[2*kt+1][1]);
            pa[3] = pack_f16(sf[2*kt+1][2], sf[2*kt+1][3]);
            #pragma unroll
            for (int nt2 = 0; nt2 < 2; nt2++) {
                uint32_t bf[2];
                bf[0] = vtw[(h*16 + nt2*8 + lr)*SVT + 8*kt + lq];
                bf[1] = vtw[(h*16 + nt2*8 + lr)*SVT + 8*kt + lq + 4];
                mma_f16(oacc[2*h + nt2], pa, bf);
            }
        }
    }

    // ---- SE add ----------------------------------------------------------------
    {
        const float wfv = __ldg(wf);
        const float* sew = sm + OFF_SE + wl*48;
        #pragma unroll
        for (int n = 0; n < 6; n++) {
            const int c0 = n*8 + 2*lq;
            const uint32_t wA = xlw[r0*SK     + n*4 + lq];
            const uint32_t wB = xlw[(r0+8)*SK + n*4 + lq];
            oacc[n][0] += wfv * h_lo(wA) * sew[c0];
            oacc[n][1] += wfv * h_hi(wA) * sew[c0+1];
            oacc[n][2] += wfv * h_lo(wB) * sew[c0];
            oacc[n][3] += wfv * h_hi(wB) * sew[c0+1];
        }
    }

    // ---- proj GEMM + direct f16 scatter -----------------------------------------
    uint32_t pa[3][4];
    #pragma unroll
    for (int kt = 0; kt < 3; kt++) {
        pa[kt][0] = pack_f16(oacc[2*kt][0],   oacc[2*kt][1]);
        pa[kt][1] = pack_f16(oacc[2*kt][2],   oacc[2*kt][3]);
        pa[kt][2] = pack_f16(oacc[2*kt+1][0], oacc[2*kt+1][1]);
        pa[kt][3] = pack_f16(oacc[2*kt+1][2], oacc[2*kt+1][3]);
    }

    const int gyA = (wy*8 + (r0 >> 3) + 4) & 255;
    const int gxA = (wx*8 + (r0 & 7) + 4) & 255;
    const int gyB = (wy*8 + ((r0+8) >> 3) + 4) & 255;
    const int gxB = (wx*8 + ((r0+8) & 7) + 4) & 255;
    uint32_t* orowA = g_attn + (((size_t)bimg << 16) | (gyA << 8) | gxA) * 24;
    uint32_t* orowB = g_attn + (((size_t)bimg << 16) | (gyB << 8) | gxB) * 24;

    #pragma unroll
    for (int nt = 0; nt < 6; nt++) {
        float pf[4] = {0.f,0.f,0.f,0.f};
        #pragma unroll
        for (int kt = 0; kt < 3; kt++) {
            uint32_t bf[2];
            bf[0] = s_wp[(nt*8 + lr)*SK + 8*kt + lq];
            bf[1] = s_wp[(nt*8 + lr)*SK + 8*kt + lq + 4];
            mma_f16(pf, pa[kt], bf);
        }
        const float be = sm[OFF_PB + nt*8 + 2*lq];
        const float bo = sm[OFF_PB + nt*8 + 2*lq + 1];
        orowA[nt*4 + lq] = pack_f16(pf[0]+be, pf[1]+bo);
        orowB[nt*4 + lq] = pack_f16(pf[2]+be, pf[3]+bo);
    }
}

// ===========================================================================
// MLP: fp16 m16n8k16, 512 thr = 16 warps x 32 tokens (2 m-tiles).
// ===========================================================================
#define XS   52
#define W1S  200
#define W2S  56
#define B_SMEM_FLOATS (24*W1S + 96*W2S + 192 + 48 + 48 + 48 + 16*32*XS)

__global__ void __launch_bounds__(512) mlp_kernel(
    const float* __restrict__ x,
    const float* __restrict__ g2,   const float* __restrict__ b2,
    const float* __restrict__ f1w,  const float* __restrict__ f1b,
    const float* __restrict__ f2w,  const float* __restrict__ f2b,
    float* __restrict__ out)
{
    extern __shared__ float sm[];
    uint32_t* s_w1 = (uint32_t*)sm;
    uint32_t* s_w2 = (uint32_t*)(sm + 24*W1S);
    float* s_b1 = sm + 24*W1S + 96*W2S;
    float* s_2b = s_b1 + 192;
    float* s_g2 = s_2b + 48;
    float* s_b2 = s_g2 + 48;
    float* s_xg = s_b2 + 48;                     // 16 warps x 32 rows x XS

    const int tid  = threadIdx.x;
    const int wid  = tid >> 5;
    const int lane = tid & 31;
    const int lr   = lane >> 2;
    const int lq   = lane & 3;

    for (int i = tid; i < 24*192; i += 512) {
        const int p = i / 192, o = i % 192;
        s_w1[p*W1S + o] = pack_f16(f1w[o*48 + 2*p], f1w[o*48 + 2*p + 1]);
    }
    for (int i = tid; i < 96*48; i += 512) {
        const int hp = i / 48, ch = i % 48;
        s_w2[hp*W2S + ch] = pack_f16(f2w[ch*192 + 2*hp], f2w[ch*192 + 2*hp + 1]);
    }
    if (tid < 192) s_b1[tid] = f1b[tid];
    if (tid < 48) { s_2b[tid] = f2b[tid]; s_g2[tid] = g2[tid]; s_b2[tid] = b2[tid]; }
    __syncthreads();

    const size_t tokbase = (size_t)blockIdx.x * 512;

    // ---- residual + LN2: every thread owns one token ------------------------
    {
        const size_t tok = tokbase + tid;        // warp w rows = tokens w*32..w*32+31
        const float* xrow = x + tok*48;
        const uint32_t* hrow = g_attn + tok*24;
        float v[48];
        float mu = 0.f, sq = 0.f;
        #pragma unroll
        for (int c = 0; c < 48; c += 8) {
            float4 a0 = __ldg((const float4*)(xrow + c));
            float4 a1 = __ldg((const float4*)(xrow + c + 4));
            uint4  hw = __ldg((const uint4*)(hrow + (c >> 1)));
            float v0 = a0.x + h_lo(hw.x), v1 = a0.y + h_hi(hw.x);
            float v2 = a0.z + h_lo(hw.y), v3 = a0.w + h_hi(hw.y);
            float v4 = a1.x + h_lo(hw.z), v5 = a1.y + h_hi(hw.z);
            float v6 = a1.z + h_lo(hw.w), v7 = a1.w + h_hi(hw.w);
            v[c]=v0; v[c+1]=v1; v[c+2]=v2; v[c+3]=v3;
            v[c+4]=v4; v[c+5]=v5; v[c+6]=v6; v[c+7]=v7;
            mu += (v0+v1)+(v2+v3)+(v4+v5)+(v6+v7);
            sq += v0*v0+v1*v1+v2*v2+v3*v3+v4*v4+v5*v5+v6*v6+v7*v7;
        }
        mu *= (1.f/48.f);
        const float inv = rsqrtf(sq*(1.f/48.f) - mu*mu + 1e-5f);
        uint32_t* myx = (uint32_t*)(s_xg + (size_t)tid*XS);
        #pragma unroll
        for (int p = 0; p < 24; p++) {
            const float e0 = (v[2*p]   - mu) * inv * s_g2[2*p]   + s_b2[2*p];
            const float e1 = (v[2*p+1] - mu) * inv * s_g2[2*p+1] + s_b2[2*p+1];
            myx[p] = pack_f16(e0, e1);
        }
    }
    __syncthreads();

    // ---- A (xln 32x48 f16) fragments: 2 m-tiles x 3 k16-tiles ----------------
    uint32_t afr[2][3][4];
    {
        const uint32_t* wx = (const uint32_t*)(s_xg + (size_t)wid*32*XS);
        #pragma unroll
        for (int mt = 0; mt < 2; mt++)
            #pragma unroll
            for (int kt = 0; kt < 3; kt++) {
                const int r = mt*16 + lr;
                afr[mt][kt][0] = wx[r*XS     + 8*kt + lq];
                afr[mt][kt][1] = wx[(r+8)*XS + 8*kt + lq];
                afr[mt][kt][2] = wx[r*XS     + 8*kt + lq + 4];
                afr[mt][kt][3] = wx[(r+8)*XS + 8*kt + lq + 4];
            }
    }

    float yacc[2][6][4];
    #pragma unroll
    for (int mt = 0; mt < 2; mt++)
        #pragma unroll
        for (int nt = 0; nt < 6; nt++)
            #pragma unroll
            for (int r = 0; r < 4; r++) yacc[mt][nt][r] = 0.f;

    // ---- main loop: 12 chunks of 16 hidden; B loads shared by both m-tiles ---
    for (int it = 0; it < 12; it++) {
        float h0[2][4] = {{0.f,0.f,0.f,0.f},{0.f,0.f,0.f,0.f}};
        float h1[2][4] = {{0.f,0.f,0.f,0.f},{0.f,0.f,0.f,0.f}};
        #pragma unroll
        for (int kt = 0; kt < 3; kt++) {
            const uint32_t* wA = s_w1 + (8*kt + lq  )*W1S + 16*it;
            const uint32_t* wB = s_w1 + (8*kt + lq+4)*W1S + 16*it;
            uint32_t b0[2], b1[2];
            b0[0] = wA[lr];     b0[1] = wB[lr];
            b1[0] = wA[8 + lr]; b1[1] = wB[8 + lr];
            #pragma unroll
            for (int mt = 0; mt < 2; mt++) {
                mma_f16(h0[mt], afr[mt][kt], b0);
                mma_f16(h1[mt], afr[mt][kt], b1);
            }
        }
        const float2 bbA = *(const float2*)(s_b1 + 16*it + 2*lq);
        const float2 bbB = *(const float2*)(s_b1 + 16*it + 8 + 2*lq);
        uint32_t ga[2][4];
        #pragma unroll
        for (int mt = 0; mt < 2; mt++) {
            #pragma unroll
            for (int r = 0; r < 4; r++) {
                h0[mt][r] = gelu_fast(h0[mt][r] + ((r & 1) ? bbA.y : bbA.x));
                h1[mt][r] = gelu_fast(h1[mt][r] + ((r & 1) ? bbB.y : bbB.x));
            }
            ga[mt][0] = pack_f16(h0[mt][0], h0[mt][1]);
            ga[mt][1] = pack_f16(h0[mt][2], h0[mt][3]);
            ga[mt][2] = pack_f16(h1[mt][0], h1[mt][1]);
            ga[mt][3] = pack_f16(h1[mt][2], h1[mt][3]);
        }
        const uint32_t* w2A = s_w2 + (8*it + lq  )*W2S;
        const uint32_t* w2B = s_w2 + (8*it + lq+4)*W2S;
        #pragma unroll
        for (int nt2 = 0; nt2 < 6; nt2++) {
            uint32_t bb[2];
            bb[0] = w2A[nt2*8 + lr];
            bb[1] = w2B[nt2*8 + lr];
            mma_f16(yacc[0][nt2], ga[0], bb);
            mma_f16(yacc[1][nt2], ga[1], bb);
        }
    }

    // ---- epilogue: stage Y, recompute residual (L2-hot), single out write ----
    __syncwarp();
    float* wy = s_xg + (size_t)wid*32*XS;
    #pragma unroll
    for (int mt = 0; mt < 2; mt++)
        #pragma unroll
        for (int nt2 = 0; nt2 < 6; nt2++) {
            const int r = mt*16 + lr;
            const int c = 8*nt2 + 2*lq;
            *(float2*)(wy + r*XS + c)     = make_float2(yacc[mt][nt2][0], yacc[mt][nt2][1]);
            *(float2*)(wy + (r+8)*XS + c) = make_float2(yacc[mt][nt2][2], yacc[mt][nt2][3]);
        }
    __syncwarp();

    {
        const size_t tok = tokbase + wid*32 + lane;     // row = lane
        const float* xrow = x + tok*48;
        const uint32_t* hrow = g_attn + tok*24;
        float* orow = out + tok*48;
        const float* yrow = wy + lane*XS;
        #pragma unroll
        for (int k = 0; k < 12; k++) {
            const int c = k*4;
            float4 yv  = *(const float4*)(yrow + c);
            float4 xa  = __ldg((const float4*)(xrow + c));
            uint2  hh  = *(const uint2*)(hrow + (c >> 1));
            float4 r;
            r.x = xa.x + h_lo(hh.x) + yv.x + s_2b[c];
            r.y = xa.y + h_hi(hh.x) + yv.y + s_2b[c+1];
            r.z = xa.z + h_lo(hh.y) + yv.z + s_2b[c+2];
            r.w = xa.w + h_hi(hh.y) + yv.w + s_2b[c+3];
            *(float4*)(orow + c) = r;
        }
    }
}

// ===========================================================================
extern "C" void kernel_launch(void* const* d_in, const int* in_sizes, int n_in,
                              void* d_out, int out_size)
{
    const float* x      = (const float*)d_in[0];
    const float* g1     = (const float*)d_in[1];
    const float* b1     = (const float*)d_in[2];
    const float* qkvw   = (const float*)d_in[3];
    const float* qkvb   = (const float*)d_in[4];
    const float* rpbt   = (const float*)d_in[5];
    const float* wf     = (const float*)d_in[6];
    const float* sw1    = (const float*)d_in[7];
    const float* sb1    = (const float*)d_in[8];
    const float* sw2    = (const float*)d_in[9];
    const float* sb2    = (const float*)d_in[10];
    const float* pw     = (const float*)d_in[11];
    const float* pb     = (const float*)d_in[12];
    const float* g2     = (const float*)d_in[13];
    const float* b2     = (const float*)d_in[14];
    const float* f1w    = (const float*)d_in[15];
    const float* f1b    = (const float*)d_in[16];
    const float* f2w    = (const float*)d_in[17];
    const float* f2b    = (const float*)d_in[18];
    float* out = (float*)d_out;

    const int a_smem = A_SMEM_FLOATS * 4;   // ~138 KB
    const int b_smem = B_SMEM_FLOATS * 4;   // ~148 KB -> 1 CTA/SM, 16 warps
    cudaFuncSetAttribute(attn_kernel, cudaFuncAttributeMaxDynamicSharedMemorySize, a_smem);
    cudaFuncSetAttribute(mlp_kernel,  cudaFuncAttributeMaxDynamicSharedMemorySize, b_smem);

    attn_kernel<<<BN/4, 512, a_smem>>>(x, g1, b1, qkvw, qkvb, rpbt, wf,
                                       sw1, sb1, sw2, sb2, pw, pb);

    mlp_kernel<<<(BB*HH*WWD)/512, 512, b_smem>>>(x, g2, b2, f1w, f1b, f2w, f2b, out);
}

// round 17
// speedup vs baseline: 4.3219x; 1.0425x over previous
#include <cuda_runtime.h>
#include <cuda_fp16.h>
#include <math.h>
#include <stdint.h>

// ---------------------------------------------------------------------------
// Swin block: B=8, H=W=256, C=48, NH=3 (hd=16), WS=8 (N=64), SS=4, HID=192
// Kernel A: 512 thr = 4 windows x 4 warps (16 query rows each). fp16 m16n8k16.
//           R17: rpb rows preloaded once per head (bB[nt]==bA[nt-1] identity),
//           edge/interior specialization of the shift mask.
// Kernel B: 512 thr = 16 warps x 32 tokens (2 m-tiles). fp16 m16n8k16 MLP.
// ---------------------------------------------------------------------------

#define BB    8
#define HH    256
#define WWD   256
#define CC    48
#define NWIN  1024
#define BN    8192

// attention-branch output, packed f16x2: 24 words per pixel
__device__ uint32_t g_attn[(size_t)BB * HH * WWD * 24];

__device__ __forceinline__ void mma_f16(float* c, const uint32_t* a, const uint32_t* b) {
    asm volatile("mma.sync.aligned.m16n8k16.row.col.f32.f16.f16.f32 "
        "{%0,%1,%2,%3}, {%4,%5,%6,%7}, {%8,%9}, {%0,%1,%2,%3};"
        : "+f"(c[0]), "+f"(c[1]), "+f"(c[2]), "+f"(c[3])
        : "r"(a[0]), "r"(a[1]), "r"(a[2]), "r"(a[3]), "r"(b[0]), "r"(b[1]));
}
// pack two floats into f16x2: first arg -> low 16 bits
__device__ __forceinline__ uint32_t pack_f16(float lo, float hi) {
    uint32_t r;
    asm("cvt.rn.f16x2.f32 %0, %1, %2;" : "=r"(r) : "f"(hi), "f"(lo));
    return r;
}
__device__ __forceinline__ float h_lo(uint32_t w) {
    return __low2float(*reinterpret_cast<const __half2*>(&w));
}
__device__ __forceinline__ float h_hi(uint32_t w) {
    return __high2float(*reinterpret_cast<const __half2*>(&w));
}
// tanh-form GELU via sigmoid: x * sigmoid(1.59577x + 0.0713548x^3)
__device__ __forceinline__ float gelu_fast(float x) {
    const float t  = x * x;
    const float z2 = x * (1.5957691216f + 0.0713548162f * t);
    return x * __fdividef(1.f, 1.f + __expf(-z2));
}

// ---- attn smem layout (32-bit words) ----
#define SK   28     // xln / k row stride (rows hold <=24 words)
#define SV   25     // v packed row stride (repack staging only, 24 words)
#define SVT  36     // VT row stride (rows hold 32 keypair words)
#define OFF_WQ   0                        // 144 x 28 (f16x2) qkv weights [out][chpair]
#define OFF_WP   (OFF_WQ  + 144*SK)       // 48 x 28  proj weights  [out][chpair]
#define OFF_RPB  (OFF_WP  + 48*SK)        // 676
#define OFF_QKVB (OFF_RPB + 676)          // 144
#define OFF_PB   (OFF_QKVB+ 144)          // 48
#define OFF_SW1  (OFF_PB  + 48)           // 144
#define OFF_SB1  (OFF_SW1 + 144)          // 4
#define OFF_SW2  (OFF_SB1 + 4)            // 144
#define OFF_SB2  (OFF_SW2 + 144)          // 48
#define OFF_MEAN (OFF_SB2 + 48)           // 192
#define OFF_SE   (OFF_MEAN+ 192)          // 192
#define OFF_HH   (OFF_SE  + 192)          // 16
#define OFF_XLN  (OFF_HH  + 16)           // 4 windows x 64 x SK (f16x2 xln)
#define OFF_K    (OFF_XLN + 4*64*SK)      // 4 x 64 x SK  k [token][dimpair]
#define OFF_V    (OFF_K   + 4*64*SK)      // 4 x 64 x SV  v [token][dimpair]
#define OFF_VT   (OFF_V   + 4*64*SV)      // 4 x 48 x SVT v^T [dim][keypair 0..31]
#define A_SMEM_FLOATS (OFF_VT + 4*48*SVT)

__global__ void __launch_bounds__(512) attn_kernel(
    const float* __restrict__ x,
    const float* __restrict__ g1,   const float* __restrict__ b1,
    const float* __restrict__ qkvw, const float* __restrict__ qkvb,
    const float* __restrict__ rpbt, const float* __restrict__ wf,
    const float* __restrict__ sw1,  const float* __restrict__ sb1,
    const float* __restrict__ sw2,  const float* __restrict__ sb2,
    const float* __restrict__ pw,   const float* __restrict__ pb)
{
    extern __shared__ float sm[];
    uint32_t* s_wq = (uint32_t*)(sm + OFF_WQ);
    uint32_t* s_wp = (uint32_t*)(sm + OFF_WP);

    const int tid  = threadIdx.x;
    const int wid  = tid >> 5;
    const int lane = tid & 31;
    const int lr   = lane >> 2;
    const int lq   = lane & 3;

    // ---- stage weights packed f16x2 + tables -------------------------------
    for (int i = tid; i < 144*24; i += 512) {
        const int o = i / 24, p = i % 24;
        s_wq[o*SK + p] = pack_f16(qkvw[o*48 + 2*p], qkvw[o*48 + 2*p + 1]);
    }
    for (int i = tid; i < 48*24; i += 512) {
        const int o = i / 24, p = i % 24;
        s_wp[o*SK + p] = pack_f16(pw[o*48 + 2*p], pw[o*48 + 2*p + 1]);
    }
    for (int i = tid; i < 675; i += 512) sm[OFF_RPB + i] = __ldg(rpbt + i);
    for (int i = tid; i < 144; i += 512) {
        sm[OFF_QKVB + i] = qkvb[i];
        sm[OFF_SW1  + i] = sw1[i];
        sm[OFF_SW2  + i] = sw2[i];
    }
    if (tid < 48) { sm[OFF_PB + tid] = pb[tid]; sm[OFF_SB2 + tid] = sb2[tid]; }
    if (tid < 3)  sm[OFF_SB1 + tid] = sb1[tid];

    // ---- LN1: threads 0..255 = one token of one window (pack f16) ---------
    if (tid < 256) {
        const int wl2 = tid >> 6, tok2 = tid & 63;
        const int wg2 = blockIdx.x*4 + wl2;
        const int b2 = wg2 >> 10, ww = wg2 & 1023;
        const int wy2 = ww >> 5, wx2 = ww & 31;
        const int gy = (wy2*8 + (tok2 >> 3) + 4) & 255;
        const int gx = (wx2*8 + (tok2 & 7) + 4) & 255;
        const float* xrow = x + (((size_t)b2 << 16) | (gy << 8) | gx) * CC;
        float v[48];
        float mu = 0.f, sq = 0.f;
        #pragma unroll
        for (int c = 0; c < 48; c += 4) {
            float4 t = __ldg((const float4*)(xrow + c));
            v[c]=t.x; v[c+1]=t.y; v[c+2]=t.z; v[c+3]=t.w;
            mu += t.x + t.y + t.z + t.w;
            sq += t.x*t.x + t.y*t.y + t.z*t.z + t.w*t.w;
        }
        mu *= (1.f/48.f);
        const float inv = rsqrtf(sq*(1.f/48.f) - mu*mu + 1e-5f);
        uint32_t* myx = (uint32_t*)(sm + OFF_XLN) + (wl2*64 + tok2)*SK;
        #pragma unroll
        for (int p = 0; p < 24; p++) {
            const float e0 = (v[2*p]   - mu) * inv * __ldg(g1 + 2*p)   + __ldg(b1 + 2*p);
            const float e1 = (v[2*p+1] - mu) * inv * __ldg(g1 + 2*p+1) + __ldg(b1 + 2*p+1);
            myx[p] = pack_f16(e0, e1);
        }
    }
    __syncthreads();

    // ---- SE: mean (of f16 xln) -> fc1+relu -> fc2+sigmoid ------------------
    if (tid < 192) {
        const int wl2 = tid / 48, c = tid % 48;
        const uint32_t* xw = (const uint32_t*)(sm + OFF_XLN) + wl2*64*SK;
        float s = 0.f;
        for (int t = 0; t < 64; t++) {
            const uint32_t w = xw[t*SK + (c >> 1)];
            s += (c & 1) ? h_hi(w) : h_lo(w);
        }
        sm[OFF_MEAN + wl2*48 + c] = s * (1.f/64.f);
    }
    __syncthreads();
    if (tid < 12) {
        const int wl2 = tid / 3, o = tid % 3;
        float a = sm[OFF_SB1 + o];
        #pragma unroll
        for (int c = 0; c < 48; c++) a += sm[OFF_MEAN + wl2*48 + c] * sm[OFF_SW1 + o*48 + c];
        sm[OFF_HH + wl2*4 + o] = fmaxf(a, 0.f);
    }
    __syncthreads();
    if (tid < 192) {
        const int wl2 = tid / 48, c = tid % 48;
        float a = sm[OFF_SB2 + c] + sm[OFF_HH + wl2*4 + 0]*sm[OFF_SW2 + c*3 + 0]
                                  + sm[OFF_HH + wl2*4 + 1]*sm[OFF_SW2 + c*3 + 1]
                                  + sm[OFF_HH + wl2*4 + 2]*sm[OFF_SW2 + c*3 + 2];
        sm[OFF_SE + wl2*48 + c] = 1.f/(1.f + __expf(-a));
    }
    __syncthreads();

    // ---- per-warp geometry: 4 warps per window, 16 query rows each ---------
    const int wl = wid >> 2;
    const int rowbase = (wid & 3) * 16;
    const int wg = blockIdx.x*4 + wl;
    const int bimg = wg >> 10, ww = wg & 1023;
    const int wy = ww >> 5, wx = ww & 31;
    uint32_t* xlw = (uint32_t*)(sm + OFF_XLN) + wl*64*SK;
    uint32_t* kw  = (uint32_t*)(sm + OFF_K)   + wl*64*SK;
    uint32_t* vw  = (uint32_t*)(sm + OFF_V)   + wl*64*SV;
    uint32_t* vtw = (uint32_t*)(sm + OFF_VT)  + wl*48*SVT;
    const int r0 = rowbase + lr;

    // ---- qkv GEMM: A = xln[16x48] f16 (3 k16 tiles) -------------------------
    uint32_t afr[3][4];
    #pragma unroll
    for (int kt = 0; kt < 3; kt++) {
        afr[kt][0] = xlw[r0*SK     + 8*kt + lq];
        afr[kt][1] = xlw[(r0+8)*SK + 8*kt + lq];
        afr[kt][2] = xlw[r0*SK     + 8*kt + lq + 4];
        afr[kt][3] = xlw[(r0+8)*SK + 8*kt + lq + 4];
    }

    float qf[6][4];
    #pragma unroll
    for (int nt = 0; nt < 18; nt++) {
        float cf[4] = {0.f,0.f,0.f,0.f};
        #pragma unroll
        for (int kt = 0; kt < 3; kt++) {
            uint32_t bf[2];
            bf[0] = s_wq[(nt*8 + lr)*SK + 8*kt + lq];
            bf[1] = s_wq[(nt*8 + lr)*SK + 8*kt + lq + 4];
            mma_f16(cf, afr[kt], bf);
        }
        const float be = sm[OFF_QKVB + nt*8 + 2*lq];
        const float bo = sm[OFF_QKVB + nt*8 + 2*lq + 1];
        if (nt < 6) {
            qf[nt][0]=(cf[0]+be)*0.25f; qf[nt][1]=(cf[1]+bo)*0.25f;
            qf[nt][2]=(cf[2]+be)*0.25f; qf[nt][3]=(cf[3]+bo)*0.25f;
        } else if (nt < 12) {
            const int dp = (nt - 6)*4 + lq;
            kw[r0*SK     + dp] = pack_f16(cf[0]+be, cf[1]+bo);
            kw[(r0+8)*SK + dp] = pack_f16(cf[2]+be, cf[3]+bo);
        } else {
            const int dp = (nt - 12)*4 + lq;
            vw[r0*SV     + dp] = pack_f16(cf[0]+be, cf[1]+bo);
            vw[(r0+8)*SV + dp] = pack_f16(cf[2]+be, cf[3]+bo);
        }
    }
    __syncthreads();

    // ---- V repack: [token][dimpair] -> VT [dim][keypair] (stride SVT) ------
    {
        const int rwarp = wid & 3;          // 6 dimpairs per warp
        #pragma unroll
        for (int i = 0; i < 6; i++) {
            const int dp = rwarp*6 + i;     // 0..23
            const uint32_t wa = vw[(2*lane)*SV + dp];
            const uint32_t wb = vw[(2*lane+1)*SV + dp];
            vtw[(2*dp)*SVT   + lane] = __byte_perm(wa, wb, 0x5410);  // dim 2dp
            vtw[(2*dp+1)*SVT + lane] = __byte_perm(wa, wb, 0x7632);  // dim 2dp+1
        }
    }
    __syncthreads();

    // ---- attention -----------------------------------------------------------
    float oacc[6][4];
    #pragma unroll
    for (int n = 0; n < 6; n++)
        #pragma unroll
        for (int r = 0; r < 4; r++) oacc[n][r] = 0.f;

    const bool edge = (wy == 31) || (wx == 31);
    // token-in-window coords for rows iA=r0, iB=r0+8:
    //   tiA = rowbase>>3 (lane-uniform), tiB = tiA+1, tjA = tjB = lr
    const int tiA = rowbase >> 3;
    const int ryA = (wy==31) ? (tiA   >= 4 ? 2 : 1) : 0;
    const int ryB = (wy==31) ? (tiA+1 >= 4 ? 2 : 1) : 0;
    const int rxA = (wx==31) ? (lr    >= 4 ? 2 : 1) : 0;   // rxB == rxA

    #pragma unroll
    for (int h = 0; h < 3; h++) {
        // q A-frag: pure pack from qkv C-frags (k16 = full head dim)
        uint32_t qa[4];
        qa[0] = pack_f16(qf[2*h][0],   qf[2*h][1]);
        qa[1] = pack_f16(qf[2*h][2],   qf[2*h][3]);
        qa[2] = pack_f16(qf[2*h+1][0], qf[2*h+1][1]);
        qa[3] = pack_f16(qf[2*h+1][2], qf[2*h+1][3]);

        float sf[8][4];
        #pragma unroll
        for (int nt = 0; nt < 8; nt++) {
            #pragma unroll
            for (int r = 0; r < 4; r++) sf[nt][r] = 0.f;
            uint32_t bf[2];
            bf[0] = kw[(nt*8 + lr)*SK + h*8 + lq];
            bf[1] = kw[(nt*8 + lr)*SK + h*8 + lq + 4];
            mma_f16(sf[nt], qa, bf);
        }

        // ---- rpb rows preloaded once (bB[nt] row == bA[nt-1] row) ----------
        // bias element for (query row tiQ, key j=nt*8+2lq+e):
        //   rpb[((tiQ - nt + 7)*15 + (lr - 2lq - e + 7))*3 + h]
        // rows needed: tiA-nt+7 (nt 0..7) and tiA+1-nt+7 => tiA..tiA+8.
        float rv[9][2];
        {
            const int cb0 = OFF_RPB + (tiA*15 + (lr - 2*lq + 7))*3 + h;
            #pragma unroll
            for (int k = 0; k < 9; k++) {
                rv[k][0] = sm[cb0 + k*45];
                rv[k][1] = sm[cb0 + k*45 - 3];
            }
        }
        if (edge) {
            #pragma unroll
            for (int nt = 0; nt < 8; nt++) {
                const int ryj = (wy==31) ? (nt >= 4 ? 2 : 1) : 0;
                #pragma unroll
                for (int e = 0; e < 2; e++) {
                    const int cj = 2*lq + e;
                    const int rxj = (wx==31) ? (cj >= 4 ? 2 : 1) : 0;
                    const float mA = (ryj != ryA || rxj != rxA) ? -100.f : 0.f;
                    const float mB = (ryj != ryB || rxj != rxA) ? -100.f : 0.f;
                    sf[nt][e]   += rv[7-nt][e] + mA;
                    sf[nt][e+2] += rv[8-nt][e] + mB;
                }
            }
        } else {
            #pragma unroll
            for (int nt = 0; nt < 8; nt++) {
                sf[nt][0] += rv[7-nt][0];
                sf[nt][1] += rv[7-nt][1];
                sf[nt][2] += rv[8-nt][0];
                sf[nt][3] += rv[8-nt][1];
            }
        }

        // ---- softmax (fp32 in C-frags) --------------------------------------
        {
            float mxA = -1e30f, mxB = -1e30f;
            #pragma unroll
            for (int nt = 0; nt < 8; nt++) {
                mxA = fmaxf(mxA, fmaxf(sf[nt][0], sf[nt][1]));
                mxB = fmaxf(mxB, fmaxf(sf[nt][2], sf[nt][3]));
            }
            mxA = fmaxf(mxA, __shfl_xor_sync(0xffffffffu, mxA, 1));
            mxA = fmaxf(mxA, __shfl_xor_sync(0xffffffffu, mxA, 2));
            mxB = fmaxf(mxB, __shfl_xor_sync(0xffffffffu, mxB, 1));
            mxB = fmaxf(mxB, __shfl_xor_sync(0xffffffffu, mxB, 2));
            float sA = 0.f, sB = 0.f;
            #pragma unroll
            for (int nt = 0; nt < 8; nt++) {
                sf[nt][0] = __expf(sf[nt][0] - mxA);
                sf[nt][1] = __expf(sf[nt][1] - mxA);
                sf[nt][2] = __expf(sf[nt][2] - mxB);
                sf[nt][3] = __expf(sf[nt][3] - mxB);
                sA += sf[nt][0] + sf[nt][1];
                sB += sf[nt][2] + sf[nt][3];
            }
            sA += __shfl_xor_sync(0xffffffffu, sA, 1);
            sA += __shfl_xor_sync(0xffffffffu, sA, 2);
            sB += __shfl_xor_sync(0xffffffffu, sB, 1);
            sB += __shfl_xor_sync(0xffffffffu, sB, 2);
            const float rAi = 1.f / sA, rBi = 1.f / sB;
            #pragma unroll
            for (int nt = 0; nt < 8; nt++) {
                sf[nt][0] *= rAi; sf[nt][1] *= rAi;
                sf[nt][2] *= rBi; sf[nt][3] *= rBi;
            }
        }

        // P.V: A-frags packed from prob C-frags; B from VT [dim][keypair]
        #pragma unroll
        for (int kt = 0; kt < 4; kt++) {
            uint32_t pa[4];
            pa[0] = pack_f16(sf[2*kt][0],   sf[2*kt][1]);
            pa[1] = pack_f16(sf[2*kt][2],   sf[2*kt][3]);
            pa[2] = pack_f16(sf[2*kt+1][0], sf[2*kt+1][1]);
            pa[3] = pack_f16(sf[2*kt+1][2], sf[2*kt+1][3]);
            #pragma unroll
            for (int nt2 = 0; nt2 < 2; nt2++) {
                uint32_t bf[2];
                bf[0] = vtw[(h*16 + nt2*8 + lr)*SVT + 8*kt + lq];
                bf[1] = vtw[(h*16 + nt2*8 + lr)*SVT + 8*kt + lq + 4];
                mma_f16(oacc[2*h + nt2], pa, bf);
            }
        }
    }

    // ---- SE add ----------------------------------------------------------------
    {
        const float wfv = __ldg(wf);
        const float* sew = sm + OFF_SE + wl*48;
        #pragma unroll
        for (int n = 0; n < 6; n++) {
            const int c0 = n*8 + 2*lq;
            const uint32_t wA = xlw[r0*SK     + n*4 + lq];
            const uint32_t wB = xlw[(r0+8)*SK + n*4 + lq];
            oacc[n][0] += wfv * h_lo(wA) * sew[c0];
            oacc[n][1] += wfv * h_hi(wA) * sew[c0+1];
            oacc[n][2] += wfv * h_lo(wB) * sew[c0];
            oacc[n][3] += wfv * h_hi(wB) * sew[c0+1];
        }
    }

    // ---- proj GEMM + direct f16 scatter -----------------------------------------
    uint32_t pa[3][4];
    #pragma unroll
    for (int kt = 0; kt < 3; kt++) {
        pa[kt][0] = pack_f16(oacc[2*kt][0],   oacc[2*kt][1]);
        pa[kt][1] = pack_f16(oacc[2*kt][2],   oacc[2*kt][3]);
        pa[kt][2] = pack_f16(oacc[2*kt+1][0], oacc[2*kt+1][1]);
        pa[kt][3] = pack_f16(oacc[2*kt+1][2], oacc[2*kt+1][3]);
    }

    const int gyA = (wy*8 + (r0 >> 3) + 4) & 255;
    const int gxA = (wx*8 + (r0 & 7) + 4) & 255;
    const int gyB = (wy*8 + ((r0+8) >> 3) + 4) & 255;
    const int gxB = (wx*8 + ((r0+8) & 7) + 4) & 255;
    uint32_t* orowA = g_attn + (((size_t)bimg << 16) | (gyA << 8) | gxA) * 24;
    uint32_t* orowB = g_attn + (((size_t)bimg << 16) | (gyB << 8) | gxB) * 24;

    #pragma unroll
    for (int nt = 0; nt < 6; nt++) {
        float pf[4] = {0.f,0.f,0.f,0.f};
        #pragma unroll
        for (int kt = 0; kt < 3; kt++) {
            uint32_t bf[2];
            bf[0] = s_wp[(nt*8 + lr)*SK + 8*kt + lq];
            bf[1] = s_wp[(nt*8 + lr)*SK + 8*kt + lq + 4];
            mma_f16(pf, pa[kt], bf);
        }
        const float be = sm[OFF_PB + nt*8 + 2*lq];
        const float bo = sm[OFF_PB + nt*8 + 2*lq + 1];
        orowA[nt*4 + lq] = pack_f16(pf[0]+be, pf[1]+bo);
        orowB[nt*4 + lq] = pack_f16(pf[2]+be, pf[3]+bo);
    }
}

// ===========================================================================
// MLP: fp16 m16n8k16, 512 thr = 16 warps x 32 tokens (2 m-tiles).
// ===========================================================================
#define XS   52
#define W1S  200
#define W2S  56
#define B_SMEM_FLOATS (24*W1S + 96*W2S + 192 + 48 + 48 + 48 + 16*32*XS)

__global__ void __launch_bounds__(512) mlp_kernel(
    const float* __restrict__ x,
    const float* __restrict__ g2,   const float* __restrict__ b2,
    const float* __restrict__ f1w,  const float* __restrict__ f1b,
    const float* __restrict__ f2w,  const float* __restrict__ f2b,
    float* __restrict__ out)
{
    extern __shared__ float sm[];
    uint32_t* s_w1 = (uint32_t*)sm;
    uint32_t* s_w2 = (uint32_t*)(sm + 24*W1S);
    float* s_b1 = sm + 24*W1S + 96*W2S;
    float* s_2b = s_b1 + 192;
    float* s_g2 = s_2b + 48;
    float* s_b2 = s_g2 + 48;
    float* s_xg = s_b2 + 48;                     // 16 warps x 32 rows x XS

    const int tid  = threadIdx.x;
    const int wid  = tid >> 5;
    const int lane = tid & 31;
    const int lr   = lane >> 2;
    const int lq   = lane & 3;

    for (int i = tid; i < 24*192; i += 512) {
        const int p = i / 192, o = i % 192;
        s_w1[p*W1S + o] = pack_f16(f1w[o*48 + 2*p], f1w[o*48 + 2*p + 1]);
    }
    for (int i = tid; i < 96*48; i += 512) {
        const int hp = i / 48, ch = i % 48;
        s_w2[hp*W2S + ch] = pack_f16(f2w[ch*192 + 2*hp], f2w[ch*192 + 2*hp + 1]);
    }
    if (tid < 192) s_b1[tid] = f1b[tid];
    if (tid < 48) { s_2b[tid] = f2b[tid]; s_g2[tid] = g2[tid]; s_b2[tid] = b2[tid]; }
    __syncthreads();

    const size_t tokbase = (size_t)blockIdx.x * 512;

    // ---- residual + LN2: every thread owns one token ------------------------
    {
        const size_t tok = tokbase + tid;        // warp w rows = tokens w*32..w*32+31
        const float* xrow = x + tok*48;
        const uint32_t* hrow = g_attn + tok*24;
        float v[48];
        float mu = 0.f, sq = 0.f;
        #pragma unroll
        for (int c = 0; c < 48; c += 8) {
            float4 a0 = __ldg((const float4*)(xrow + c));
            float4 a1 = __ldg((const float4*)(xrow + c + 4));
            uint4  hw = __ldg((const uint4*)(hrow + (c >> 1)));
            float v0 = a0.x + h_lo(hw.x), v1 = a0.y + h_hi(hw.x);
            float v2 = a0.z + h_lo(hw.y), v3 = a0.w + h_hi(hw.y);
            float v4 = a1.x + h_lo(hw.z), v5 = a1.y + h_hi(hw.z);
            float v6 = a1.z + h_lo(hw.w), v7 = a1.w + h_hi(hw.w);
            v[c]=v0; v[c+1]=v1; v[c+2]=v2; v[c+3]=v3;
            v[c+4]=v4; v[c+5]=v5; v[c+6]=v6; v[c+7]=v7;
            mu += (v0+v1)+(v2+v3)+(v4+v5)+(v6+v7);
            sq += v0*v0+v1*v1+v2*v2+v3*v3+v4*v4+v5*v5+v6*v6+v7*v7;
        }
        mu *= (1.f/48.f);
        const float inv = rsqrtf(sq*(1.f/48.f) - mu*mu + 1e-5f);
        uint32_t* myx = (uint32_t*)(s_xg + (size_t)tid*XS);
        #pragma unroll
        for (int p = 0; p < 24; p++) {
            const float e0 = (v[2*p]   - mu) * inv * s_g2[2*p]   + s_b2[2*p];
            const float e1 = (v[2*p+1] - mu) * inv * s_g2[2*p+1] + s_b2[2*p+1];
            myx[p] = pack_f16(e0, e1);
        }
    }
    __syncthreads();

    // ---- A (xln 32x48 f16) fragments: 2 m-tiles x 3 k16-tiles ----------------
    uint32_t afr[2][3][4];
    {
        const uint32_t* wx = (const uint32_t*)(s_xg + (size_t)wid*32*XS);
        #pragma unroll
        for (int mt = 0; mt < 2; mt++)
            #pragma unroll
            for (int kt = 0; kt < 3; kt++) {
                const int r = mt*16 + lr;
                afr[mt][kt][0] = wx[r*XS     + 8*kt + lq];
                afr[mt][kt][1] = wx[(r+8)*XS + 8*kt + lq];
                afr[mt][kt][2] = wx[r*XS     + 8*kt + lq + 4];
                afr[mt][kt][3] = wx[(r+8)*XS + 8*kt + lq + 4];
            }
    }

    float yacc[2][6][4];
    #pragma unroll
    for (int mt = 0; mt < 2; mt++)
        #pragma unroll
        for (int nt = 0; nt < 6; nt++)
            #pragma unroll
            for (int r = 0; r < 4; r++) yacc[mt][nt][r] = 0.f;

    // ---- main loop: 12 chunks of 16 hidden; B loads shared by both m-tiles ---
    for (int it = 0; it < 12; it++) {
        float h0[2][4] = {{0.f,0.f,0.f,0.f},{0.f,0.f,0.f,0.f}};
        float h1[2][4] = {{0.f,0.f,0.f,0.f},{0.f,0.f,0.f,0.f}};
        #pragma unroll
        for (int kt = 0; kt < 3; kt++) {
            const uint32_t* wA = s_w1 + (8*kt + lq  )*W1S + 16*it;
            const uint32_t* wB = s_w1 + (8*kt + lq+4)*W1S + 16*it;
            uint32_t b0[2], b1[2];
            b0[0] = wA[lr];     b0[1] = wB[lr];
            b1[0] = wA[8 + lr]; b1[1] = wB[8 + lr];
            #pragma unroll
            for (int mt = 0; mt < 2; mt++) {
                mma_f16(h0[mt], afr[mt][kt], b0);
                mma_f16(h1[mt], afr[mt][kt], b1);
            }
        }
        const float2 bbA = *(const float2*)(s_b1 + 16*it + 2*lq);
        const float2 bbB = *(const float2*)(s_b1 + 16*it + 8 + 2*lq);
        uint32_t ga[2][4];
        #pragma unroll
        for (int mt = 0; mt < 2; mt++) {
            #pragma unroll
            for (int r = 0; r < 4; r++) {
                h0[mt][r] = gelu_fast(h0[mt][r] + ((r & 1) ? bbA.y : bbA.x));
                h1[mt][r] = gelu_fast(h1[mt][r] + ((r & 1) ? bbB.y : bbB.x));
            }
            ga[mt][0] = pack_f16(h0[mt][0], h0[mt][1]);
            ga[mt][1] = pack_f16(h0[mt][2], h0[mt][3]);
            ga[mt][2] = pack_f16(h1[mt][0], h1[mt][1]);
            ga[mt][3] = pack_f16(h1[mt][2], h1[mt][3]);
        }
        const uint32_t* w2A = s_w2 + (8*it + lq  )*W2S;
        const uint32_t* w2B = s_w2 + (8*it + lq+4)*W2S;
        #pragma unroll
        for (int nt2 = 0; nt2 < 6; nt2++) {
            uint32_t bb[2];
            bb[0] = w2A[nt2*8 + lr];
            bb[1] = w2B[nt2*8 + lr];
            mma_f16(yacc[0][nt2], ga[0], bb);
            mma_f16(yacc[1][nt2], ga[1], bb);
        }
    }

    // ---- epilogue: stage Y, recompute residual (L2-hot), single out write ----
    __syncwarp();
    float* wy = s_xg + (size_t)wid*32*XS;
    #pragma unroll
    for (int mt = 0; mt < 2; mt++)
        #pragma unroll
        for (int nt2 = 0; nt2 < 6; nt2++) {
            const int r = mt*16 + lr;
            const int c = 8*nt2 + 2*lq;
            *(float2*)(wy + r*XS + c)     = make_float2(yacc[mt][nt2][0], yacc[mt][nt2][1]);
            *(float2*)(wy + (r+8)*XS + c) = make_float2(yacc[mt][nt2][2], yacc[mt][nt2][3]);
        }
    __syncwarp();

    {
        const size_t tok = tokbase + wid*32 + lane;     // row = lane
        const float* xrow = x + tok*48;
        const uint32_t* hrow = g_attn + tok*24;
        float* orow = out + tok*48;
        const float* yrow = wy + lane*XS;
        #pragma unroll
        for (int k = 0; k < 12; k++) {
            const int c = k*4;
            float4 yv  = *(const float4*)(yrow + c);
            float4 xa  = __ldg((const float4*)(xrow + c));
            uint2  hh  = *(const uint2*)(hrow + (c >> 1));
            float4 r;
            r.x = xa.x + h_lo(hh.x) + yv.x + s_2b[c];
            r.y = xa.y + h_hi(hh.x) + yv.y + s_2b[c+1];
            r.z = xa.z + h_lo(hh.y) + yv.z + s_2b[c+2];
            r.w = xa.w + h_hi(hh.y) + yv.w + s_2b[c+3];
            *(float4*)(orow + c) = r;
        }
    }
}

// ===========================================================================
extern "C" void kernel_launch(void* const* d_in, const int* in_sizes, int n_in,
                              void* d_out, int out_size)
{
    const float* x      = (const float*)d_in[0];
    const float* g1     = (const float*)d_in[1];
    const float* b1     = (const float*)d_in[2];
    const float* qkvw   = (const float*)d_in[3];
    const float* qkvb   = (const float*)d_in[4];
    const float* rpbt   = (const float*)d_in[5];
    const float* wf     = (const float*)d_in[6];
    const float* sw1    = (const float*)d_in[7];
    const float* sb1    = (const float*)d_in[8];
    const float* sw2    = (const float*)d_in[9];
    const float* sb2    = (const float*)d_in[10];
    const float* pw     = (const float*)d_in[11];
    const float* pb     = (const float*)d_in[12];
    const float* g2     = (const float*)d_in[13];
    const float* b2     = (const float*)d_in[14];
    const float* f1w    = (const float*)d_in[15];
    const float* f1b    = (const float*)d_in[16];
    const float* f2w    = (const float*)d_in[17];
    const float* f2b    = (const float*)d_in[18];
    float* out = (float*)d_out;

    const int a_smem = A_SMEM_FLOATS * 4;   // ~138 KB
    const int b_smem = B_SMEM_FLOATS * 4;   // ~148 KB -> 1 CTA/SM, 16 warps
    cudaFuncSetAttribute(attn_kernel, cudaFuncAttributeMaxDynamicSharedMemorySize, a_smem);
    cudaFuncSetAttribute(mlp_kernel,  cudaFuncAttributeMaxDynamicSharedMemorySize, b_smem);

    attn_kernel<<<BN/4, 512, a_smem>>>(x, g1, b1, qkvw, qkvb, rpbt, wf,
                                       sw1, sb1, sw2, sb2, pw, pb);

    mlp_kernel<<<(BB*HH*WWD)/512, 512, b_smem>>>(x, g2, b2, f1w, f1b, f2w, f2b, out);
}